// round 2
// baseline (speedup 1.0000x reference)
#include <cuda_runtime.h>

#define NN 4096
#define CC 96
#define EE 131072
#define NHEADS 4
#define DH 24

// ---------------- scratch (no allocation allowed) ----------------
__device__ float g_h[NN*CC];
__device__ float g_agg[NN*CC];
__device__ float g_t1[NN*CC];
__device__ float g_pre1[NN*CC];
__device__ float g_qkv[NN*3*CC];
__device__ float g_attno[NN*CC];
__device__ float g_pre2[NN*CC];
__device__ float g_outb[NN*CC];
__device__ float g_t2[NN*2*CC];
__device__ float g_pre3[NN*CC];
__device__ float g_y[NN*CC];
__device__ float g_stats[6*CC];
__device__ int   g_src[EE];
__device__ int   g_dst[EE];
__device__ int   g_eat[EE];
__device__ int   g_flags[2];   // [0]: edge_index is int64, [1]: edge_attr is int64

// ---------------- dtype detection + index decode ----------------
__global__ void detect_idx(const unsigned* __restrict__ ei, const unsigned* __restrict__ ea) {
    if (threadIdx.x == 0) {
        int z = 1;
        for (int k = 0; k < 16; k++) if (ei[2 * k + 1] != 0u) { z = 0; break; }
        g_flags[0] = z;
        int z2 = 1;
        for (int k = 0; k < 16; k++) if (ea[2 * k + 1] != 0u) { z2 = 0; break; }
        g_flags[1] = z2;
    }
}

__global__ void decode_idx(const void* __restrict__ ei, const void* __restrict__ ea) {
    int e = blockIdx.x * blockDim.x + threadIdx.x;
    if (e >= EE) return;
    if (g_flags[0]) {
        const long long* p = (const long long*)ei;
        g_src[e] = (int)p[e];
        g_dst[e] = (int)p[EE + e];
    } else {
        const int* p = (const int*)ei;
        g_src[e] = p[e];
        g_dst[e] = p[EE + e];
    }
    if (g_flags[1]) {
        const long long* p = (const long long*)ea;
        g_eat[e] = (int)p[e];
    } else {
        const int* p = (const int*)ea;
        g_eat[e] = p[e];
    }
}

// ---------------- utility ----------------
__global__ void zero_kernel(float* __restrict__ p, int n) {
    int i = blockIdx.x*blockDim.x + threadIdx.x;
    if (i < n) p[i] = 0.f;
}

// ---------------- SGEMM: C = (A [+A2]) @ W + bias [+res] [relu] ----------------
// BM=64 BN=64 BK=16, 256 threads, 4x4 microtile. M % 64 == 0, K % 16 == 0, N % 4 == 0.
__global__ __launch_bounds__(256) void sgemm(
    const float* __restrict__ A, const float* __restrict__ A2,
    const float* __restrict__ W, const float* __restrict__ bias,
    const float* __restrict__ res, float* __restrict__ C,
    int M, int N, int K, int relu)
{
    __shared__ float As[16][64];
    __shared__ float Bs[16][64];
    const int tid  = threadIdx.x;
    const int row0 = blockIdx.y * 64;
    const int col0 = blockIdx.x * 64;
    const int ty = tid >> 4, tx = tid & 15;

    const int ar = tid >> 2, ak = (tid & 3) * 4;       // A tile: 64 rows x 4 float4
    const int bk = tid >> 4, bc = (tid & 15) * 4;      // B tile: 16 rows x 16 float4

    float acc[4][4];
    #pragma unroll
    for (int i = 0; i < 4; i++)
        #pragma unroll
        for (int j = 0; j < 4; j++) acc[i][j] = 0.f;

    for (int k0 = 0; k0 < K; k0 += 16) {
        float4 a = *(const float4*)(A + (size_t)(row0 + ar) * K + k0 + ak);
        if (A2) {
            float4 a2 = *(const float4*)(A2 + (size_t)(row0 + ar) * K + k0 + ak);
            a.x += a2.x; a.y += a2.y; a.z += a2.z; a.w += a2.w;
        }
        As[ak + 0][ar] = a.x; As[ak + 1][ar] = a.y;
        As[ak + 2][ar] = a.z; As[ak + 3][ar] = a.w;

        float4 bv = make_float4(0.f, 0.f, 0.f, 0.f);
        if (col0 + bc < N)
            bv = *(const float4*)(W + (size_t)(k0 + bk) * N + col0 + bc);
        *(float4*)&Bs[bk][bc] = bv;

        __syncthreads();
        #pragma unroll
        for (int kk = 0; kk < 16; kk++) {
            float4 ra = *(const float4*)&As[kk][ty * 4];
            float4 rb = *(const float4*)&Bs[kk][tx * 4];
            float ja[4] = {ra.x, ra.y, ra.z, ra.w};
            float jb[4] = {rb.x, rb.y, rb.z, rb.w};
            #pragma unroll
            for (int i = 0; i < 4; i++)
                #pragma unroll
                for (int j = 0; j < 4; j++) acc[i][j] += ja[i] * jb[j];
        }
        __syncthreads();
    }

    #pragma unroll
    for (int i = 0; i < 4; i++) {
        int r = row0 + ty * 4 + i;
        #pragma unroll
        for (int j = 0; j < 4; j++) {
            int c = col0 + tx * 4 + j;
            if (c < N) {
                float v = acc[i][j] + bias[c];
                if (res) v += res[(size_t)r * N + c];
                if (relu) v = fmaxf(v, 0.f);
                C[(size_t)r * N + c] = v;
            }
        }
    }
}

// ---------------- GINE edge scatter: agg[dst] += relu(h[src] + emb[attr]) ----------------
__global__ void gine_edge(const float* __restrict__ h, const float* __restrict__ emb,
                          float* __restrict__ agg) {
    int t = blockIdx.x * blockDim.x + threadIdx.x;
    if (t >= EE * 24) return;
    int e = t / 24;
    int g = t % 24;
    int src = g_src[e];
    int dst = g_dst[e];
    int a   = g_eat[e];
    float4 hv = *(const float4*)(h + (size_t)src * CC + g * 4);
    float4 ev = *(const float4*)(emb + (size_t)a * CC + g * 4);
    float4 mm;
    mm.x = fmaxf(hv.x + ev.x, 0.f);
    mm.y = fmaxf(hv.y + ev.y, 0.f);
    mm.z = fmaxf(hv.z + ev.z, 0.f);
    mm.w = fmaxf(hv.w + ev.w, 0.f);
    float* ap = agg + (size_t)dst * CC + g * 4;
    atomicAdd(ap + 0, mm.x);
    atomicAdd(ap + 1, mm.y);
    atomicAdd(ap + 2, mm.z);
    atomicAdd(ap + 3, mm.w);
}

// ---------------- flash attention (fp32, online softmax) ----------------
// grid (NN/128, NHEADS), 128 threads. Thread t owns query q0+t of head blockIdx.y.
__global__ __launch_bounds__(128) void flash_attn(const float* __restrict__ qkv,
                                                  float* __restrict__ outp) {
    const int h  = blockIdx.y;
    const int q0 = blockIdx.x * 128;
    const int tid = threadIdx.x;
    __shared__ float Ks[128][DH];
    __shared__ float Vs[128][DH];
    const float scale = 0.20412414523193154f;  // 1/sqrt(24)

    float q[DH];
    {
        const float* qp = qkv + (size_t)(q0 + tid) * (3 * CC) + h * DH;
        #pragma unroll
        for (int d = 0; d < DH; d++) q[d] = qp[d] * scale;
    }
    float m = -1e30f, l = 0.f;
    float o[DH];
    #pragma unroll
    for (int d = 0; d < DH; d++) o[d] = 0.f;

    for (int kt = 0; kt < NN; kt += 128) {
        __syncthreads();
        {
            const float* kp = qkv + (size_t)(kt + tid) * (3 * CC) + CC + h * DH;
            const float* vp = kp + CC;
            #pragma unroll
            for (int d = 0; d < DH; d += 4) {
                *(float4*)&Ks[tid][d] = *(const float4*)(kp + d);
                *(float4*)&Vs[tid][d] = *(const float4*)(vp + d);
            }
        }
        __syncthreads();

        #pragma unroll 1
        for (int j0 = 0; j0 < 128; j0 += 8) {
            float s[8];
            #pragma unroll
            for (int jj = 0; jj < 8; jj++) s[jj] = 0.f;
            #pragma unroll
            for (int d = 0; d < DH; d += 4) {
                #pragma unroll
                for (int jj = 0; jj < 8; jj++) {
                    float4 kv = *(const float4*)&Ks[j0 + jj][d];
                    s[jj] += q[d] * kv.x + q[d + 1] * kv.y + q[d + 2] * kv.z + q[d + 3] * kv.w;
                }
            }
            float mx = m;
            #pragma unroll
            for (int jj = 0; jj < 8; jj++) mx = fmaxf(mx, s[jj]);
            float corr = __expf(m - mx);
            m = mx;
            float p[8], ps = 0.f;
            #pragma unroll
            for (int jj = 0; jj < 8; jj++) { p[jj] = __expf(s[jj] - mx); ps += p[jj]; }
            l = l * corr + ps;
            #pragma unroll
            for (int d = 0; d < DH; d++) o[d] *= corr;
            #pragma unroll
            for (int jj = 0; jj < 8; jj++) {
                float pj = p[jj];
                #pragma unroll
                for (int d = 0; d < DH; d += 4) {
                    float4 vv = *(const float4*)&Vs[j0 + jj][d];
                    o[d]     += pj * vv.x;
                    o[d + 1] += pj * vv.y;
                    o[d + 2] += pj * vv.z;
                    o[d + 3] += pj * vv.w;
                }
            }
        }
    }
    float invl = 1.f / l;
    float* op = outp + (size_t)(q0 + tid) * CC + h * DH;
    #pragma unroll
    for (int d = 0; d < DH; d++) op[d] = o[d] * invl;
}

// ---------------- BatchNorm: per-channel sum / sumsq over nodes ----------------
__global__ void bn_stats(const float* __restrict__ x, float* __restrict__ s,
                         float* __restrict__ s2) {
    int c  = threadIdx.x;       // 0..95
    int r0 = blockIdx.x * 64;
    float a = 0.f, b = 0.f;
    for (int r = r0; r < r0 + 64; r++) {
        float v = x[(size_t)r * CC + c];
        a += v; b += v * v;
    }
    atomicAdd(&s[c], a);
    atomicAdd(&s2[c], b);
}

// out = BN1(p1)*g1+b1 + BN2(p2)*g2+b2
__global__ void bn2_add(const float* __restrict__ p1, const float* __restrict__ p2,
                        const float* __restrict__ st,
                        const float* __restrict__ g1, const float* __restrict__ b1,
                        const float* __restrict__ g2, const float* __restrict__ b2,
                        float* __restrict__ out) {
    int i = blockIdx.x * blockDim.x + threadIdx.x;
    if (i >= NN * CC) return;
    int c = i % CC;
    const float invn = 1.f / NN;
    float m1 = st[c] * invn;
    float v1 = st[CC + c] * invn - m1 * m1;
    float m2 = st[2 * CC + c] * invn;
    float v2 = st[3 * CC + c] * invn - m2 * m2;
    float o = (p1[i] - m1) * rsqrtf(v1 + 1e-5f) * g1[c] + b1[c]
            + (p2[i] - m2) * rsqrtf(v2 + 1e-5f) * g2[c] + b2[c];
    out[i] = o;
}

__global__ void bn_apply(const float* __restrict__ p, const float* __restrict__ s,
                         const float* __restrict__ s2, const float* __restrict__ g,
                         const float* __restrict__ b, float* __restrict__ o) {
    int i = blockIdx.x * blockDim.x + threadIdx.x;
    if (i >= NN * CC) return;
    int c = i % CC;
    const float invn = 1.f / NN;
    float m = s[c] * invn;
    float v = s2[c] * invn - m * m;
    o[i] = (p[i] - m) * rsqrtf(v + 1e-5f) * g[c] + b[c];
}

// ---------------- final per-row LayerNorm, one warp per row ----------------
__global__ void out_ln(const float* __restrict__ y, const float* __restrict__ g,
                       const float* __restrict__ b, float* __restrict__ out) {
    int lane = threadIdx.x & 31;
    int warp = threadIdx.x >> 5;
    int row  = blockIdx.x * 4 + warp;
    const float* yr = y + (size_t)row * CC;
    float v0 = yr[lane], v1 = yr[lane + 32], v2 = yr[lane + 64];
    float s = v0 + v1 + v2;
    #pragma unroll
    for (int o = 16; o; o >>= 1) s += __shfl_xor_sync(0xffffffffu, s, o);
    float mean = s * (1.f / 96.f);
    float d0 = v0 - mean, d1 = v1 - mean, d2 = v2 - mean;
    float qv = d0 * d0 + d1 * d1 + d2 * d2;
    #pragma unroll
    for (int o = 16; o; o >>= 1) qv += __shfl_xor_sync(0xffffffffu, qv, o);
    float inv = rsqrtf(qv * (1.f / 96.f) + 1e-5f);
    float* orow = out + (size_t)row * CC;
    orow[lane]      = d0 * inv * g[lane]      + b[lane];
    orow[lane + 32] = d1 * inv * g[lane + 32] + b[lane + 32];
    orow[lane + 64] = d2 * inv * g[lane + 64] + b[lane + 64];
}

// ---------------- launch ----------------
extern "C" void kernel_launch(void* const* d_in, const int* in_sizes, int n_in,
                              void* d_out, int out_size) {
    const float*     x    = (const float*)d_in[0];
    const void*      ei   = d_in[1];
    const void*      ea   = d_in[2];
    const float*     w_in = (const float*)d_in[3];
    const float*     b_in = (const float*)d_in[4];
    const float*     emb  = (const float*)d_in[5];
    const float*     gw1  = (const float*)d_in[6];
    const float*     gb1  = (const float*)d_in[7];
    const float*     gw2  = (const float*)d_in[8];
    const float*     gb2  = (const float*)d_in[9];
    const float*     wqkv = (const float*)d_in[10];
    const float*     bqkv = (const float*)d_in[11];
    const float*     wo   = (const float*)d_in[12];
    const float*     bo   = (const float*)d_in[13];
    const float*     bng  = (const float*)d_in[14];
    const float*     bnb  = (const float*)d_in[15];
    const float*     fw1  = (const float*)d_in[16];
    const float*     fb1  = (const float*)d_in[17];
    const float*     fw2  = (const float*)d_in[18];
    const float*     fb2  = (const float*)d_in[19];
    const float*     w_o  = (const float*)d_in[20];
    const float*     b_o  = (const float*)d_in[21];
    const float*     lng  = (const float*)d_in[22];
    const float*     lnb  = (const float*)d_in[23];
    float* out = (float*)d_out;

    float *h_, *agg_, *t1_, *pre1_, *qkv_, *attno_, *pre2_, *outb_, *t2_, *pre3_, *y_, *st_;
    cudaGetSymbolAddress((void**)&h_,    g_h);
    cudaGetSymbolAddress((void**)&agg_,  g_agg);
    cudaGetSymbolAddress((void**)&t1_,   g_t1);
    cudaGetSymbolAddress((void**)&pre1_, g_pre1);
    cudaGetSymbolAddress((void**)&qkv_,  g_qkv);
    cudaGetSymbolAddress((void**)&attno_,g_attno);
    cudaGetSymbolAddress((void**)&pre2_, g_pre2);
    cudaGetSymbolAddress((void**)&outb_, g_outb);
    cudaGetSymbolAddress((void**)&t2_,   g_t2);
    cudaGetSymbolAddress((void**)&pre3_, g_pre3);
    cudaGetSymbolAddress((void**)&y_,    g_y);
    cudaGetSymbolAddress((void**)&st_,   g_stats);

    auto gemm = [&](const float* A, const float* A2, const float* W, const float* bias,
                    const float* res, float* Cp, int M, int Nc, int K, int relu) {
        dim3 grid((Nc + 63) / 64, M / 64);
        sgemm<<<grid, 256>>>(A, A2, W, bias, res, Cp, M, Nc, K, relu);
    };

    const int NCEL = NN * CC;

    // decode edge indices (dtype-robust: int32 or int64)
    detect_idx<<<1, 32>>>((const unsigned*)ei, (const unsigned*)ea);
    decode_idx<<<(EE + 255) / 256, 256>>>(ei, ea);

    // input projection
    gemm(x, nullptr, w_in, b_in, nullptr, h_, NN, CC, 64, 0);

    for (int i = 0; i < 2; i++) {
        // --- GINE branch ---
        zero_kernel<<<(NCEL + 255) / 256, 256>>>(agg_, NCEL);
        zero_kernel<<<3, 256>>>(st_, 6 * CC);
        gine_edge<<<(EE * 24 + 255) / 256, 256>>>(h_, emb, agg_);
        gemm(agg_, h_, gw1, gb1, nullptr, t1_, NN, CC, CC, 1);       // relu((h+agg)@w1+b1)
        gemm(t1_, nullptr, gw2, gb2, h_, pre1_, NN, CC, CC, 0);      // t1@w2+b2 + h
        bn_stats<<<64, 96>>>(pre1_, st_ + 0, st_ + CC);

        // --- attention branch ---
        gemm(h_, nullptr, wqkv + (size_t)i * CC * 3 * CC, bqkv + (size_t)i * 3 * CC,
             nullptr, qkv_, NN, 3 * CC, CC, 0);
        flash_attn<<<dim3(NN / 128, NHEADS), 128>>>(qkv_, attno_);
        gemm(attno_, nullptr, wo + (size_t)i * CC * CC, bo + (size_t)i * CC,
             h_, pre2_, NN, CC, CC, 0);                               // attn@wo+bo + h
        bn_stats<<<64, 96>>>(pre2_, st_ + 2 * CC, st_ + 3 * CC);

        // --- merge + FFN ---
        bn2_add<<<(NCEL + 255) / 256, 256>>>(pre1_, pre2_, st_,
                                             bng + (size_t)i * 3 * CC, bnb + (size_t)i * 3 * CC,
                                             bng + (size_t)i * 3 * CC + CC, bnb + (size_t)i * 3 * CC + CC,
                                             outb_);
        gemm(outb_, nullptr, fw1 + (size_t)i * CC * 2 * CC, fb1 + (size_t)i * 2 * CC,
             nullptr, t2_, NN, 2 * CC, CC, 1);
        gemm(t2_, nullptr, fw2 + (size_t)i * 2 * CC * CC, fb2 + (size_t)i * CC,
             outb_, pre3_, NN, CC, 2 * CC, 0);
        bn_stats<<<64, 96>>>(pre3_, st_ + 4 * CC, st_ + 5 * CC);
        bn_apply<<<(NCEL + 255) / 256, 256>>>(pre3_, st_ + 4 * CC, st_ + 5 * CC,
                                              bng + (size_t)i * 3 * CC + 2 * CC,
                                              bnb + (size_t)i * 3 * CC + 2 * CC, h_);
    }

    // output projection + LayerNorm
    gemm(h_, nullptr, w_o, b_o, nullptr, y_, NN, CC, CC, 0);
    out_ln<<<NN / 4, 128>>>(y_, lng, lnb, out);
}

// round 3
// speedup vs baseline: 1.4206x; 1.4206x over previous
#include <cuda_runtime.h>

#define NN 4096
#define CC 96
#define EE 131072
#define NHEADS 4
#define DH 24
#define SPLITS 4
#define KPT (NN / SPLITS)

typedef unsigned long long u64;

// ---------------- scratch (no allocation allowed) ----------------
__device__ float g_h[NN*CC];
__device__ float g_agg[NN*CC];
__device__ float g_t1[NN*CC];
__device__ float g_pre1[NN*CC];
__device__ float g_qkv[NN*3*CC];
__device__ float g_attno[NN*CC];
__device__ float g_pre2[NN*CC];
__device__ float g_outb[NN*CC];
__device__ float g_t2[NN*2*CC];
__device__ float g_pre3[NN*CC];
__device__ float g_y[NN*CC];
__device__ float g_stats[6*CC];
__device__ int   g_src[EE];
__device__ int   g_dst[EE];
__device__ int   g_eat[EE];
__device__ int   g_flags[2];
// CSR
__device__ int   g_cnt[NN];
__device__ int   g_off[NN+1];
__device__ int   g_cur[NN];
__device__ int   g_csrc[EE];
__device__ int   g_ceat[EE];
// flash partials
__device__ float g_po[SPLITS*NHEADS*NN*DH];
__device__ float g_pm[SPLITS*NHEADS*NN];
__device__ float g_pl[SPLITS*NHEADS*NN];

// ---------------- packed f32x2 helpers ----------------
__device__ __forceinline__ u64 pack2(float lo, float hi) {
    u64 r; asm("mov.b64 %0,{%1,%2};" : "=l"(r) : "f"(lo), "f"(hi)); return r;
}
__device__ __forceinline__ void unpack2(u64 v, float& lo, float& hi) {
    asm("mov.b64 {%0,%1},%2;" : "=f"(lo), "=f"(hi) : "l"(v));
}
__device__ __forceinline__ u64 fma2(u64 a, u64 b, u64 c) {
    u64 d; asm("fma.rn.f32x2 %0,%1,%2,%3;" : "=l"(d) : "l"(a), "l"(b), "l"(c)); return d;
}
__device__ __forceinline__ u64 mul2(u64 a, u64 b) {
    u64 d; asm("mul.rn.f32x2 %0,%1,%2;" : "=l"(d) : "l"(a), "l"(b)); return d;
}
#define LDS2(r0, r1, addr, IMM) \
    asm("ld.shared.v2.u64 {%0,%1},[%2+" IMM "];" : "=l"(r0), "=l"(r1) : "r"(addr))

// ---------------- dtype detection + index decode ----------------
__global__ void detect_idx(const unsigned* __restrict__ ei, const unsigned* __restrict__ ea) {
    if (threadIdx.x == 0) {
        int z = 1;
        for (int k = 0; k < 16; k++) if (ei[2 * k + 1] != 0u) { z = 0; break; }
        g_flags[0] = z;
        int z2 = 1;
        for (int k = 0; k < 16; k++) if (ea[2 * k + 1] != 0u) { z2 = 0; break; }
        g_flags[1] = z2;
    }
}

__global__ void decode_idx(const void* __restrict__ ei, const void* __restrict__ ea) {
    int e = blockIdx.x * blockDim.x + threadIdx.x;
    if (e >= EE) return;
    if (g_flags[0]) {
        const long long* p = (const long long*)ei;
        g_src[e] = (int)p[e];
        g_dst[e] = (int)p[EE + e];
    } else {
        const int* p = (const int*)ei;
        g_src[e] = p[e];
        g_dst[e] = p[EE + e];
    }
    if (g_flags[1]) {
        const long long* p = (const long long*)ea;
        g_eat[e] = (int)p[e];
    } else {
        const int* p = (const int*)ea;
        g_eat[e] = p[e];
    }
}

// ---------------- utility ----------------
__global__ void zero_kernel(float* __restrict__ p, int n) {
    int i = blockIdx.x*blockDim.x + threadIdx.x;
    if (i < n) p[i] = 0.f;
}
__global__ void zero_int(int* __restrict__ p, int n) {
    int i = blockIdx.x*blockDim.x + threadIdx.x;
    if (i < n) p[i] = 0;
}

// ---------------- CSR build ----------------
__global__ void csr_count() {
    int e = blockIdx.x * blockDim.x + threadIdx.x;
    if (e < EE) atomicAdd(&g_cnt[g_dst[e]], 1);
}
__global__ __launch_bounds__(1024) void csr_scan() {
    __shared__ int sh[1024];
    int t = threadIdx.x;
    int c0 = g_cnt[4*t], c1 = g_cnt[4*t+1], c2 = g_cnt[4*t+2], c3 = g_cnt[4*t+3];
    int s = c0 + c1 + c2 + c3;
    sh[t] = s;
    __syncthreads();
    for (int o = 1; o < 1024; o <<= 1) {
        int v = (t >= o) ? sh[t - o] : 0;
        __syncthreads();
        sh[t] += v;
        __syncthreads();
    }
    int base = sh[t] - s;                 // exclusive
    g_off[4*t] = base;       g_cur[4*t] = base;
    g_off[4*t+1] = base+c0;  g_cur[4*t+1] = base+c0;
    g_off[4*t+2] = base+c0+c1; g_cur[4*t+2] = base+c0+c1;
    g_off[4*t+3] = base+c0+c1+c2; g_cur[4*t+3] = base+c0+c1+c2;
    if (t == 1023) g_off[NN] = sh[1023];
}
__global__ void csr_fill() {
    int e = blockIdx.x * blockDim.x + threadIdx.x;
    if (e >= EE) return;
    int pos = atomicAdd(&g_cur[g_dst[e]], 1);
    g_csrc[pos] = g_src[e];
    g_ceat[pos] = g_eat[e];
}

// ---------------- GINE aggregate: warp per node, no atomics ----------------
__global__ __launch_bounds__(256) void gine_agg(const float* __restrict__ h,
                                                const float* __restrict__ emb,
                                                float* __restrict__ agg) {
    int warp = (blockIdx.x * 256 + threadIdx.x) >> 5;
    int lane = threadIdx.x & 31;
    if (warp >= NN) return;
    int beg = g_off[warp], end = g_off[warp + 1];
    float a0 = 0.f, a1 = 0.f, a2 = 0.f;
    for (int i = beg; i < end; i++) {
        int src = g_csrc[i], et = g_ceat[i];
        const float* hp = h + (size_t)src * CC;
        const float* ep = emb + (size_t)et * CC;
        a0 += fmaxf(hp[lane]      + ep[lane],      0.f);
        a1 += fmaxf(hp[lane + 32] + ep[lane + 32], 0.f);
        a2 += fmaxf(hp[lane + 64] + ep[lane + 64], 0.f);
    }
    float* ap = agg + (size_t)warp * CC;
    ap[lane] = a0; ap[lane + 32] = a1; ap[lane + 64] = a2;
}

// ---------------- SGEMM: C = (A [+A2]) @ W + bias [+res] [relu] ----------------
__global__ __launch_bounds__(256) void sgemm(
    const float* __restrict__ A, const float* __restrict__ A2,
    const float* __restrict__ W, const float* __restrict__ bias,
    const float* __restrict__ res, float* __restrict__ C,
    int M, int N, int K, int relu)
{
    __shared__ float As[16][64];
    __shared__ float Bs[16][64];
    const int tid  = threadIdx.x;
    const int row0 = blockIdx.y * 64;
    const int col0 = blockIdx.x * 64;
    const int ty = tid >> 4, tx = tid & 15;

    const int ar = tid >> 2, ak = (tid & 3) * 4;
    const int bk = tid >> 4, bc = (tid & 15) * 4;

    float acc[4][4];
    #pragma unroll
    for (int i = 0; i < 4; i++)
        #pragma unroll
        for (int j = 0; j < 4; j++) acc[i][j] = 0.f;

    for (int k0 = 0; k0 < K; k0 += 16) {
        float4 a = *(const float4*)(A + (size_t)(row0 + ar) * K + k0 + ak);
        if (A2) {
            float4 a2 = *(const float4*)(A2 + (size_t)(row0 + ar) * K + k0 + ak);
            a.x += a2.x; a.y += a2.y; a.z += a2.z; a.w += a2.w;
        }
        As[ak + 0][ar] = a.x; As[ak + 1][ar] = a.y;
        As[ak + 2][ar] = a.z; As[ak + 3][ar] = a.w;

        float4 bv = make_float4(0.f, 0.f, 0.f, 0.f);
        if (col0 + bc < N)
            bv = *(const float4*)(W + (size_t)(k0 + bk) * N + col0 + bc);
        *(float4*)&Bs[bk][bc] = bv;

        __syncthreads();
        #pragma unroll
        for (int kk = 0; kk < 16; kk++) {
            float4 ra = *(const float4*)&As[kk][ty * 4];
            float4 rb = *(const float4*)&Bs[kk][tx * 4];
            float ja[4] = {ra.x, ra.y, ra.z, ra.w};
            float jb[4] = {rb.x, rb.y, rb.z, rb.w};
            #pragma unroll
            for (int i = 0; i < 4; i++)
                #pragma unroll
                for (int j = 0; j < 4; j++) acc[i][j] += ja[i] * jb[j];
        }
        __syncthreads();
    }

    #pragma unroll
    for (int i = 0; i < 4; i++) {
        int r = row0 + ty * 4 + i;
        #pragma unroll
        for (int j = 0; j < 4; j++) {
            int c = col0 + tx * 4 + j;
            if (c < N) {
                float v = acc[i][j] + bias[c];
                if (res) v += res[(size_t)r * N + c];
                if (relu) v = fmaxf(v, 0.f);
                C[(size_t)r * N + c] = v;
            }
        }
    }
}

// ---------------- split-K flash attention (f32x2 packed) ----------------
// grid (NN/128, NHEADS, SPLITS), 128 threads. Thread owns one query; keys [sp*KPT, sp*KPT+KPT).
__global__ __launch_bounds__(128) void flash_split(const float* __restrict__ qkv,
                                                   float* __restrict__ po,
                                                   float* __restrict__ pm,
                                                   float* __restrict__ pl) {
    const int h  = blockIdx.y;
    const int q0 = blockIdx.x * 128;
    const int sp = blockIdx.z;
    const int tid = threadIdx.x;
    __shared__ __align__(16) float Ks[128 * DH];
    __shared__ __align__(16) float Vs[128 * DH];
    const float scale = 0.20412414523193154f;  // 1/sqrt(24)

    u64 q2[12];
    {
        const float* qp = qkv + (size_t)(q0 + tid) * (3 * CC) + h * DH;
        const u64 sc2 = pack2(scale, scale);
        #pragma unroll
        for (int i = 0; i < 12; i++) q2[i] = mul2(((const u64*)qp)[i], sc2);
    }
    float m = -1e30f, l = 0.f;
    u64 o2[12];
    #pragma unroll
    for (int i = 0; i < 12; i++) o2[i] = 0ull;

    const unsigned ksb = (unsigned)__cvta_generic_to_shared(Ks);
    const unsigned vsb = (unsigned)__cvta_generic_to_shared(Vs);

    for (int kt = sp * KPT; kt < sp * KPT + KPT; kt += 128) {
        __syncthreads();
        {
            const float* kp = qkv + (size_t)(kt + tid) * (3 * CC) + CC + h * DH;
            #pragma unroll
            for (int d = 0; d < DH; d += 4) {
                *(float4*)&Ks[tid * DH + d] = *(const float4*)(kp + d);
                *(float4*)&Vs[tid * DH + d] = *(const float4*)(kp + CC + d);
            }
        }
        __syncthreads();

        #pragma unroll 1
        for (int j0 = 0; j0 < 128; j0 += 8) {
            float s[8];
            #pragma unroll
            for (int jj = 0; jj < 8; jj++) {
                u64 acc = 0ull;
                unsigned a = ksb + (j0 + jj) * (DH * 4);
                u64 k0, k1;
                LDS2(k0, k1, a, "0");  acc = fma2(q2[0],  k0, acc); acc = fma2(q2[1],  k1, acc);
                LDS2(k0, k1, a, "16"); acc = fma2(q2[2],  k0, acc); acc = fma2(q2[3],  k1, acc);
                LDS2(k0, k1, a, "32"); acc = fma2(q2[4],  k0, acc); acc = fma2(q2[5],  k1, acc);
                LDS2(k0, k1, a, "48"); acc = fma2(q2[6],  k0, acc); acc = fma2(q2[7],  k1, acc);
                LDS2(k0, k1, a, "64"); acc = fma2(q2[8],  k0, acc); acc = fma2(q2[9],  k1, acc);
                LDS2(k0, k1, a, "80"); acc = fma2(q2[10], k0, acc); acc = fma2(q2[11], k1, acc);
                float lo, hi; unpack2(acc, lo, hi);
                s[jj] = lo + hi;
            }
            float mx = m;
            #pragma unroll
            for (int jj = 0; jj < 8; jj++) mx = fmaxf(mx, s[jj]);
            float corr = __expf(m - mx);
            m = mx;
            float p[8], ps = 0.f;
            #pragma unroll
            for (int jj = 0; jj < 8; jj++) { p[jj] = __expf(s[jj] - mx); ps += p[jj]; }
            l = l * corr + ps;
            u64 corr2 = pack2(corr, corr);
            #pragma unroll
            for (int i = 0; i < 12; i++) o2[i] = mul2(o2[i], corr2);
            #pragma unroll
            for (int jj = 0; jj < 8; jj++) {
                u64 p2 = pack2(p[jj], p[jj]);
                unsigned a = vsb + (j0 + jj) * (DH * 4);
                u64 v0, v1;
                LDS2(v0, v1, a, "0");  o2[0]  = fma2(p2, v0, o2[0]);  o2[1]  = fma2(p2, v1, o2[1]);
                LDS2(v0, v1, a, "16"); o2[2]  = fma2(p2, v0, o2[2]);  o2[3]  = fma2(p2, v1, o2[3]);
                LDS2(v0, v1, a, "32"); o2[4]  = fma2(p2, v0, o2[4]);  o2[5]  = fma2(p2, v1, o2[5]);
                LDS2(v0, v1, a, "48"); o2[6]  = fma2(p2, v0, o2[6]);  o2[7]  = fma2(p2, v1, o2[7]);
                LDS2(v0, v1, a, "64"); o2[8]  = fma2(p2, v0, o2[8]);  o2[9]  = fma2(p2, v1, o2[9]);
                LDS2(v0, v1, a, "80"); o2[10] = fma2(p2, v0, o2[10]); o2[11] = fma2(p2, v1, o2[11]);
            }
        }
    }
    const int idx = (sp * NHEADS + h) * NN + q0 + tid;
    pm[idx] = m;
    pl[idx] = l;
    u64* op = (u64*)(po + (size_t)idx * DH);
    #pragma unroll
    for (int i = 0; i < 12; i++) op[i] = o2[i];
}

// merge splits: out[q, h*DH+d]
__global__ void flash_combine(const float* __restrict__ po, const float* __restrict__ pm,
                              const float* __restrict__ pl, float* __restrict__ outp) {
    int t = blockIdx.x * blockDim.x + threadIdx.x;
    if (t >= NN * NHEADS) return;
    int q = t & (NN - 1);
    int h = t >> 12;
    float ms[SPLITS], ls[SPLITS];
    float M = -1e30f;
    #pragma unroll
    for (int s = 0; s < SPLITS; s++) {
        ms[s] = pm[(s * NHEADS + h) * NN + q];
        ls[s] = pl[(s * NHEADS + h) * NN + q];
        M = fmaxf(M, ms[s]);
    }
    float w[SPLITS], L = 0.f;
    #pragma unroll
    for (int s = 0; s < SPLITS; s++) { w[s] = __expf(ms[s] - M); L += ls[s] * w[s]; }
    float inv = 1.f / L;
    float* op = outp + (size_t)q * CC + h * DH;
    #pragma unroll
    for (int d = 0; d < DH; d += 4) {
        float4 acc = make_float4(0.f, 0.f, 0.f, 0.f);
        #pragma unroll
        for (int s = 0; s < SPLITS; s++) {
            const float4 v = *(const float4*)(po + ((size_t)(s * NHEADS + h) * NN + q) * DH + d);
            acc.x += w[s] * v.x; acc.y += w[s] * v.y; acc.z += w[s] * v.z; acc.w += w[s] * v.w;
        }
        acc.x *= inv; acc.y *= inv; acc.z *= inv; acc.w *= inv;
        *(float4*)(op + d) = acc;
    }
}

// ---------------- BatchNorm: per-channel sum / sumsq over nodes ----------------
__global__ void bn_stats(const float* __restrict__ x, float* __restrict__ s,
                         float* __restrict__ s2) {
    int c  = threadIdx.x;
    int r0 = blockIdx.x * 64;
    float a = 0.f, b = 0.f;
    for (int r = r0; r < r0 + 64; r++) {
        float v = x[(size_t)r * CC + c];
        a += v; b += v * v;
    }
    atomicAdd(&s[c], a);
    atomicAdd(&s2[c], b);
}

__global__ void bn2_add(const float* __restrict__ p1, const float* __restrict__ p2,
                        const float* __restrict__ st,
                        const float* __restrict__ g1, const float* __restrict__ b1,
                        const float* __restrict__ g2, const float* __restrict__ b2,
                        float* __restrict__ out) {
    int i = blockIdx.x * blockDim.x + threadIdx.x;
    if (i >= NN * CC) return;
    int c = i % CC;
    const float invn = 1.f / NN;
    float m1 = st[c] * invn;
    float v1 = st[CC + c] * invn - m1 * m1;
    float m2 = st[2 * CC + c] * invn;
    float v2 = st[3 * CC + c] * invn - m2 * m2;
    float o = (p1[i] - m1) * rsqrtf(v1 + 1e-5f) * g1[c] + b1[c]
            + (p2[i] - m2) * rsqrtf(v2 + 1e-5f) * g2[c] + b2[c];
    out[i] = o;
}

__global__ void bn_apply(const float* __restrict__ p, const float* __restrict__ s,
                         const float* __restrict__ s2, const float* __restrict__ g,
                         const float* __restrict__ b, float* __restrict__ o) {
    int i = blockIdx.x * blockDim.x + threadIdx.x;
    if (i >= NN * CC) return;
    int c = i % CC;
    const float invn = 1.f / NN;
    float m = s[c] * invn;
    float v = s2[c] * invn - m * m;
    o[i] = (p[i] - m) * rsqrtf(v + 1e-5f) * g[c] + b[c];
}

// ---------------- final per-row LayerNorm, one warp per row ----------------
__global__ void out_ln(const float* __restrict__ y, const float* __restrict__ g,
                       const float* __restrict__ b, float* __restrict__ out) {
    int lane = threadIdx.x & 31;
    int warp = threadIdx.x >> 5;
    int row  = blockIdx.x * 4 + warp;
    const float* yr = y + (size_t)row * CC;
    float v0 = yr[lane], v1 = yr[lane + 32], v2 = yr[lane + 64];
    float s = v0 + v1 + v2;
    #pragma unroll
    for (int o = 16; o; o >>= 1) s += __shfl_xor_sync(0xffffffffu, s, o);
    float mean = s * (1.f / 96.f);
    float d0 = v0 - mean, d1 = v1 - mean, d2 = v2 - mean;
    float qv = d0 * d0 + d1 * d1 + d2 * d2;
    #pragma unroll
    for (int o = 16; o; o >>= 1) qv += __shfl_xor_sync(0xffffffffu, qv, o);
    float inv = rsqrtf(qv * (1.f / 96.f) + 1e-5f);
    float* orow = out + (size_t)row * CC;
    orow[lane]      = d0 * inv * g[lane]      + b[lane];
    orow[lane + 32] = d1 * inv * g[lane + 32] + b[lane + 32];
    orow[lane + 64] = d2 * inv * g[lane + 64] + b[lane + 64];
}

// ---------------- launch ----------------
extern "C" void kernel_launch(void* const* d_in, const int* in_sizes, int n_in,
                              void* d_out, int out_size) {
    const float*     x    = (const float*)d_in[0];
    const void*      ei   = d_in[1];
    const void*      ea   = d_in[2];
    const float*     w_in = (const float*)d_in[3];
    const float*     b_in = (const float*)d_in[4];
    const float*     emb  = (const float*)d_in[5];
    const float*     gw1  = (const float*)d_in[6];
    const float*     gb1  = (const float*)d_in[7];
    const float*     gw2  = (const float*)d_in[8];
    const float*     gb2  = (const float*)d_in[9];
    const float*     wqkv = (const float*)d_in[10];
    const float*     bqkv = (const float*)d_in[11];
    const float*     wo   = (const float*)d_in[12];
    const float*     bo   = (const float*)d_in[13];
    const float*     bng  = (const float*)d_in[14];
    const float*     bnb  = (const float*)d_in[15];
    const float*     fw1  = (const float*)d_in[16];
    const float*     fb1  = (const float*)d_in[17];
    const float*     fw2  = (const float*)d_in[18];
    const float*     fb2  = (const float*)d_in[19];
    const float*     w_o  = (const float*)d_in[20];
    const float*     b_o  = (const float*)d_in[21];
    const float*     lng  = (const float*)d_in[22];
    const float*     lnb  = (const float*)d_in[23];
    float* out = (float*)d_out;

    float *h_, *agg_, *t1_, *pre1_, *qkv_, *attno_, *pre2_, *outb_, *t2_, *pre3_, *y_, *st_;
    float *po_, *pm_, *pl_;
    int *cnt_;
    cudaGetSymbolAddress((void**)&h_,    g_h);
    cudaGetSymbolAddress((void**)&agg_,  g_agg);
    cudaGetSymbolAddress((void**)&t1_,   g_t1);
    cudaGetSymbolAddress((void**)&pre1_, g_pre1);
    cudaGetSymbolAddress((void**)&qkv_,  g_qkv);
    cudaGetSymbolAddress((void**)&attno_,g_attno);
    cudaGetSymbolAddress((void**)&pre2_, g_pre2);
    cudaGetSymbolAddress((void**)&outb_, g_outb);
    cudaGetSymbolAddress((void**)&t2_,   g_t2);
    cudaGetSymbolAddress((void**)&pre3_, g_pre3);
    cudaGetSymbolAddress((void**)&y_,    g_y);
    cudaGetSymbolAddress((void**)&st_,   g_stats);
    cudaGetSymbolAddress((void**)&po_,   g_po);
    cudaGetSymbolAddress((void**)&pm_,   g_pm);
    cudaGetSymbolAddress((void**)&pl_,   g_pl);
    cudaGetSymbolAddress((void**)&cnt_,  g_cnt);

    auto gemm = [&](const float* A, const float* A2, const float* W, const float* bias,
                    const float* res, float* Cp, int M, int Nc, int K, int relu) {
        dim3 grid((Nc + 63) / 64, M / 64);
        sgemm<<<grid, 256>>>(A, A2, W, bias, res, Cp, M, Nc, K, relu);
    };

    const int NCEL = NN * CC;

    // edge decode + CSR build (once per launch)
    detect_idx<<<1, 32>>>((const unsigned*)ei, (const unsigned*)ea);
    decode_idx<<<(EE + 255) / 256, 256>>>(ei, ea);
    zero_int<<<(NN + 255) / 256, 256>>>(cnt_, NN);
    csr_count<<<(EE + 255) / 256, 256>>>();
    csr_scan<<<1, 1024>>>();
    csr_fill<<<(EE + 255) / 256, 256>>>();

    // input projection
    gemm(x, nullptr, w_in, b_in, nullptr, h_, NN, CC, 64, 0);

    for (int i = 0; i < 2; i++) {
        zero_kernel<<<3, 256>>>(st_, 6 * CC);

        // --- GINE branch (atomic-free) ---
        gine_agg<<<NN / 8, 256>>>(h_, emb, agg_);
        gemm(agg_, h_, gw1, gb1, nullptr, t1_, NN, CC, CC, 1);
        gemm(t1_, nullptr, gw2, gb2, h_, pre1_, NN, CC, CC, 0);
        bn_stats<<<64, 96>>>(pre1_, st_ + 0, st_ + CC);

        // --- attention branch ---
        gemm(h_, nullptr, wqkv + (size_t)i * CC * 3 * CC, bqkv + (size_t)i * 3 * CC,
             nullptr, qkv_, NN, 3 * CC, CC, 0);
        flash_split<<<dim3(NN / 128, NHEADS, SPLITS), 128>>>(qkv_, po_, pm_, pl_);
        flash_combine<<<(NN * NHEADS + 255) / 256, 256>>>(po_, pm_, pl_, attno_);
        gemm(attno_, nullptr, wo + (size_t)i * CC * CC, bo + (size_t)i * CC,
             h_, pre2_, NN, CC, CC, 0);
        bn_stats<<<64, 96>>>(pre2_, st_ + 2 * CC, st_ + 3 * CC);

        // --- merge + FFN ---
        bn2_add<<<(NCEL + 255) / 256, 256>>>(pre1_, pre2_, st_,
                                             bng + (size_t)i * 3 * CC, bnb + (size_t)i * 3 * CC,
                                             bng + (size_t)i * 3 * CC + CC, bnb + (size_t)i * 3 * CC + CC,
                                             outb_);
        gemm(outb_, nullptr, fw1 + (size_t)i * CC * 2 * CC, fb1 + (size_t)i * 2 * CC,
             nullptr, t2_, NN, 2 * CC, CC, 1);
        gemm(t2_, nullptr, fw2 + (size_t)i * 2 * CC * CC, fb2 + (size_t)i * CC,
             outb_, pre3_, NN, CC, 2 * CC, 0);
        bn_stats<<<64, 96>>>(pre3_, st_ + 4 * CC, st_ + 5 * CC);
        bn_apply<<<(NCEL + 255) / 256, 256>>>(pre3_, st_ + 4 * CC, st_ + 5 * CC,
                                              bng + (size_t)i * 3 * CC + 2 * CC,
                                              bnb + (size_t)i * 3 * CC + 2 * CC, h_);
    }

    // output projection + LayerNorm
    gemm(h_, nullptr, w_o, b_o, nullptr, y_, NN, CC, CC, 0);
    out_ln<<<NN / 4, 128>>>(y_, lng, lnb, out);
}

// round 4
// speedup vs baseline: 1.6832x; 1.1848x over previous
#include <cuda_runtime.h>

#define NN 4096
#define CC 96
#define EE 131072
#define NHEADS 4
#define DH 24
#define SPLITS 8
#define KPT (NN / SPLITS)

typedef unsigned long long u64;

// ---------------- scratch ----------------
__device__ float g_h[NN*CC];
__device__ float g_agg[NN*CC];
__device__ float g_t1[NN*CC];
__device__ float g_pre1[NN*CC];
__device__ float g_qkv[NN*3*CC];
__device__ float g_attno[NN*CC];
__device__ float g_pre2[NN*CC];
__device__ float g_outb[NN*CC];
__device__ float g_t2[NN*2*CC];
__device__ float g_pre3[NN*CC];
__device__ float g_y[NN*CC];
__device__ float g_stats[6*CC];
__device__ int   g_src[EE];
__device__ int   g_dst[EE];
__device__ int   g_eat[EE];
__device__ int   g_flags[2];
__device__ int   g_cnt[NN];
__device__ int   g_off[NN+1];
__device__ int   g_cur[NN];
__device__ int   g_csrc[EE];
__device__ int   g_ceat[EE];
__device__ float g_po[SPLITS*NHEADS*NN*DH];
__device__ float g_pm[SPLITS*NHEADS*NN];
__device__ float g_pl[SPLITS*NHEADS*NN];

// ---------------- packed f32x2 helpers ----------------
__device__ __forceinline__ u64 pack2(float lo, float hi) {
    u64 r; asm("mov.b64 %0,{%1,%2};" : "=l"(r) : "f"(lo), "f"(hi)); return r;
}
__device__ __forceinline__ void unpack2(u64 v, float& lo, float& hi) {
    asm("mov.b64 {%0,%1},%2;" : "=f"(lo), "=f"(hi) : "l"(v));
}
__device__ __forceinline__ u64 fma2(u64 a, u64 b, u64 c) {
    u64 d; asm("fma.rn.f32x2 %0,%1,%2,%3;" : "=l"(d) : "l"(a), "l"(b), "l"(c)); return d;
}
__device__ __forceinline__ u64 mul2(u64 a, u64 b) {
    u64 d; asm("mul.rn.f32x2 %0,%1,%2;" : "=l"(d) : "l"(a), "l"(b)); return d;
}
#define LDS2(r0, r1, addr, IMM) \
    asm("ld.shared.v2.u64 {%0,%1},[%2+" IMM "];" : "=l"(r0), "=l"(r1) : "r"(addr))

// ---------------- dtype detection (warp-parallel) ----------------
__global__ void detect_idx(const unsigned* __restrict__ ei, const unsigned* __restrict__ ea) {
    int lane = threadIdx.x;
    unsigned v1 = (lane < 16) ? ei[2 * lane + 1] : 0u;
    unsigned v2 = (lane < 16) ? ea[2 * lane + 1] : 0u;
    unsigned b1 = __ballot_sync(0xffffffffu, v1 != 0u);
    unsigned b2 = __ballot_sync(0xffffffffu, v2 != 0u);
    if (lane == 0) { g_flags[0] = (b1 == 0u); g_flags[1] = (b2 == 0u); }
}

// decode + dst-degree count in one pass
__global__ void decode_idx(const void* __restrict__ ei, const void* __restrict__ ea) {
    int e = blockIdx.x * blockDim.x + threadIdx.x;
    if (e >= EE) return;
    int s, d, a;
    if (g_flags[0]) {
        const long long* p = (const long long*)ei;
        s = (int)p[e]; d = (int)p[EE + e];
    } else {
        const int* p = (const int*)ei;
        s = p[e]; d = p[EE + e];
    }
    if (g_flags[1]) {
        const long long* p = (const long long*)ea;
        a = (int)p[e];
    } else {
        const int* p = (const int*)ea;
        a = p[e];
    }
    g_src[e] = s; g_dst[e] = d; g_eat[e] = a;
    atomicAdd(&g_cnt[d], 1);
}

// ---------------- utility ----------------
__global__ void zero_kernel(float* __restrict__ p, int n) {
    int i = blockIdx.x*blockDim.x + threadIdx.x;
    if (i < n) p[i] = 0.f;
}
__global__ void zero_int(int* __restrict__ p, int n) {
    int i = blockIdx.x*blockDim.x + threadIdx.x;
    if (i < n) p[i] = 0;
}

// ---------------- CSR build ----------------
__global__ __launch_bounds__(1024) void csr_scan() {
    __shared__ int sh[1024];
    int t = threadIdx.x;
    int c0 = g_cnt[4*t], c1 = g_cnt[4*t+1], c2 = g_cnt[4*t+2], c3 = g_cnt[4*t+3];
    int s = c0 + c1 + c2 + c3;
    sh[t] = s;
    __syncthreads();
    for (int o = 1; o < 1024; o <<= 1) {
        int v = (t >= o) ? sh[t - o] : 0;
        __syncthreads();
        sh[t] += v;
        __syncthreads();
    }
    int base = sh[t] - s;
    g_off[4*t] = base;            g_cur[4*t] = base;
    g_off[4*t+1] = base+c0;       g_cur[4*t+1] = base+c0;
    g_off[4*t+2] = base+c0+c1;    g_cur[4*t+2] = base+c0+c1;
    g_off[4*t+3] = base+c0+c1+c2; g_cur[4*t+3] = base+c0+c1+c2;
    if (t == 1023) g_off[NN] = sh[1023];
}
__global__ void csr_fill() {
    int e = blockIdx.x * blockDim.x + threadIdx.x;
    if (e >= EE) return;
    int pos = atomicAdd(&g_cur[g_dst[e]], 1);
    g_csrc[pos] = g_src[e];
    g_ceat[pos] = g_eat[e];
}

// ---------------- GINE aggregate: warp per node, no atomics ----------------
__global__ __launch_bounds__(256) void gine_agg(const float* __restrict__ h,
                                                const float* __restrict__ emb,
                                                float* __restrict__ agg) {
    int warp = (blockIdx.x * 256 + threadIdx.x) >> 5;
    int lane = threadIdx.x & 31;
    if (warp >= NN) return;
    int beg = g_off[warp], end = g_off[warp + 1];
    float a0 = 0.f, a1 = 0.f, a2 = 0.f;
    for (int i = beg; i < end; i++) {
        int src = g_csrc[i], et = g_ceat[i];
        const float* hp = h + (size_t)src * CC;
        const float* ep = emb + (size_t)et * CC;
        a0 += fmaxf(hp[lane]      + ep[lane],      0.f);
        a1 += fmaxf(hp[lane + 32] + ep[lane + 32], 0.f);
        a2 += fmaxf(hp[lane + 64] + ep[lane + 64], 0.f);
    }
    float* ap = agg + (size_t)warp * CC;
    ap[lane] = a0; ap[lane + 32] = a1; ap[lane + 64] = a2;
}

// ---------------- SGEMM with optional fused BN-stats epilogue ----------------
__global__ __launch_bounds__(256) void sgemm(
    const float* __restrict__ A, const float* __restrict__ A2,
    const float* __restrict__ W, const float* __restrict__ bias,
    const float* __restrict__ res, float* __restrict__ C,
    int M, int N, int K, int relu,
    float* __restrict__ st_s, float* __restrict__ st_s2)
{
    __shared__ float As[16][64];
    __shared__ float Bs[16][64];
    const int tid  = threadIdx.x;
    const int row0 = blockIdx.y * 64;
    const int col0 = blockIdx.x * 64;
    const int ty = tid >> 4, tx = tid & 15;

    const int ar = tid >> 2, ak = (tid & 3) * 4;
    const int bk = tid >> 4, bc = (tid & 15) * 4;

    float acc[4][4];
    #pragma unroll
    for (int i = 0; i < 4; i++)
        #pragma unroll
        for (int j = 0; j < 4; j++) acc[i][j] = 0.f;

    for (int k0 = 0; k0 < K; k0 += 16) {
        float4 a = *(const float4*)(A + (size_t)(row0 + ar) * K + k0 + ak);
        if (A2) {
            float4 a2 = *(const float4*)(A2 + (size_t)(row0 + ar) * K + k0 + ak);
            a.x += a2.x; a.y += a2.y; a.z += a2.z; a.w += a2.w;
        }
        As[ak + 0][ar] = a.x; As[ak + 1][ar] = a.y;
        As[ak + 2][ar] = a.z; As[ak + 3][ar] = a.w;

        float4 bv = make_float4(0.f, 0.f, 0.f, 0.f);
        if (col0 + bc < N)
            bv = *(const float4*)(W + (size_t)(k0 + bk) * N + col0 + bc);
        *(float4*)&Bs[bk][bc] = bv;

        __syncthreads();
        #pragma unroll
        for (int kk = 0; kk < 16; kk++) {
            float4 ra = *(const float4*)&As[kk][ty * 4];
            float4 rb = *(const float4*)&Bs[kk][tx * 4];
            float ja[4] = {ra.x, ra.y, ra.z, ra.w};
            float jb[4] = {rb.x, rb.y, rb.z, rb.w};
            #pragma unroll
            for (int i = 0; i < 4; i++)
                #pragma unroll
                for (int j = 0; j < 4; j++) acc[i][j] += ja[i] * jb[j];
        }
        __syncthreads();
    }

    float cs[4] = {0.f, 0.f, 0.f, 0.f};
    float cq[4] = {0.f, 0.f, 0.f, 0.f};
    #pragma unroll
    for (int i = 0; i < 4; i++) {
        int r = row0 + ty * 4 + i;
        #pragma unroll
        for (int j = 0; j < 4; j++) {
            int c = col0 + tx * 4 + j;
            if (c < N) {
                float v = acc[i][j] + bias[c];
                if (res) v += res[(size_t)r * N + c];
                if (relu) v = fmaxf(v, 0.f);
                C[(size_t)r * N + c] = v;
                cs[j] += v; cq[j] += v * v;
            }
        }
    }

    if (st_s) {
        __syncthreads();   // re-use As/Bs
        #pragma unroll
        for (int j = 0; j < 4; j++) { As[ty][tx * 4 + j] = cs[j]; Bs[ty][tx * 4 + j] = cq[j]; }
        __syncthreads();
        if (tid < 64) {
            int c = col0 + tid;
            if (c < N) {
                float a = 0.f, b = 0.f;
                #pragma unroll
                for (int t = 0; t < 16; t++) { a += As[t][tid]; b += Bs[t][tid]; }
                atomicAdd(&st_s[c], a);
                atomicAdd(&st_s2[c], b);
            }
        }
    }
}

// ---------------- split-K flash attention, 2 queries per thread ----------------
// grid (NN/256, NHEADS, SPLITS), 128 threads. Thread owns queries q0+tid and q0+128+tid.
__global__ __launch_bounds__(128) void flash_split(const float* __restrict__ qkv,
                                                   float* __restrict__ po,
                                                   float* __restrict__ pm,
                                                   float* __restrict__ pl) {
    const int h  = blockIdx.y;
    const int q0 = blockIdx.x * 256;
    const int sp = blockIdx.z;
    const int tid = threadIdx.x;
    __shared__ __align__(16) float Ks[128 * DH];
    __shared__ __align__(16) float Vs[128 * DH];
    const float scale = 0.20412414523193154f;  // 1/sqrt(24)

    u64 qa[12], qb[12];
    {
        const u64 sc2 = pack2(scale, scale);
        const float* qpa = qkv + (size_t)(q0 + tid) * (3 * CC) + h * DH;
        const float* qpb = qkv + (size_t)(q0 + 128 + tid) * (3 * CC) + h * DH;
        #pragma unroll
        for (int i = 0; i < 12; i++) {
            qa[i] = mul2(((const u64*)qpa)[i], sc2);
            qb[i] = mul2(((const u64*)qpb)[i], sc2);
        }
    }
    float ma = -1e30f, la = 0.f, mb = -1e30f, lb = 0.f;
    u64 oa[12], ob[12];
    #pragma unroll
    for (int i = 0; i < 12; i++) { oa[i] = 0ull; ob[i] = 0ull; }

    const unsigned ksb = (unsigned)__cvta_generic_to_shared(Ks);
    const unsigned vsb = (unsigned)__cvta_generic_to_shared(Vs);

    for (int kt = sp * KPT; kt < sp * KPT + KPT; kt += 128) {
        __syncthreads();
        {
            const float* kp = qkv + (size_t)(kt + tid) * (3 * CC) + CC + h * DH;
            #pragma unroll
            for (int d = 0; d < DH; d += 4) {
                *(float4*)&Ks[tid * DH + d] = *(const float4*)(kp + d);
                *(float4*)&Vs[tid * DH + d] = *(const float4*)(kp + CC + d);
            }
        }
        __syncthreads();

        #pragma unroll 1
        for (int j0 = 0; j0 < 128; j0 += 8) {
            float sa[8], sb[8];
            #pragma unroll
            for (int jj = 0; jj < 8; jj++) {
                u64 aca = 0ull, acb = 0ull;
                unsigned a = ksb + (j0 + jj) * (DH * 4);
                u64 k0, k1;
#define QKS(IMM, i0, i1) \
                LDS2(k0, k1, a, IMM); \
                aca = fma2(qa[i0], k0, aca); acb = fma2(qb[i0], k0, acb); \
                aca = fma2(qa[i1], k1, aca); acb = fma2(qb[i1], k1, acb);
                QKS("0", 0, 1)  QKS("16", 2, 3)  QKS("32", 4, 5)
                QKS("48", 6, 7) QKS("64", 8, 9)  QKS("80", 10, 11)
#undef QKS
                float lo, hi;
                unpack2(aca, lo, hi); sa[jj] = lo + hi;
                unpack2(acb, lo, hi); sb[jj] = lo + hi;
            }
            float mxa = ma, mxb = mb;
            #pragma unroll
            for (int jj = 0; jj < 8; jj++) { mxa = fmaxf(mxa, sa[jj]); mxb = fmaxf(mxb, sb[jj]); }
            float ca = __expf(ma - mxa), cb = __expf(mb - mxb);
            ma = mxa; mb = mxb;
            float pa[8], pb[8], psa = 0.f, psb = 0.f;
            #pragma unroll
            for (int jj = 0; jj < 8; jj++) {
                pa[jj] = __expf(sa[jj] - mxa); psa += pa[jj];
                pb[jj] = __expf(sb[jj] - mxb); psb += pb[jj];
            }
            la = la * ca + psa; lb = lb * cb + psb;
            u64 ca2 = pack2(ca, ca), cb2 = pack2(cb, cb);
            #pragma unroll
            for (int i = 0; i < 12; i++) { oa[i] = mul2(oa[i], ca2); ob[i] = mul2(ob[i], cb2); }
            #pragma unroll
            for (int jj = 0; jj < 8; jj++) {
                u64 pa2 = pack2(pa[jj], pa[jj]);
                u64 pb2 = pack2(pb[jj], pb[jj]);
                unsigned a = vsb + (j0 + jj) * (DH * 4);
                u64 v0, v1;
#define AVS(IMM, i0, i1) \
                LDS2(v0, v1, a, IMM); \
                oa[i0] = fma2(pa2, v0, oa[i0]); ob[i0] = fma2(pb2, v0, ob[i0]); \
                oa[i1] = fma2(pa2, v1, oa[i1]); ob[i1] = fma2(pb2, v1, ob[i1]);
                AVS("0", 0, 1)  AVS("16", 2, 3)  AVS("32", 4, 5)
                AVS("48", 6, 7) AVS("64", 8, 9)  AVS("80", 10, 11)
#undef AVS
            }
        }
    }
    {
        const int idx = (sp * NHEADS + h) * NN + q0 + tid;
        pm[idx] = ma; pl[idx] = la;
        u64* op = (u64*)(po + (size_t)idx * DH);
        #pragma unroll
        for (int i = 0; i < 12; i++) op[i] = oa[i];
    }
    {
        const int idx = (sp * NHEADS + h) * NN + q0 + 128 + tid;
        pm[idx] = mb; pl[idx] = lb;
        u64* op = (u64*)(po + (size_t)idx * DH);
        #pragma unroll
        for (int i = 0; i < 12; i++) op[i] = ob[i];
    }
}

__global__ void flash_combine(const float* __restrict__ po, const float* __restrict__ pm,
                              const float* __restrict__ pl, float* __restrict__ outp) {
    int t = blockIdx.x * blockDim.x + threadIdx.x;
    if (t >= NN * NHEADS) return;
    int q = t & (NN - 1);
    int h = t >> 12;
    float ms[SPLITS], ls[SPLITS];
    float M = -1e30f;
    #pragma unroll
    for (int s = 0; s < SPLITS; s++) {
        ms[s] = pm[(s * NHEADS + h) * NN + q];
        ls[s] = pl[(s * NHEADS + h) * NN + q];
        M = fmaxf(M, ms[s]);
    }
    float w[SPLITS], L = 0.f;
    #pragma unroll
    for (int s = 0; s < SPLITS; s++) { w[s] = __expf(ms[s] - M); L += ls[s] * w[s]; }
    float inv = 1.f / L;
    float* op = outp + (size_t)q * CC + h * DH;
    #pragma unroll
    for (int d = 0; d < DH; d += 4) {
        float4 acc = make_float4(0.f, 0.f, 0.f, 0.f);
        #pragma unroll
        for (int s = 0; s < SPLITS; s++) {
            const float4 v = *(const float4*)(po + ((size_t)(s * NHEADS + h) * NN + q) * DH + d);
            acc.x += w[s] * v.x; acc.y += w[s] * v.y; acc.z += w[s] * v.z; acc.w += w[s] * v.w;
        }
        acc.x *= inv; acc.y *= inv; acc.z *= inv; acc.w *= inv;
        *(float4*)(op + d) = acc;
    }
}

// ---------------- BN elementwise ----------------
__global__ void bn2_add(const float* __restrict__ p1, const float* __restrict__ p2,
                        const float* __restrict__ st,
                        const float* __restrict__ g1, const float* __restrict__ b1,
                        const float* __restrict__ g2, const float* __restrict__ b2,
                        float* __restrict__ out) {
    int i = blockIdx.x * blockDim.x + threadIdx.x;
    if (i >= NN * CC) return;
    int c = i % CC;
    const float invn = 1.f / NN;
    float m1 = st[c] * invn;
    float v1 = st[CC + c] * invn - m1 * m1;
    float m2 = st[2 * CC + c] * invn;
    float v2 = st[3 * CC + c] * invn - m2 * m2;
    float o = (p1[i] - m1) * rsqrtf(v1 + 1e-5f) * g1[c] + b1[c]
            + (p2[i] - m2) * rsqrtf(v2 + 1e-5f) * g2[c] + b2[c];
    out[i] = o;
}

__global__ void bn_apply(const float* __restrict__ p, const float* __restrict__ s,
                         const float* __restrict__ s2, const float* __restrict__ g,
                         const float* __restrict__ b, float* __restrict__ o) {
    int i = blockIdx.x * blockDim.x + threadIdx.x;
    if (i >= NN * CC) return;
    int c = i % CC;
    const float invn = 1.f / NN;
    float m = s[c] * invn;
    float v = s2[c] * invn - m * m;
    o[i] = (p[i] - m) * rsqrtf(v + 1e-5f) * g[c] + b[c];
}

// ---------------- final per-row LayerNorm ----------------
__global__ void out_ln(const float* __restrict__ y, const float* __restrict__ g,
                       const float* __restrict__ b, float* __restrict__ out) {
    int lane = threadIdx.x & 31;
    int warp = threadIdx.x >> 5;
    int row  = blockIdx.x * 4 + warp;
    const float* yr = y + (size_t)row * CC;
    float v0 = yr[lane], v1 = yr[lane + 32], v2 = yr[lane + 64];
    float s = v0 + v1 + v2;
    #pragma unroll
    for (int o = 16; o; o >>= 1) s += __shfl_xor_sync(0xffffffffu, s, o);
    float mean = s * (1.f / 96.f);
    float d0 = v0 - mean, d1 = v1 - mean, d2 = v2 - mean;
    float qv = d0 * d0 + d1 * d1 + d2 * d2;
    #pragma unroll
    for (int o = 16; o; o >>= 1) qv += __shfl_xor_sync(0xffffffffu, qv, o);
    float inv = rsqrtf(qv * (1.f / 96.f) + 1e-5f);
    float* orow = out + (size_t)row * CC;
    orow[lane]      = d0 * inv * g[lane]      + b[lane];
    orow[lane + 32] = d1 * inv * g[lane + 32] + b[lane + 32];
    orow[lane + 64] = d2 * inv * g[lane + 64] + b[lane + 64];
}

// ---------------- launch ----------------
extern "C" void kernel_launch(void* const* d_in, const int* in_sizes, int n_in,
                              void* d_out, int out_size) {
    const float*     x    = (const float*)d_in[0];
    const void*      ei   = d_in[1];
    const void*      ea   = d_in[2];
    const float*     w_in = (const float*)d_in[3];
    const float*     b_in = (const float*)d_in[4];
    const float*     emb  = (const float*)d_in[5];
    const float*     gw1  = (const float*)d_in[6];
    const float*     gb1  = (const float*)d_in[7];
    const float*     gw2  = (const float*)d_in[8];
    const float*     gb2  = (const float*)d_in[9];
    const float*     wqkv = (const float*)d_in[10];
    const float*     bqkv = (const float*)d_in[11];
    const float*     wo   = (const float*)d_in[12];
    const float*     bo   = (const float*)d_in[13];
    const float*     bng  = (const float*)d_in[14];
    const float*     bnb  = (const float*)d_in[15];
    const float*     fw1  = (const float*)d_in[16];
    const float*     fb1  = (const float*)d_in[17];
    const float*     fw2  = (const float*)d_in[18];
    const float*     fb2  = (const float*)d_in[19];
    const float*     w_o  = (const float*)d_in[20];
    const float*     b_o  = (const float*)d_in[21];
    const float*     lng  = (const float*)d_in[22];
    const float*     lnb  = (const float*)d_in[23];
    float* out = (float*)d_out;

    float *h_, *agg_, *t1_, *pre1_, *qkv_, *attno_, *pre2_, *outb_, *t2_, *pre3_, *y_, *st_;
    float *po_, *pm_, *pl_;
    int *cnt_;
    cudaGetSymbolAddress((void**)&h_,    g_h);
    cudaGetSymbolAddress((void**)&agg_,  g_agg);
    cudaGetSymbolAddress((void**)&t1_,   g_t1);
    cudaGetSymbolAddress((void**)&pre1_, g_pre1);
    cudaGetSymbolAddress((void**)&qkv_,  g_qkv);
    cudaGetSymbolAddress((void**)&attno_,g_attno);
    cudaGetSymbolAddress((void**)&pre2_, g_pre2);
    cudaGetSymbolAddress((void**)&outb_, g_outb);
    cudaGetSymbolAddress((void**)&t2_,   g_t2);
    cudaGetSymbolAddress((void**)&pre3_, g_pre3);
    cudaGetSymbolAddress((void**)&y_,    g_y);
    cudaGetSymbolAddress((void**)&st_,   g_stats);
    cudaGetSymbolAddress((void**)&po_,   g_po);
    cudaGetSymbolAddress((void**)&pm_,   g_pm);
    cudaGetSymbolAddress((void**)&pl_,   g_pl);
    cudaGetSymbolAddress((void**)&cnt_,  g_cnt);

    auto gemm = [&](const float* A, const float* A2, const float* W, const float* bias,
                    const float* res, float* Cp, int M, int Nc, int K, int relu,
                    float* ss = nullptr, float* ss2 = nullptr) {
        dim3 grid((Nc + 63) / 64, M / 64);
        sgemm<<<grid, 256>>>(A, A2, W, bias, res, Cp, M, Nc, K, relu, ss, ss2);
    };

    const int NCEL = NN * CC;

    // CSR prologue
    detect_idx<<<1, 32>>>((const unsigned*)ei, (const unsigned*)ea);
    zero_int<<<(NN + 255) / 256, 256>>>(cnt_, NN);
    decode_idx<<<(EE + 255) / 256, 256>>>(ei, ea);
    csr_scan<<<1, 1024>>>();
    csr_fill<<<(EE + 255) / 256, 256>>>();

    gemm(x, nullptr, w_in, b_in, nullptr, h_, NN, CC, 64, 0);

    for (int i = 0; i < 2; i++) {
        zero_kernel<<<3, 256>>>(st_, 6 * CC);

        // --- GINE branch ---
        gine_agg<<<NN / 8, 256>>>(h_, emb, agg_);
        gemm(agg_, h_, gw1, gb1, nullptr, t1_, NN, CC, CC, 1);
        gemm(t1_, nullptr, gw2, gb2, h_, pre1_, NN, CC, CC, 0, st_ + 0, st_ + CC);

        // --- attention branch ---
        gemm(h_, nullptr, wqkv + (size_t)i * CC * 3 * CC, bqkv + (size_t)i * 3 * CC,
             nullptr, qkv_, NN, 3 * CC, CC, 0);
        flash_split<<<dim3(NN / 256, NHEADS, SPLITS), 128>>>(qkv_, po_, pm_, pl_);
        flash_combine<<<(NN * NHEADS + 255) / 256, 256>>>(po_, pm_, pl_, attno_);
        gemm(attno_, nullptr, wo + (size_t)i * CC * CC, bo + (size_t)i * CC,
             h_, pre2_, NN, CC, CC, 0, st_ + 2 * CC, st_ + 3 * CC);

        // --- merge + FFN ---
        bn2_add<<<(NCEL + 255) / 256, 256>>>(pre1_, pre2_, st_,
                                             bng + (size_t)i * 3 * CC, bnb + (size_t)i * 3 * CC,
                                             bng + (size_t)i * 3 * CC + CC, bnb + (size_t)i * 3 * CC + CC,
                                             outb_);
        gemm(outb_, nullptr, fw1 + (size_t)i * CC * 2 * CC, fb1 + (size_t)i * 2 * CC,
             nullptr, t2_, NN, 2 * CC, CC, 1);
        gemm(t2_, nullptr, fw2 + (size_t)i * 2 * CC * CC, fb2 + (size_t)i * CC,
             outb_, pre3_, NN, CC, 2 * CC, 0, st_ + 4 * CC, st_ + 5 * CC);
        bn_apply<<<(NCEL + 255) / 256, 256>>>(pre3_, st_ + 4 * CC, st_ + 5 * CC,
                                              bng + (size_t)i * 3 * CC + 2 * CC,
                                              bnb + (size_t)i * 3 * CC + 2 * CC, h_);
    }

    gemm(h_, nullptr, w_o, b_o, nullptr, y_, NN, CC, CC, 0);
    out_ln<<<NN / 4, 128>>>(y_, lng, lnb, out);
}

// round 5
// speedup vs baseline: 1.8235x; 1.0833x over previous
#include <cuda_runtime.h>

#define NN 4096
#define CC 96
#define EE 131072
#define NHEADS 4
#define DH 24
#define SPLITS 8
#define KPT (NN / SPLITS)

typedef unsigned long long u64;

// ---------------- scratch ----------------
__device__ float g_h[NN*CC];
__device__ float g_agg[NN*CC];
__device__ float g_t1[NN*CC];
__device__ float g_pre1[NN*CC];
__device__ float g_qkv[NN*3*CC];
__device__ float g_attno[NN*CC];
__device__ float g_pre2[NN*CC];
__device__ float g_outb[NN*CC];
__device__ float g_t2[NN*2*CC];
__device__ float g_pre3[NN*CC];
__device__ float g_y[NN*CC];
__device__ float g_stats[12*CC];          // per-layer slices: layer i -> + i*6*CC
__device__ int   g_src[EE];
__device__ int   g_dst[EE];
__device__ int   g_eat[EE];
__device__ int   g_flags[2];
__device__ int   g_cnt[NN];
__device__ int   g_off[NN+1];
__device__ int   g_cur[NN];
__device__ int   g_csrc[EE];
__device__ int   g_ceat[EE];
__device__ float g_po[SPLITS*NHEADS*NN*DH];
__device__ float g_pl[SPLITS*NHEADS*NN];

// ---------------- packed f32x2 helpers ----------------
__device__ __forceinline__ u64 pack2(float lo, float hi) {
    u64 r; asm("mov.b64 %0,{%1,%2};" : "=l"(r) : "f"(lo), "f"(hi)); return r;
}
__device__ __forceinline__ void unpack2(u64 v, float& lo, float& hi) {
    asm("mov.b64 {%0,%1},%2;" : "=f"(lo), "=f"(hi) : "l"(v));
}
__device__ __forceinline__ u64 fma2(u64 a, u64 b, u64 c) {
    u64 d; asm("fma.rn.f32x2 %0,%1,%2,%3;" : "=l"(d) : "l"(a), "l"(b), "l"(c)); return d;
}
__device__ __forceinline__ u64 mul2(u64 a, u64 b) {
    u64 d; asm("mul.rn.f32x2 %0,%1,%2;" : "=l"(d) : "l"(a), "l"(b)); return d;
}
#define LDS2(r0, r1, addr, IMM) \
    asm("ld.shared.v2.u64 {%0,%1},[%2+" IMM "];" : "=l"(r0), "=l"(r1) : "r"(addr))

// ---------------- prologue: dtype detect + zero cnt/stats (1 launch) ----------------
__global__ void prep(const unsigned* __restrict__ ei, const unsigned* __restrict__ ea) {
    int t = blockIdx.x * blockDim.x + threadIdx.x;
    if (blockIdx.x == 0 && threadIdx.x < 32) {
        int lane = threadIdx.x;
        unsigned v1 = (lane < 16) ? ei[2 * lane + 1] : 0u;
        unsigned v2 = (lane < 16) ? ea[2 * lane + 1] : 0u;
        unsigned b1 = __ballot_sync(0xffffffffu, v1 != 0u);
        unsigned b2 = __ballot_sync(0xffffffffu, v2 != 0u);
        if (lane == 0) { g_flags[0] = (b1 == 0u); g_flags[1] = (b2 == 0u); }
    }
    if (t < NN) g_cnt[t] = 0;
    if (t < 12 * CC) g_stats[t] = 0.f;
}

// decode + dst-degree count in one pass
__global__ void decode_idx(const void* __restrict__ ei, const void* __restrict__ ea) {
    int e = blockIdx.x * blockDim.x + threadIdx.x;
    if (e >= EE) return;
    int s, d, a;
    if (g_flags[0]) {
        const long long* p = (const long long*)ei;
        s = (int)p[e]; d = (int)p[EE + e];
    } else {
        const int* p = (const int*)ei;
        s = p[e]; d = p[EE + e];
    }
    if (g_flags[1]) {
        const long long* p = (const long long*)ea;
        a = (int)p[e];
    } else {
        const int* p = (const int*)ea;
        a = p[e];
    }
    g_src[e] = s; g_dst[e] = d; g_eat[e] = a;
    atomicAdd(&g_cnt[d], 1);
}

// ---------------- CSR build ----------------
__global__ __launch_bounds__(1024) void csr_scan() {
    __shared__ int sh[1024];
    int t = threadIdx.x;
    int c0 = g_cnt[4*t], c1 = g_cnt[4*t+1], c2 = g_cnt[4*t+2], c3 = g_cnt[4*t+3];
    int s = c0 + c1 + c2 + c3;
    sh[t] = s;
    __syncthreads();
    for (int o = 1; o < 1024; o <<= 1) {
        int v = (t >= o) ? sh[t - o] : 0;
        __syncthreads();
        sh[t] += v;
        __syncthreads();
    }
    int base = sh[t] - s;
    g_off[4*t] = base;            g_cur[4*t] = base;
    g_off[4*t+1] = base+c0;       g_cur[4*t+1] = base+c0;
    g_off[4*t+2] = base+c0+c1;    g_cur[4*t+2] = base+c0+c1;
    g_off[4*t+3] = base+c0+c1+c2; g_cur[4*t+3] = base+c0+c1+c2;
    if (t == 1023) g_off[NN] = sh[1023];
}
__global__ void csr_fill() {
    int e = blockIdx.x * blockDim.x + threadIdx.x;
    if (e >= EE) return;
    int pos = atomicAdd(&g_cur[g_dst[e]], 1);
    g_csrc[pos] = g_src[e];
    g_ceat[pos] = g_eat[e];
}

// ---------------- GINE aggregate: warp per node, no atomics ----------------
__global__ __launch_bounds__(256) void gine_agg(const float* __restrict__ h,
                                                const float* __restrict__ emb,
                                                float* __restrict__ agg) {
    int warp = (blockIdx.x * 256 + threadIdx.x) >> 5;
    int lane = threadIdx.x & 31;
    if (warp >= NN) return;
    int beg = g_off[warp], end = g_off[warp + 1];
    float a0 = 0.f, a1 = 0.f, a2 = 0.f;
    for (int i = beg; i < end; i++) {
        int src = g_csrc[i], et = g_ceat[i];
        const float* hp = h + (size_t)src * CC;
        const float* ep = emb + (size_t)et * CC;
        a0 += fmaxf(hp[lane]      + ep[lane],      0.f);
        a1 += fmaxf(hp[lane + 32] + ep[lane + 32], 0.f);
        a2 += fmaxf(hp[lane + 64] + ep[lane + 64], 0.f);
    }
    float* ap = agg + (size_t)warp * CC;
    ap[lane] = a0; ap[lane + 32] = a1; ap[lane + 64] = a2;
}

// ---------------- SGEMM (f32x2 inner) with optional fused BN-stats ----------------
__global__ __launch_bounds__(256) void sgemm(
    const float* __restrict__ A, const float* __restrict__ A2,
    const float* __restrict__ W, const float* __restrict__ bias,
    const float* __restrict__ res, float* __restrict__ C,
    int M, int N, int K, int relu,
    float* __restrict__ st_s, float* __restrict__ st_s2)
{
    __shared__ __align__(16) float As[16][64];
    __shared__ __align__(16) float Bs[16][64];
    const int tid  = threadIdx.x;
    const int row0 = blockIdx.y * 64;
    const int col0 = blockIdx.x * 64;
    const int ty = tid >> 4, tx = tid & 15;

    const int ar = tid >> 2, ak = (tid & 3) * 4;
    const int bk = tid >> 4, bc = (tid & 15) * 4;

    u64 acc2[4][2];
    #pragma unroll
    for (int i = 0; i < 4; i++) { acc2[i][0] = 0ull; acc2[i][1] = 0ull; }

    for (int k0 = 0; k0 < K; k0 += 16) {
        float4 a = *(const float4*)(A + (size_t)(row0 + ar) * K + k0 + ak);
        if (A2) {
            float4 a2 = *(const float4*)(A2 + (size_t)(row0 + ar) * K + k0 + ak);
            a.x += a2.x; a.y += a2.y; a.z += a2.z; a.w += a2.w;
        }
        As[ak + 0][ar] = a.x; As[ak + 1][ar] = a.y;
        As[ak + 2][ar] = a.z; As[ak + 3][ar] = a.w;

        float4 bv = make_float4(0.f, 0.f, 0.f, 0.f);
        if (col0 + bc < N)
            bv = *(const float4*)(W + (size_t)(k0 + bk) * N + col0 + bc);
        *(float4*)&Bs[bk][bc] = bv;

        __syncthreads();
        #pragma unroll
        for (int kk = 0; kk < 16; kk++) {
            float4 ra = *(const float4*)&As[kk][ty * 4];
            const u64* bp = (const u64*)&Bs[kk][tx * 4];
            u64 rb0 = bp[0], rb1 = bp[1];
            u64 a0 = pack2(ra.x, ra.x), a1 = pack2(ra.y, ra.y);
            u64 a2 = pack2(ra.z, ra.z), a3 = pack2(ra.w, ra.w);
            acc2[0][0] = fma2(a0, rb0, acc2[0][0]); acc2[0][1] = fma2(a0, rb1, acc2[0][1]);
            acc2[1][0] = fma2(a1, rb0, acc2[1][0]); acc2[1][1] = fma2(a1, rb1, acc2[1][1]);
            acc2[2][0] = fma2(a2, rb0, acc2[2][0]); acc2[2][1] = fma2(a2, rb1, acc2[2][1]);
            acc2[3][0] = fma2(a3, rb0, acc2[3][0]); acc2[3][1] = fma2(a3, rb1, acc2[3][1]);
        }
        __syncthreads();
    }

    float acc[4][4];
    #pragma unroll
    for (int i = 0; i < 4; i++) {
        unpack2(acc2[i][0], acc[i][0], acc[i][1]);
        unpack2(acc2[i][1], acc[i][2], acc[i][3]);
    }

    float cs[4] = {0.f, 0.f, 0.f, 0.f};
    float cq[4] = {0.f, 0.f, 0.f, 0.f};
    #pragma unroll
    for (int i = 0; i < 4; i++) {
        int r = row0 + ty * 4 + i;
        #pragma unroll
        for (int j = 0; j < 4; j++) {
            int c = col0 + tx * 4 + j;
            if (c < N) {
                float v = acc[i][j] + bias[c];
                if (res) v += res[(size_t)r * N + c];
                if (relu) v = fmaxf(v, 0.f);
                C[(size_t)r * N + c] = v;
                cs[j] += v; cq[j] += v * v;
            }
        }
    }

    if (st_s) {
        __syncthreads();
        #pragma unroll
        for (int j = 0; j < 4; j++) { As[ty][tx * 4 + j] = cs[j]; Bs[ty][tx * 4 + j] = cq[j]; }
        __syncthreads();
        if (tid < 64) {
            int c = col0 + tid;
            if (c < N) {
                float a = 0.f, b = 0.f;
                #pragma unroll
                for (int t = 0; t < 16; t++) { a += As[t][tid]; b += Bs[t][tid]; }
                atomicAdd(&st_s[c], a);
                atomicAdd(&st_s2[c], b);
            }
        }
    }
}

// ---------------- split-K flash attention, max-free softmax, 2 q/thread ----------------
__global__ __launch_bounds__(128) void flash_split(const float* __restrict__ qkv,
                                                   float* __restrict__ po,
                                                   float* __restrict__ pl) {
    const int h  = blockIdx.y;
    const int q0 = blockIdx.x * 256;
    const int sp = blockIdx.z;
    const int tid = threadIdx.x;
    __shared__ __align__(16) float Ks[128 * DH];
    __shared__ __align__(16) float Vs[128 * DH];
    const float scale = 0.20412414523193154f;  // 1/sqrt(24)

    u64 qa[12], qb[12];
    {
        const u64 sc2 = pack2(scale, scale);
        const float* qpa = qkv + (size_t)(q0 + tid) * (3 * CC) + h * DH;
        const float* qpb = qkv + (size_t)(q0 + 128 + tid) * (3 * CC) + h * DH;
        #pragma unroll
        for (int i = 0; i < 12; i++) {
            qa[i] = mul2(((const u64*)qpa)[i], sc2);
            qb[i] = mul2(((const u64*)qpb)[i], sc2);
        }
    }
    float la = 0.f, lb = 0.f;
    u64 oa[12], ob[12];
    #pragma unroll
    for (int i = 0; i < 12; i++) { oa[i] = 0ull; ob[i] = 0ull; }

    const unsigned ksb = (unsigned)__cvta_generic_to_shared(Ks);
    const unsigned vsb = (unsigned)__cvta_generic_to_shared(Vs);

    for (int kt = sp * KPT; kt < sp * KPT + KPT; kt += 128) {
        __syncthreads();
        {
            const float* kp = qkv + (size_t)(kt + tid) * (3 * CC) + CC + h * DH;
            #pragma unroll
            for (int d = 0; d < DH; d += 4) {
                *(float4*)&Ks[tid * DH + d] = *(const float4*)(kp + d);
                *(float4*)&Vs[tid * DH + d] = *(const float4*)(kp + CC + d);
            }
        }
        __syncthreads();

        #pragma unroll 1
        for (int j0 = 0; j0 < 128; j0 += 8) {
            float sa[8], sb[8];
            #pragma unroll
            for (int jj = 0; jj < 8; jj++) {
                u64 aca = 0ull, acb = 0ull;
                unsigned a = ksb + (j0 + jj) * (DH * 4);
                u64 k0, k1;
#define QKS(IMM, i0, i1) \
                LDS2(k0, k1, a, IMM); \
                aca = fma2(qa[i0], k0, aca); acb = fma2(qb[i0], k0, acb); \
                aca = fma2(qa[i1], k1, aca); acb = fma2(qb[i1], k1, acb);
                QKS("0", 0, 1)  QKS("16", 2, 3)  QKS("32", 4, 5)
                QKS("48", 6, 7) QKS("64", 8, 9)  QKS("80", 10, 11)
#undef QKS
                float lo, hi;
                unpack2(aca, lo, hi); sa[jj] = lo + hi;
                unpack2(acb, lo, hi); sb[jj] = lo + hi;
            }
            float pa[8], pb[8], psa = 0.f, psb = 0.f;
            #pragma unroll
            for (int jj = 0; jj < 8; jj++) {
                pa[jj] = __expf(sa[jj]); psa += pa[jj];
                pb[jj] = __expf(sb[jj]); psb += pb[jj];
            }
            la += psa; lb += psb;
            #pragma unroll
            for (int jj = 0; jj < 8; jj++) {
                u64 pa2 = pack2(pa[jj], pa[jj]);
                u64 pb2 = pack2(pb[jj], pb[jj]);
                unsigned a = vsb + (j0 + jj) * (DH * 4);
                u64 v0, v1;
#define AVS(IMM, i0, i1) \
                LDS2(v0, v1, a, IMM); \
                oa[i0] = fma2(pa2, v0, oa[i0]); ob[i0] = fma2(pb2, v0, ob[i0]); \
                oa[i1] = fma2(pa2, v1, oa[i1]); ob[i1] = fma2(pb2, v1, ob[i1]);
                AVS("0", 0, 1)  AVS("16", 2, 3)  AVS("32", 4, 5)
                AVS("48", 6, 7) AVS("64", 8, 9)  AVS("80", 10, 11)
#undef AVS
            }
        }
    }
    {
        const int idx = (sp * NHEADS + h) * NN + q0 + tid;
        pl[idx] = la;
        u64* op = (u64*)(po + (size_t)idx * DH);
        #pragma unroll
        for (int i = 0; i < 12; i++) op[i] = oa[i];
    }
    {
        const int idx = (sp * NHEADS + h) * NN + q0 + 128 + tid;
        pl[idx] = lb;
        u64* op = (u64*)(po + (size_t)idx * DH);
        #pragma unroll
        for (int i = 0; i < 12; i++) op[i] = ob[i];
    }
}

// merge splits (plain sums — max-free)
__global__ void flash_combine(const float* __restrict__ po, const float* __restrict__ pl,
                              float* __restrict__ outp) {
    int t = blockIdx.x * blockDim.x + threadIdx.x;
    if (t >= NN * NHEADS) return;
    int q = t & (NN - 1);
    int h = t >> 12;
    float L = 0.f;
    #pragma unroll
    for (int s = 0; s < SPLITS; s++) L += pl[(s * NHEADS + h) * NN + q];
    float inv = 1.f / L;
    float* op = outp + (size_t)q * CC + h * DH;
    #pragma unroll
    for (int d = 0; d < DH; d += 4) {
        float4 acc = make_float4(0.f, 0.f, 0.f, 0.f);
        #pragma unroll
        for (int s = 0; s < SPLITS; s++) {
            const float4 v = *(const float4*)(po + ((size_t)(s * NHEADS + h) * NN + q) * DH + d);
            acc.x += v.x; acc.y += v.y; acc.z += v.z; acc.w += v.w;
        }
        acc.x *= inv; acc.y *= inv; acc.z *= inv; acc.w *= inv;
        *(float4*)(op + d) = acc;
    }
}

// ---------------- BN elementwise ----------------
__global__ void bn2_add(const float* __restrict__ p1, const float* __restrict__ p2,
                        const float* __restrict__ st,
                        const float* __restrict__ g1, const float* __restrict__ b1,
                        const float* __restrict__ g2, const float* __restrict__ b2,
                        float* __restrict__ out) {
    int i = blockIdx.x * blockDim.x + threadIdx.x;
    if (i >= NN * CC) return;
    int c = i % CC;
    const float invn = 1.f / NN;
    float m1 = st[c] * invn;
    float v1 = st[CC + c] * invn - m1 * m1;
    float m2 = st[2 * CC + c] * invn;
    float v2 = st[3 * CC + c] * invn - m2 * m2;
    float o = (p1[i] - m1) * rsqrtf(v1 + 1e-5f) * g1[c] + b1[c]
            + (p2[i] - m2) * rsqrtf(v2 + 1e-5f) * g2[c] + b2[c];
    out[i] = o;
}

__global__ void bn_apply(const float* __restrict__ p, const float* __restrict__ s,
                         const float* __restrict__ s2, const float* __restrict__ g,
                         const float* __restrict__ b, float* __restrict__ o) {
    int i = blockIdx.x * blockDim.x + threadIdx.x;
    if (i >= NN * CC) return;
    int c = i % CC;
    const float invn = 1.f / NN;
    float m = s[c] * invn;
    float v = s2[c] * invn - m * m;
    o[i] = (p[i] - m) * rsqrtf(v + 1e-5f) * g[c] + b[c];
}

// ---------------- final per-row LayerNorm ----------------
__global__ void out_ln(const float* __restrict__ y, const float* __restrict__ g,
                       const float* __restrict__ b, float* __restrict__ out) {
    int lane = threadIdx.x & 31;
    int warp = threadIdx.x >> 5;
    int row  = blockIdx.x * 4 + warp;
    const float* yr = y + (size_t)row * CC;
    float v0 = yr[lane], v1 = yr[lane + 32], v2 = yr[lane + 64];
    float s = v0 + v1 + v2;
    #pragma unroll
    for (int o = 16; o; o >>= 1) s += __shfl_xor_sync(0xffffffffu, s, o);
    float mean = s * (1.f / 96.f);
    float d0 = v0 - mean, d1 = v1 - mean, d2 = v2 - mean;
    float qv = d0 * d0 + d1 * d1 + d2 * d2;
    #pragma unroll
    for (int o = 16; o; o >>= 1) qv += __shfl_xor_sync(0xffffffffu, qv, o);
    float inv = rsqrtf(qv * (1.f / 96.f) + 1e-5f);
    float* orow = out + (size_t)row * CC;
    orow[lane]      = d0 * inv * g[lane]      + b[lane];
    orow[lane + 32] = d1 * inv * g[lane + 32] + b[lane + 32];
    orow[lane + 64] = d2 * inv * g[lane + 64] + b[lane + 64];
}

// ---------------- launch ----------------
extern "C" void kernel_launch(void* const* d_in, const int* in_sizes, int n_in,
                              void* d_out, int out_size) {
    const float*     x    = (const float*)d_in[0];
    const void*      ei   = d_in[1];
    const void*      ea   = d_in[2];
    const float*     w_in = (const float*)d_in[3];
    const float*     b_in = (const float*)d_in[4];
    const float*     emb  = (const float*)d_in[5];
    const float*     gw1  = (const float*)d_in[6];
    const float*     gb1  = (const float*)d_in[7];
    const float*     gw2  = (const float*)d_in[8];
    const float*     gb2  = (const float*)d_in[9];
    const float*     wqkv = (const float*)d_in[10];
    const float*     bqkv = (const float*)d_in[11];
    const float*     wo   = (const float*)d_in[12];
    const float*     bo   = (const float*)d_in[13];
    const float*     bng  = (const float*)d_in[14];
    const float*     bnb  = (const float*)d_in[15];
    const float*     fw1  = (const float*)d_in[16];
    const float*     fb1  = (const float*)d_in[17];
    const float*     fw2  = (const float*)d_in[18];
    const float*     fb2  = (const float*)d_in[19];
    const float*     w_o  = (const float*)d_in[20];
    const float*     b_o  = (const float*)d_in[21];
    const float*     lng  = (const float*)d_in[22];
    const float*     lnb  = (const float*)d_in[23];
    float* out = (float*)d_out;

    float *h_, *agg_, *t1_, *pre1_, *qkv_, *attno_, *pre2_, *outb_, *t2_, *pre3_, *y_, *stA_;
    float *po_, *pl_;
    cudaGetSymbolAddress((void**)&h_,    g_h);
    cudaGetSymbolAddress((void**)&agg_,  g_agg);
    cudaGetSymbolAddress((void**)&t1_,   g_t1);
    cudaGetSymbolAddress((void**)&pre1_, g_pre1);
    cudaGetSymbolAddress((void**)&qkv_,  g_qkv);
    cudaGetSymbolAddress((void**)&attno_,g_attno);
    cudaGetSymbolAddress((void**)&pre2_, g_pre2);
    cudaGetSymbolAddress((void**)&outb_, g_outb);
    cudaGetSymbolAddress((void**)&t2_,   g_t2);
    cudaGetSymbolAddress((void**)&pre3_, g_pre3);
    cudaGetSymbolAddress((void**)&y_,    g_y);
    cudaGetSymbolAddress((void**)&stA_,  g_stats);
    cudaGetSymbolAddress((void**)&po_,   g_po);
    cudaGetSymbolAddress((void**)&pl_,   g_pl);

    auto gemm = [&](const float* A, const float* A2, const float* W, const float* bias,
                    const float* res, float* Cp, int M, int Nc, int K, int relu,
                    float* ss = nullptr, float* ss2 = nullptr) {
        dim3 grid((Nc + 63) / 64, M / 64);
        sgemm<<<grid, 256>>>(A, A2, W, bias, res, Cp, M, Nc, K, relu, ss, ss2);
    };

    const int NCEL = NN * CC;

    // 1: prologue (detect + zero cnt/stats)
    prep<<<16, 256>>>((const unsigned*)ei, (const unsigned*)ea);
    // 2: input projection
    gemm(x, nullptr, w_in, b_in, nullptr, h_, NN, CC, 64, 0);

    for (int i = 0; i < 2; i++) {
        float* st_ = stA_ + (size_t)i * 6 * CC;

        // --- attention branch first (launch #4 overall = flash_split, for ncu) ---
        gemm(h_, nullptr, wqkv + (size_t)i * CC * 3 * CC, bqkv + (size_t)i * 3 * CC,
             nullptr, qkv_, NN, 3 * CC, CC, 0);
        flash_split<<<dim3(NN / 256, NHEADS, SPLITS), 128>>>(qkv_, po_, pl_);
        flash_combine<<<(NN * NHEADS + 255) / 256, 256>>>(po_, pl_, attno_);
        gemm(attno_, nullptr, wo + (size_t)i * CC * CC, bo + (size_t)i * CC,
             h_, pre2_, NN, CC, CC, 0, st_ + 2 * CC, st_ + 3 * CC);

        if (i == 0) {
            // CSR build (once; needed before first gine_agg)
            decode_idx<<<(EE + 255) / 256, 256>>>(ei, ea);
            csr_scan<<<1, 1024>>>();
            csr_fill<<<(EE + 255) / 256, 256>>>();
        }

        // --- GINE branch ---
        gine_agg<<<NN / 8, 256>>>(h_, emb, agg_);
        gemm(agg_, h_, gw1, gb1, nullptr, t1_, NN, CC, CC, 1);
        gemm(t1_, nullptr, gw2, gb2, h_, pre1_, NN, CC, CC, 0, st_ + 0, st_ + CC);

        // --- merge + FFN ---
        bn2_add<<<(NCEL + 255) / 256, 256>>>(pre1_, pre2_, st_,
                                             bng + (size_t)i * 3 * CC, bnb + (size_t)i * 3 * CC,
                                             bng + (size_t)i * 3 * CC + CC, bnb + (size_t)i * 3 * CC + CC,
                                             outb_);
        gemm(outb_, nullptr, fw1 + (size_t)i * CC * 2 * CC, fb1 + (size_t)i * 2 * CC,
             nullptr, t2_, NN, 2 * CC, CC, 1);
        gemm(t2_, nullptr, fw2 + (size_t)i * 2 * CC * CC, fb2 + (size_t)i * CC,
             outb_, pre3_, NN, CC, 2 * CC, 0, st_ + 4 * CC, st_ + 5 * CC);
        bn_apply<<<(NCEL + 255) / 256, 256>>>(pre3_, st_ + 4 * CC, st_ + 5 * CC,
                                              bng + (size_t)i * 3 * CC + 2 * CC,
                                              bnb + (size_t)i * 3 * CC + 2 * CC, h_);
    }

    gemm(h_, nullptr, w_o, b_o, nullptr, y_, NN, CC, CC, 0);
    out_ln<<<NN / 4, 128>>>(y_, lng, lnb, out);
}

// round 7
// speedup vs baseline: 3.0699x; 1.6835x over previous
#include <cuda_runtime.h>
#include <cuda_bf16.h>
#include <cstdint>

#define NN 4096
#define CC 96
#define EE 131072
#define NHEADS 4
#define DH 24
#define SPLITS 4

typedef unsigned long long u64;

// ---------------- scratch ----------------
__device__ float g_h[NN*CC];
__device__ float g_agg[NN*CC];
__device__ float g_t1[NN*CC];
__device__ float g_pre1[NN*CC];
__device__ float g_qkv[NN*3*CC];
__device__ float g_attno[NN*CC];
__device__ float g_pre2[NN*CC];
__device__ float g_outb[NN*CC];
__device__ float g_t2[NN*2*CC];
__device__ float g_pre3[NN*CC];
__device__ float g_y[NN*CC];
__device__ float g_stats[12*CC];
__device__ int   g_src[EE];
__device__ int   g_dst[EE];
__device__ int   g_eat[EE];
__device__ int   g_flags[2];
__device__ int   g_cnt[NN];
__device__ int   g_off[NN+1];
__device__ int   g_cur[NN];
__device__ int   g_csrc[EE];
__device__ int   g_ceat[EE];
__device__ float g_po[SPLITS*NHEADS*NN*DH];
__device__ float g_pl[SPLITS*NHEADS*NN];

// ---------------- packed f32x2 helpers (sgemm) ----------------
__device__ __forceinline__ u64 pack2(float lo, float hi) {
    u64 r; asm("mov.b64 %0,{%1,%2};" : "=l"(r) : "f"(lo), "f"(hi)); return r;
}
__device__ __forceinline__ void unpack2(u64 v, float& lo, float& hi) {
    asm("mov.b64 {%0,%1},%2;" : "=f"(lo), "=f"(hi) : "l"(v));
}
__device__ __forceinline__ u64 fma2(u64 a, u64 b, u64 c) {
    u64 d; asm("fma.rn.f32x2 %0,%1,%2,%3;" : "=l"(d) : "l"(a), "l"(b), "l"(c)); return d;
}

// ---------------- mma.sync helpers ----------------
__device__ __forceinline__ unsigned f2tf32(float f) {
    unsigned r; asm("cvt.rna.tf32.f32 %0, %1;" : "=r"(r) : "f"(f)); return r;
}
// pack (lo, hi) -> bf16x2 with lo in low half
__device__ __forceinline__ unsigned pkbf(float lo, float hi) {
    unsigned r; asm("cvt.rn.bf16x2.f32 %0, %1, %2;" : "=r"(r) : "f"(hi), "f"(lo)); return r;
}
__device__ __forceinline__ void mma_tf32(float* c, const unsigned* a, const unsigned* b) {
    asm volatile("mma.sync.aligned.m16n8k8.row.col.f32.tf32.tf32.f32 "
        "{%0,%1,%2,%3}, {%4,%5,%6,%7}, {%8,%9}, {%0,%1,%2,%3};"
        : "+f"(c[0]), "+f"(c[1]), "+f"(c[2]), "+f"(c[3])
        : "r"(a[0]), "r"(a[1]), "r"(a[2]), "r"(a[3]), "r"(b[0]), "r"(b[1]));
}
__device__ __forceinline__ void mma_bf16(float* c, const unsigned* a, const unsigned* b) {
    asm volatile("mma.sync.aligned.m16n8k16.row.col.f32.bf16.bf16.f32 "
        "{%0,%1,%2,%3}, {%4,%5,%6,%7}, {%8,%9}, {%0,%1,%2,%3};"
        : "+f"(c[0]), "+f"(c[1]), "+f"(c[2]), "+f"(c[3])
        : "r"(a[0]), "r"(a[1]), "r"(a[2]), "r"(a[3]), "r"(b[0]), "r"(b[1]));
}

// ---------------- prologue ----------------
__global__ void prep(const unsigned* __restrict__ ei, const unsigned* __restrict__ ea) {
    int t = blockIdx.x * blockDim.x + threadIdx.x;
    if (blockIdx.x == 0 && threadIdx.x < 32) {
        int lane = threadIdx.x;
        unsigned v1 = (lane < 16) ? ei[2 * lane + 1] : 0u;
        unsigned v2 = (lane < 16) ? ea[2 * lane + 1] : 0u;
        unsigned b1 = __ballot_sync(0xffffffffu, v1 != 0u);
        unsigned b2 = __ballot_sync(0xffffffffu, v2 != 0u);
        if (lane == 0) { g_flags[0] = (b1 == 0u); g_flags[1] = (b2 == 0u); }
    }
    if (t < NN) g_cnt[t] = 0;
    if (t < 12 * CC) g_stats[t] = 0.f;
}

__global__ void decode_idx(const void* __restrict__ ei, const void* __restrict__ ea) {
    int e = blockIdx.x * blockDim.x + threadIdx.x;
    if (e >= EE) return;
    int s, d, a;
    if (g_flags[0]) {
        const long long* p = (const long long*)ei;
        s = (int)p[e]; d = (int)p[EE + e];
    } else {
        const int* p = (const int*)ei;
        s = p[e]; d = p[EE + e];
    }
    if (g_flags[1]) {
        const long long* p = (const long long*)ea;
        a = (int)p[e];
    } else {
        const int* p = (const int*)ea;
        a = p[e];
    }
    g_src[e] = s; g_dst[e] = d; g_eat[e] = a;
    atomicAdd(&g_cnt[d], 1);
}

__global__ __launch_bounds__(1024) void csr_scan() {
    __shared__ int sh[1024];
    int t = threadIdx.x;
    int c0 = g_cnt[4*t], c1 = g_cnt[4*t+1], c2 = g_cnt[4*t+2], c3 = g_cnt[4*t+3];
    int s = c0 + c1 + c2 + c3;
    sh[t] = s;
    __syncthreads();
    for (int o = 1; o < 1024; o <<= 1) {
        int v = (t >= o) ? sh[t - o] : 0;
        __syncthreads();
        sh[t] += v;
        __syncthreads();
    }
    int base = sh[t] - s;
    g_off[4*t] = base;            g_cur[4*t] = base;
    g_off[4*t+1] = base+c0;       g_cur[4*t+1] = base+c0;
    g_off[4*t+2] = base+c0+c1;    g_cur[4*t+2] = base+c0+c1;
    g_off[4*t+3] = base+c0+c1+c2; g_cur[4*t+3] = base+c0+c1+c2;
    if (t == 1023) g_off[NN] = sh[1023];
}
__global__ void csr_fill() {
    int e = blockIdx.x * blockDim.x + threadIdx.x;
    if (e >= EE) return;
    int pos = atomicAdd(&g_cur[g_dst[e]], 1);
    g_csrc[pos] = g_src[e];
    g_ceat[pos] = g_eat[e];
}

// ---------------- GINE aggregate ----------------
__global__ __launch_bounds__(256) void gine_agg(const float* __restrict__ h,
                                                const float* __restrict__ emb,
                                                float* __restrict__ agg) {
    int warp = (blockIdx.x * 256 + threadIdx.x) >> 5;
    int lane = threadIdx.x & 31;
    if (warp >= NN) return;
    int beg = g_off[warp], end = g_off[warp + 1];
    float a0 = 0.f, a1 = 0.f, a2 = 0.f;
    for (int i = beg; i < end; i++) {
        int src = g_csrc[i], et = g_ceat[i];
        const float* hp = h + (size_t)src * CC;
        const float* ep = emb + (size_t)et * CC;
        a0 += fmaxf(hp[lane]      + ep[lane],      0.f);
        a1 += fmaxf(hp[lane + 32] + ep[lane + 32], 0.f);
        a2 += fmaxf(hp[lane + 64] + ep[lane + 64], 0.f);
    }
    float* ap = agg + (size_t)warp * CC;
    ap[lane] = a0; ap[lane + 32] = a1; ap[lane + 64] = a2;
}

// ---------------- SGEMM (f32x2) with optional fused BN-stats ----------------
__global__ __launch_bounds__(256) void sgemm(
    const float* __restrict__ A, const float* __restrict__ A2,
    const float* __restrict__ W, const float* __restrict__ bias,
    const float* __restrict__ res, float* __restrict__ C,
    int M, int N, int K, int relu,
    float* __restrict__ st_s, float* __restrict__ st_s2)
{
    __shared__ __align__(16) float As[16][64];
    __shared__ __align__(16) float Bs[16][64];
    const int tid  = threadIdx.x;
    const int row0 = blockIdx.y * 64;
    const int col0 = blockIdx.x * 64;
    const int ty = tid >> 4, tx = tid & 15;

    const int ar = tid >> 2, ak = (tid & 3) * 4;
    const int bk = tid >> 4, bc = (tid & 15) * 4;

    u64 acc2[4][2];
    #pragma unroll
    for (int i = 0; i < 4; i++) { acc2[i][0] = 0ull; acc2[i][1] = 0ull; }

    for (int k0 = 0; k0 < K; k0 += 16) {
        float4 a = *(const float4*)(A + (size_t)(row0 + ar) * K + k0 + ak);
        if (A2) {
            float4 a2 = *(const float4*)(A2 + (size_t)(row0 + ar) * K + k0 + ak);
            a.x += a2.x; a.y += a2.y; a.z += a2.z; a.w += a2.w;
        }
        As[ak + 0][ar] = a.x; As[ak + 1][ar] = a.y;
        As[ak + 2][ar] = a.z; As[ak + 3][ar] = a.w;

        float4 bv = make_float4(0.f, 0.f, 0.f, 0.f);
        if (col0 + bc < N)
            bv = *(const float4*)(W + (size_t)(k0 + bk) * N + col0 + bc);
        *(float4*)&Bs[bk][bc] = bv;

        __syncthreads();
        #pragma unroll
        for (int kk = 0; kk < 16; kk++) {
            float4 ra = *(const float4*)&As[kk][ty * 4];
            const u64* bp = (const u64*)&Bs[kk][tx * 4];
            u64 rb0 = bp[0], rb1 = bp[1];
            u64 a0 = pack2(ra.x, ra.x), a1 = pack2(ra.y, ra.y);
            u64 a2 = pack2(ra.z, ra.z), a3 = pack2(ra.w, ra.w);
            acc2[0][0] = fma2(a0, rb0, acc2[0][0]); acc2[0][1] = fma2(a0, rb1, acc2[0][1]);
            acc2[1][0] = fma2(a1, rb0, acc2[1][0]); acc2[1][1] = fma2(a1, rb1, acc2[1][1]);
            acc2[2][0] = fma2(a2, rb0, acc2[2][0]); acc2[2][1] = fma2(a2, rb1, acc2[2][1]);
            acc2[3][0] = fma2(a3, rb0, acc2[3][0]); acc2[3][1] = fma2(a3, rb1, acc2[3][1]);
        }
        __syncthreads();
    }

    float acc[4][4];
    #pragma unroll
    for (int i = 0; i < 4; i++) {
        unpack2(acc2[i][0], acc[i][0], acc[i][1]);
        unpack2(acc2[i][1], acc[i][2], acc[i][3]);
    }

    float cs[4] = {0.f, 0.f, 0.f, 0.f};
    float cq[4] = {0.f, 0.f, 0.f, 0.f};
    #pragma unroll
    for (int i = 0; i < 4; i++) {
        int r = row0 + ty * 4 + i;
        #pragma unroll
        for (int j = 0; j < 4; j++) {
            int c = col0 + tx * 4 + j;
            if (c < N) {
                float v = acc[i][j] + bias[c];
                if (res) v += res[(size_t)r * N + c];
                if (relu) v = fmaxf(v, 0.f);
                C[(size_t)r * N + c] = v;
                cs[j] += v; cq[j] += v * v;
            }
        }
    }

    if (st_s) {
        __syncthreads();
        #pragma unroll
        for (int j = 0; j < 4; j++) { As[ty][tx * 4 + j] = cs[j]; Bs[ty][tx * 4 + j] = cq[j]; }
        __syncthreads();
        if (tid < 64) {
            int c = col0 + tid;
            if (c < N) {
                float a = 0.f, b = 0.f;
                #pragma unroll
                for (int t = 0; t < 16; t++) { a += As[t][tid]; b += Bs[t][tid]; }
                atomicAdd(&st_s[c], a);
                atomicAdd(&st_s2[c], b);
            }
        }
    }
}

// ---------------- mma.sync flash attention (tf32 S, bf16 hi/lo PV) ----------------
// grid (NN/128, NHEADS, SPLITS), 128 threads (4 warps). Warp owns 32 queries.
// Max-free softmax (Q pre-scaled by log2e/sqrt(24), exp2 in regs).
#define QSCALE 0.2944858445807166f

__global__ __launch_bounds__(128) void flash_mma(const float* __restrict__ qkv,
                                                 float* __restrict__ po,
                                                 float* __restrict__ pl) {
    __shared__ unsigned KtU[24 * 72];          // K^T tf32 bits, stride 72 (conflict-free)
    __shared__ unsigned short Vh[24 * 72];     // V^T bf16 hi, stride 72
    __shared__ unsigned short Vl[24 * 72];     // V^T bf16 lo
    const int h   = blockIdx.y;
    const int q0  = blockIdx.x * 128;
    const int sp  = blockIdx.z;
    const int tid = threadIdx.x;
    const int w   = tid >> 5;
    const int lane = tid & 31;
    const int tg = lane >> 2, tq = lane & 3;   // group row, thread-in-group

    // Q A-frags (m16n8k8 tf32), loop-invariant: 2 m-tiles x 3 k-chunks
    unsigned QA[2][3][4];
    #pragma unroll
    for (int mi = 0; mi < 2; mi++) {
        const float* qp0 = qkv + (size_t)(q0 + 32 * w + 16 * mi + tg) * (3 * CC) + h * DH;
        const float* qp1 = qp0 + (size_t)8 * (3 * CC);
        #pragma unroll
        for (int kc = 0; kc < 3; kc++) {
            QA[mi][kc][0] = f2tf32(qp0[kc * 8 + tq] * QSCALE);
            QA[mi][kc][1] = f2tf32(qp1[kc * 8 + tq] * QSCALE);
            QA[mi][kc][2] = f2tf32(qp0[kc * 8 + tq + 4] * QSCALE);
            QA[mi][kc][3] = f2tf32(qp1[kc * 8 + tq + 4] * QSCALE);
        }
    }

    float OC[2][3][4];
    #pragma unroll
    for (int mi = 0; mi < 2; mi++)
        #pragma unroll
        for (int n = 0; n < 3; n++)
            #pragma unroll
            for (int r = 0; r < 4; r++) OC[mi][n][r] = 0.f;
    float lacc[2][2] = {{0.f, 0.f}, {0.f, 0.f}};

    for (int t = 0; t < (NN / SPLITS) / 64; t++) {
        const int kt = sp * (NN / SPLITS) + t * 64;
        __syncthreads();
        // stage K^T (tf32) and V^T (bf16 hi/lo): thread -> (key=tid/2, d-half)
        {
            int key = tid >> 1;
            int dh0 = (tid & 1) * 12;
            const float* kp = qkv + (size_t)(kt + key) * (3 * CC) + CC + h * DH + dh0;
            const float* vp = kp + CC;
            float4 kv0 = *(const float4*)(kp);
            float4 kv1 = *(const float4*)(kp + 4);
            float4 kv2 = *(const float4*)(kp + 8);
            float4 vv0 = *(const float4*)(vp);
            float4 vv1 = *(const float4*)(vp + 4);
            float4 vv2 = *(const float4*)(vp + 8);
            float kf[12] = {kv0.x, kv0.y, kv0.z, kv0.w, kv1.x, kv1.y, kv1.z, kv1.w,
                            kv2.x, kv2.y, kv2.z, kv2.w};
            float vf[12] = {vv0.x, vv0.y, vv0.z, vv0.w, vv1.x, vv1.y, vv1.z, vv1.w,
                            vv2.x, vv2.y, vv2.z, vv2.w};
            #pragma unroll
            for (int i = 0; i < 12; i++) {
                int d = dh0 + i;
                KtU[d * 72 + key] = f2tf32(kf[i]);
                __nv_bfloat16 bh = __float2bfloat16(vf[i]);
                float rem = vf[i] - __bfloat162float(bh);
                __nv_bfloat16 bl = __float2bfloat16(rem);
                Vh[d * 72 + key] = __bfloat16_as_ushort(bh);
                Vl[d * 72 + key] = __bfloat16_as_ushort(bl);
            }
        }
        __syncthreads();

        // S = Q @ K^T  (2 m-tiles x 8 n-tiles x 3 k-chunks)
        float SC[2][8][4];
        #pragma unroll
        for (int mi = 0; mi < 2; mi++)
            #pragma unroll
            for (int nt = 0; nt < 8; nt++)
                #pragma unroll
                for (int r = 0; r < 4; r++) SC[mi][nt][r] = 0.f;

        #pragma unroll
        for (int nt = 0; nt < 8; nt++) {
            unsigned bB[3][2];
            #pragma unroll
            for (int kc = 0; kc < 3; kc++) {
                bB[kc][0] = KtU[(kc * 8 + tq) * 72 + nt * 8 + tg];
                bB[kc][1] = KtU[(kc * 8 + tq + 4) * 72 + nt * 8 + tg];
            }
            #pragma unroll
            for (int kc = 0; kc < 3; kc++) {
                mma_tf32(SC[0][nt], QA[0][kc], bB[kc]);
                mma_tf32(SC[1][nt], QA[1][kc], bB[kc]);
            }
        }

        // P = exp2(S), rowsum into lacc
        #pragma unroll
        for (int mi = 0; mi < 2; mi++)
            #pragma unroll
            for (int nt = 0; nt < 8; nt++)
                #pragma unroll
                for (int r = 0; r < 4; r++) {
                    float e;
                    asm("ex2.approx.ftz.f32 %0, %1;" : "=f"(e) : "f"(SC[mi][nt][r]));
                    SC[mi][nt][r] = e;
                    lacc[mi][r >> 1] += e;
                }

        // P -> bf16 A-frags (m16n8k16): C-frag pairs pack directly
        unsigned PA[2][4][4];
        #pragma unroll
        for (int mi = 0; mi < 2; mi++)
            #pragma unroll
            for (int kc4 = 0; kc4 < 4; kc4++) {
                PA[mi][kc4][0] = pkbf(SC[mi][2 * kc4][0],     SC[mi][2 * kc4][1]);
                PA[mi][kc4][1] = pkbf(SC[mi][2 * kc4][2],     SC[mi][2 * kc4][3]);
                PA[mi][kc4][2] = pkbf(SC[mi][2 * kc4 + 1][0], SC[mi][2 * kc4 + 1][1]);
                PA[mi][kc4][3] = pkbf(SC[mi][2 * kc4 + 1][2], SC[mi][2 * kc4 + 1][3]);
            }

        // O += P @ V  (bf16, hi + lo)
        #pragma unroll
        for (int kc4 = 0; kc4 < 4; kc4++) {
            #pragma unroll
            for (int n = 0; n < 3; n++) {
                int drow = n * 8 + tg;
                int col = kc4 * 16 + 2 * tq;
                unsigned bh[2], bl[2];
                bh[0] = *(const unsigned*)&Vh[drow * 72 + col];
                bh[1] = *(const unsigned*)&Vh[drow * 72 + col + 8];
                bl[0] = *(const unsigned*)&Vl[drow * 72 + col];
                bl[1] = *(const unsigned*)&Vl[drow * 72 + col + 8];
                mma_bf16(OC[0][n], PA[0][kc4], bh);
                mma_bf16(OC[1][n], PA[1][kc4], bh);
                mma_bf16(OC[0][n], PA[0][kc4], bl);
                mma_bf16(OC[1][n], PA[1][kc4], bl);
            }
        }
    }

    // reduce l over the 4 threads of each row group
    #pragma unroll
    for (int mi = 0; mi < 2; mi++)
        #pragma unroll
        for (int hi = 0; hi < 2; hi++) {
            float v = lacc[mi][hi];
            v += __shfl_xor_sync(0xffffffffu, v, 1);
            v += __shfl_xor_sync(0xffffffffu, v, 2);
            lacc[mi][hi] = v;
        }

    // store partials
    const int base = (sp * NHEADS + h) * NN;
    #pragma unroll
    for (int mi = 0; mi < 2; mi++) {
        int r0 = q0 + 32 * w + 16 * mi + tg;
        int r1 = r0 + 8;
        if (tq == 0) {
            pl[base + r0] = lacc[mi][0];
            pl[base + r1] = lacc[mi][1];
        }
        #pragma unroll
        for (int n = 0; n < 3; n++) {
            float2 v0 = make_float2(OC[mi][n][0], OC[mi][n][1]);
            float2 v1 = make_float2(OC[mi][n][2], OC[mi][n][3]);
            *(float2*)(po + ((size_t)(base + r0)) * DH + n * 8 + 2 * tq) = v0;
            *(float2*)(po + ((size_t)(base + r1)) * DH + n * 8 + 2 * tq) = v1;
        }
    }
}

// merge splits (plain sums — max-free)
__global__ void flash_combine(const float* __restrict__ po, const float* __restrict__ pl,
                              float* __restrict__ outp) {
    int t = blockIdx.x * blockDim.x + threadIdx.x;
    if (t >= NN * NHEADS) return;
    int q = t & (NN - 1);
    int h = t >> 12;
    float L = 0.f;
    #pragma unroll
    for (int s = 0; s < SPLITS; s++) L += pl[(s * NHEADS + h) * NN + q];
    float inv = 1.f / L;
    float* op = outp + (size_t)q * CC + h * DH;
    #pragma unroll
    for (int d = 0; d < DH; d += 4) {
        float4 acc = make_float4(0.f, 0.f, 0.f, 0.f);
        #pragma unroll
        for (int s = 0; s < SPLITS; s++) {
            const float4 v = *(const float4*)(po + ((size_t)(s * NHEADS + h) * NN + q) * DH + d);
            acc.x += v.x; acc.y += v.y; acc.z += v.z; acc.w += v.w;
        }
        acc.x *= inv; acc.y *= inv; acc.z *= inv; acc.w *= inv;
        *(float4*)(op + d) = acc;
    }
}

// ---------------- BN elementwise ----------------
__global__ void bn2_add(const float* __restrict__ p1, const float* __restrict__ p2,
                        const float* __restrict__ st,
                        const float* __restrict__ g1, const float* __restrict__ b1,
                        const float* __restrict__ g2, const float* __restrict__ b2,
                        float* __restrict__ out) {
    int i = blockIdx.x * blockDim.x + threadIdx.x;
    if (i >= NN * CC) return;
    int c = i % CC;
    const float invn = 1.f / NN;
    float m1 = st[c] * invn;
    float v1 = st[CC + c] * invn - m1 * m1;
    float m2 = st[2 * CC + c] * invn;
    float v2 = st[3 * CC + c] * invn - m2 * m2;
    float o = (p1[i] - m1) * rsqrtf(v1 + 1e-5f) * g1[c] + b1[c]
            + (p2[i] - m2) * rsqrtf(v2 + 1e-5f) * g2[c] + b2[c];
    out[i] = o;
}

__global__ void bn_apply(const float* __restrict__ p, const float* __restrict__ s,
                         const float* __restrict__ s2, const float* __restrict__ g,
                         const float* __restrict__ b, float* __restrict__ o) {
    int i = blockIdx.x * blockDim.x + threadIdx.x;
    if (i >= NN * CC) return;
    int c = i % CC;
    const float invn = 1.f / NN;
    float m = s[c] * invn;
    float v = s2[c] * invn - m * m;
    o[i] = (p[i] - m) * rsqrtf(v + 1e-5f) * g[c] + b[c];
}

// ---------------- final per-row LayerNorm ----------------
__global__ void out_ln(const float* __restrict__ y, const float* __restrict__ g,
                       const float* __restrict__ b, float* __restrict__ out) {
    int lane = threadIdx.x & 31;
    int warp = threadIdx.x >> 5;
    int row  = blockIdx.x * 4 + warp;
    const float* yr = y + (size_t)row * CC;
    float v0 = yr[lane], v1 = yr[lane + 32], v2 = yr[lane + 64];
    float s = v0 + v1 + v2;
    #pragma unroll
    for (int o = 16; o; o >>= 1) s += __shfl_xor_sync(0xffffffffu, s, o);
    float mean = s * (1.f / 96.f);
    float d0 = v0 - mean, d1 = v1 - mean, d2 = v2 - mean;
    float qv = d0 * d0 + d1 * d1 + d2 * d2;
    #pragma unroll
    for (int o = 16; o; o >>= 1) qv += __shfl_xor_sync(0xffffffffu, qv, o);
    float inv = rsqrtf(qv * (1.f / 96.f) + 1e-5f);
    float* orow = out + (size_t)row * CC;
    orow[lane]      = d0 * inv * g[lane]      + b[lane];
    orow[lane + 32] = d1 * inv * g[lane + 32] + b[lane + 32];
    orow[lane + 64] = d2 * inv * g[lane + 64] + b[lane + 64];
}

// ---------------- launch ----------------
extern "C" void kernel_launch(void* const* d_in, const int* in_sizes, int n_in,
                              void* d_out, int out_size) {
    const float*     x    = (const float*)d_in[0];
    const void*      ei   = d_in[1];
    const void*      ea   = d_in[2];
    const float*     w_in = (const float*)d_in[3];
    const float*     b_in = (const float*)d_in[4];
    const float*     emb  = (const float*)d_in[5];
    const float*     gw1  = (const float*)d_in[6];
    const float*     gb1  = (const float*)d_in[7];
    const float*     gw2  = (const float*)d_in[8];
    const float*     gb2  = (const float*)d_in[9];
    const float*     wqkv = (const float*)d_in[10];
    const float*     bqkv = (const float*)d_in[11];
    const float*     wo   = (const float*)d_in[12];
    const float*     bo   = (const float*)d_in[13];
    const float*     bng  = (const float*)d_in[14];
    const float*     bnb  = (const float*)d_in[15];
    const float*     fw1  = (const float*)d_in[16];
    const float*     fb1  = (const float*)d_in[17];
    const float*     fw2  = (const float*)d_in[18];
    const float*     fb2  = (const float*)d_in[19];
    const float*     w_o  = (const float*)d_in[20];
    const float*     b_o  = (const float*)d_in[21];
    const float*     lng  = (const float*)d_in[22];
    const float*     lnb  = (const float*)d_in[23];
    float* out = (float*)d_out;

    float *h_, *agg_, *t1_, *pre1_, *qkv_, *attno_, *pre2_, *outb_, *t2_, *pre3_, *y_, *stA_;
    float *po_, *pl_;
    cudaGetSymbolAddress((void**)&h_,    g_h);
    cudaGetSymbolAddress((void**)&agg_,  g_agg);
    cudaGetSymbolAddress((void**)&t1_,   g_t1);
    cudaGetSymbolAddress((void**)&pre1_, g_pre1);
    cudaGetSymbolAddress((void**)&qkv_,  g_qkv);
    cudaGetSymbolAddress((void**)&attno_,g_attno);
    cudaGetSymbolAddress((void**)&pre2_, g_pre2);
    cudaGetSymbolAddress((void**)&outb_, g_outb);
    cudaGetSymbolAddress((void**)&t2_,   g_t2);
    cudaGetSymbolAddress((void**)&pre3_, g_pre3);
    cudaGetSymbolAddress((void**)&y_,    g_y);
    cudaGetSymbolAddress((void**)&stA_,  g_stats);
    cudaGetSymbolAddress((void**)&po_,   g_po);
    cudaGetSymbolAddress((void**)&pl_,   g_pl);

    auto gemm = [&](const float* A, const float* A2, const float* W, const float* bias,
                    const float* res, float* Cp, int M, int Nc, int K, int relu,
                    float* ss = nullptr, float* ss2 = nullptr) {
        dim3 grid((Nc + 63) / 64, M / 64);
        sgemm<<<grid, 256>>>(A, A2, W, bias, res, Cp, M, Nc, K, relu, ss, ss2);
    };

    const int NCEL = NN * CC;

    // 1: prologue
    prep<<<16, 256>>>((const unsigned*)ei, (const unsigned*)ea);
    // 2: input projection
    gemm(x, nullptr, w_in, b_in, nullptr, h_, NN, CC, 64, 0);

    for (int i = 0; i < 2; i++) {
        float* st_ = stA_ + (size_t)i * 6 * CC;

        // --- attention branch (launch #4 overall = flash_mma, for ncu) ---
        gemm(h_, nullptr, wqkv + (size_t)i * CC * 3 * CC, bqkv + (size_t)i * 3 * CC,
             nullptr, qkv_, NN, 3 * CC, CC, 0);
        flash_mma<<<dim3(NN / 128, NHEADS, SPLITS), 128>>>(qkv_, po_, pl_);
        flash_combine<<<(NN * NHEADS + 255) / 256, 256>>>(po_, pl_, attno_);
        gemm(attno_, nullptr, wo + (size_t)i * CC * CC, bo + (size_t)i * CC,
             h_, pre2_, NN, CC, CC, 0, st_ + 2 * CC, st_ + 3 * CC);

        if (i == 0) {
            decode_idx<<<(EE + 255) / 256, 256>>>(ei, ea);
            csr_scan<<<1, 1024>>>();
            csr_fill<<<(EE + 255) / 256, 256>>>();
        }

        // --- GINE branch ---
        gine_agg<<<NN / 8, 256>>>(h_, emb, agg_);
        gemm(agg_, h_, gw1, gb1, nullptr, t1_, NN, CC, CC, 1);
        gemm(t1_, nullptr, gw2, gb2, h_, pre1_, NN, CC, CC, 0, st_ + 0, st_ + CC);

        // --- merge + FFN ---
        bn2_add<<<(NCEL + 255) / 256, 256>>>(pre1_, pre2_, st_,
                                             bng + (size_t)i * 3 * CC, bnb + (size_t)i * 3 * CC,
                                             bng + (size_t)i * 3 * CC + CC, bnb + (size_t)i * 3 * CC + CC,
                                             outb_);
        gemm(outb_, nullptr, fw1 + (size_t)i * CC * 2 * CC, fb1 + (size_t)i * 2 * CC,
             nullptr, t2_, NN, 2 * CC, CC, 1);
        gemm(t2_, nullptr, fw2 + (size_t)i * 2 * CC * CC, fb2 + (size_t)i * CC,
             outb_, pre3_, NN, CC, 2 * CC, 0, st_ + 4 * CC, st_ + 5 * CC);
        bn_apply<<<(NCEL + 255) / 256, 256>>>(pre3_, st_ + 4 * CC, st_ + 5 * CC,
                                              bng + (size_t)i * 3 * CC + 2 * CC,
                                              bnb + (size_t)i * 3 * CC + 2 * CC, h_);
    }

    gemm(h_, nullptr, w_o, b_o, nullptr, y_, NN, CC, CC, 0);
    out_ln<<<NN / 4, 128>>>(y_, lng, lnb, out);
}

// round 8
// speedup vs baseline: 3.5504x; 1.1565x over previous
#include <cuda_runtime.h>
#include <cuda_bf16.h>
#include <cstdint>

#define NN 4096
#define CC 96
#define EE 131072
#define NHEADS 4
#define DH 24
#define SPLITS 8

typedef unsigned long long u64;

// ---------------- scratch ----------------
__device__ float g_h[NN*CC];
__device__ float g_agg[NN*CC];
__device__ float g_t1[NN*CC];
__device__ float g_pre1[NN*CC];
__device__ float g_qkv[NN*3*CC];
__device__ float g_attno[NN*CC];
__device__ float g_pre2[NN*CC];
__device__ float g_outb[NN*CC];
__device__ float g_t2[NN*2*CC];
__device__ float g_pre3[NN*CC];
__device__ float g_y[NN*CC];
__device__ float g_stats[12*CC];
__device__ int   g_src[EE];
__device__ int   g_dst[EE];
__device__ int   g_eat[EE];
__device__ int   g_flags[2];
__device__ int   g_cnt[NN];
__device__ int   g_off[NN+1];
__device__ int   g_cur[NN];
__device__ int   g_csrc[EE];
__device__ int   g_ceat[EE];
__device__ float g_po[SPLITS*NHEADS*NN*DH];
__device__ float g_pl[SPLITS*NHEADS*NN];

// ---------------- mma.sync helpers ----------------
__device__ __forceinline__ unsigned f2tf32(float f) {
    unsigned r; asm("cvt.rna.tf32.f32 %0, %1;" : "=r"(r) : "f"(f)); return r;
}
__device__ __forceinline__ unsigned pkbf(float lo, float hi) {
    unsigned r; asm("cvt.rn.bf16x2.f32 %0, %1, %2;" : "=r"(r) : "f"(hi), "f"(lo)); return r;
}
__device__ __forceinline__ void mma_tf32(float* c, const unsigned* a, const unsigned* b) {
    asm volatile("mma.sync.aligned.m16n8k8.row.col.f32.tf32.tf32.f32 "
        "{%0,%1,%2,%3}, {%4,%5,%6,%7}, {%8,%9}, {%0,%1,%2,%3};"
        : "+f"(c[0]), "+f"(c[1]), "+f"(c[2]), "+f"(c[3])
        : "r"(a[0]), "r"(a[1]), "r"(a[2]), "r"(a[3]), "r"(b[0]), "r"(b[1]));
}
__device__ __forceinline__ void mma_bf16(float* c, const unsigned* a, const unsigned* b) {
    asm volatile("mma.sync.aligned.m16n8k16.row.col.f32.bf16.bf16.f32 "
        "{%0,%1,%2,%3}, {%4,%5,%6,%7}, {%8,%9}, {%0,%1,%2,%3};"
        : "+f"(c[0]), "+f"(c[1]), "+f"(c[2]), "+f"(c[3])
        : "r"(a[0]), "r"(a[1]), "r"(a[2]), "r"(a[3]), "r"(b[0]), "r"(b[1]));
}

// ---------------- prologue ----------------
__global__ void prep(const unsigned* __restrict__ ei, const unsigned* __restrict__ ea) {
    int t = blockIdx.x * blockDim.x + threadIdx.x;
    if (blockIdx.x == 0 && threadIdx.x < 32) {
        int lane = threadIdx.x;
        unsigned v1 = (lane < 16) ? ei[2 * lane + 1] : 0u;
        unsigned v2 = (lane < 16) ? ea[2 * lane + 1] : 0u;
        unsigned b1 = __ballot_sync(0xffffffffu, v1 != 0u);
        unsigned b2 = __ballot_sync(0xffffffffu, v2 != 0u);
        if (lane == 0) { g_flags[0] = (b1 == 0u); g_flags[1] = (b2 == 0u); }
    }
    if (t < NN) g_cnt[t] = 0;
    if (t < 12 * CC) g_stats[t] = 0.f;
}

__global__ void decode_idx(const void* __restrict__ ei, const void* __restrict__ ea) {
    int e = blockIdx.x * blockDim.x + threadIdx.x;
    if (e >= EE) return;
    int s, d, a;
    if (g_flags[0]) {
        const long long* p = (const long long*)ei;
        s = (int)p[e]; d = (int)p[EE + e];
    } else {
        const int* p = (const int*)ei;
        s = p[e]; d = p[EE + e];
    }
    if (g_flags[1]) {
        const long long* p = (const long long*)ea;
        a = (int)p[e];
    } else {
        const int* p = (const int*)ea;
        a = p[e];
    }
    g_src[e] = s; g_dst[e] = d; g_eat[e] = a;
    atomicAdd(&g_cnt[d], 1);
}

__global__ __launch_bounds__(1024) void csr_scan() {
    __shared__ int sh[1024];
    int t = threadIdx.x;
    int c0 = g_cnt[4*t], c1 = g_cnt[4*t+1], c2 = g_cnt[4*t+2], c3 = g_cnt[4*t+3];
    int s = c0 + c1 + c2 + c3;
    sh[t] = s;
    __syncthreads();
    for (int o = 1; o < 1024; o <<= 1) {
        int v = (t >= o) ? sh[t - o] : 0;
        __syncthreads();
        sh[t] += v;
        __syncthreads();
    }
    int base = sh[t] - s;
    g_off[4*t] = base;            g_cur[4*t] = base;
    g_off[4*t+1] = base+c0;       g_cur[4*t+1] = base+c0;
    g_off[4*t+2] = base+c0+c1;    g_cur[4*t+2] = base+c0+c1;
    g_off[4*t+3] = base+c0+c1+c2; g_cur[4*t+3] = base+c0+c1+c2;
    if (t == 1023) g_off[NN] = sh[1023];
}
__global__ void csr_fill() {
    int e = blockIdx.x * blockDim.x + threadIdx.x;
    if (e >= EE) return;
    int pos = atomicAdd(&g_cur[g_dst[e]], 1);
    g_csrc[pos] = g_src[e];
    g_ceat[pos] = g_eat[e];
}

// ---------------- GINE aggregate ----------------
__global__ __launch_bounds__(256) void gine_agg(const float* __restrict__ h,
                                                const float* __restrict__ emb,
                                                float* __restrict__ agg) {
    int warp = (blockIdx.x * 256 + threadIdx.x) >> 5;
    int lane = threadIdx.x & 31;
    if (warp >= NN) return;
    int beg = g_off[warp], end = g_off[warp + 1];
    float a0 = 0.f, a1 = 0.f, a2 = 0.f;
    for (int i = beg; i < end; i++) {
        int src = g_csrc[i], et = g_ceat[i];
        const float* hp = h + (size_t)src * CC;
        const float* ep = emb + (size_t)et * CC;
        a0 += fmaxf(hp[lane]      + ep[lane],      0.f);
        a1 += fmaxf(hp[lane + 32] + ep[lane + 32], 0.f);
        a2 += fmaxf(hp[lane + 64] + ep[lane + 64], 0.f);
    }
    float* ap = agg + (size_t)warp * CC;
    ap[lane] = a0; ap[lane + 32] = a1; ap[lane + 64] = a2;
}

// ---------------- 3xTF32 tensor-core GEMM with fused epilogue ----------------
// C = (A [+A2]) @ W + bias [+res] [relu] [BN-stats]
// grid (N/32, M/64), 128 threads. Warp w: rows [by*64 + w*16, +16), all 32 cols.
__global__ __launch_bounds__(128) void tgemm(
    const float* __restrict__ A, const float* __restrict__ A2,
    const float* __restrict__ W, const float* __restrict__ bias,
    const float* __restrict__ res, float* __restrict__ C,
    int M, int N, int K, int relu,
    float* __restrict__ st_s, float* __restrict__ st_s2)
{
    __shared__ __align__(16) unsigned Bhi[32 * 40];
    __shared__ __align__(16) unsigned Blo[32 * 40];
    __shared__ float Ssum[4][32];
    __shared__ float Ssq[4][32];
    const int tid = threadIdx.x;
    const int w = tid >> 5, lane = tid & 31;
    const int tg = lane >> 2, tq = lane & 3;
    const int row0 = blockIdx.y * 64 + w * 16;
    const int col0 = blockIdx.x * 32;

    float c[4][4];
    #pragma unroll
    for (int nt = 0; nt < 4; nt++)
        #pragma unroll
        for (int r = 0; r < 4; r++) c[nt][r] = 0.f;

    for (int k0 = 0; k0 < K; k0 += 32) {
        __syncthreads();
        #pragma unroll
        for (int j = 0; j < 2; j++) {
            int idx = tid + j * 128;
            int r = idx >> 3, c4 = (idx & 7) * 4;
            float4 v = *(const float4*)(W + (size_t)(k0 + r) * N + col0 + c4);
            unsigned h0 = f2tf32(v.x), h1 = f2tf32(v.y), h2 = f2tf32(v.z), h3 = f2tf32(v.w);
            *(uint4*)&Bhi[r * 40 + c4] = make_uint4(h0, h1, h2, h3);
            *(uint4*)&Blo[r * 40 + c4] = make_uint4(
                f2tf32(v.x - __uint_as_float(h0)), f2tf32(v.y - __uint_as_float(h1)),
                f2tf32(v.z - __uint_as_float(h2)), f2tf32(v.w - __uint_as_float(h3)));
        }
        __syncthreads();
        #pragma unroll
        for (int kc = 0; kc < 4; kc++) {
            const float* ap0 = A + (size_t)(row0 + tg) * K + k0 + kc * 8;
            const float* ap1 = A + (size_t)(row0 + tg + 8) * K + k0 + kc * 8;
            float av[4];
            av[0] = ap0[tq]; av[1] = ap1[tq]; av[2] = ap0[tq + 4]; av[3] = ap1[tq + 4];
            if (A2) {
                const float* bp0 = A2 + (size_t)(row0 + tg) * K + k0 + kc * 8;
                const float* bp1 = A2 + (size_t)(row0 + tg + 8) * K + k0 + kc * 8;
                av[0] += bp0[tq]; av[1] += bp1[tq]; av[2] += bp0[tq + 4]; av[3] += bp1[tq + 4];
            }
            unsigned ahi[4], alo[4];
            #pragma unroll
            for (int r = 0; r < 4; r++) {
                ahi[r] = f2tf32(av[r]);
                alo[r] = f2tf32(av[r] - __uint_as_float(ahi[r]));
            }
            const int kr0 = (kc * 8 + tq) * 40;
            const int kr1 = (kc * 8 + tq + 4) * 40;
            #pragma unroll
            for (int nt = 0; nt < 4; nt++) {
                unsigned bh[2], bl[2];
                bh[0] = Bhi[kr0 + nt * 8 + tg]; bh[1] = Bhi[kr1 + nt * 8 + tg];
                bl[0] = Blo[kr0 + nt * 8 + tg]; bl[1] = Blo[kr1 + nt * 8 + tg];
                mma_tf32(c[nt], ahi, bh);
                mma_tf32(c[nt], ahi, bl);
                mma_tf32(c[nt], alo, bh);
            }
        }
    }

    // epilogue
    float myS[8], myQ[8];
    #pragma unroll
    for (int nt = 0; nt < 4; nt++) {
        int cc0 = col0 + nt * 8 + 2 * tq;
        float b0 = bias[cc0], b1 = bias[cc0 + 1];
        float v00 = c[nt][0] + b0, v01 = c[nt][1] + b1;
        float v10 = c[nt][2] + b0, v11 = c[nt][3] + b1;
        if (res) {
            float2 r0v = *(const float2*)(res + (size_t)(row0 + tg) * N + cc0);
            float2 r1v = *(const float2*)(res + (size_t)(row0 + tg + 8) * N + cc0);
            v00 += r0v.x; v01 += r0v.y; v10 += r1v.x; v11 += r1v.y;
        }
        if (relu) {
            v00 = fmaxf(v00, 0.f); v01 = fmaxf(v01, 0.f);
            v10 = fmaxf(v10, 0.f); v11 = fmaxf(v11, 0.f);
        }
        *(float2*)(C + (size_t)(row0 + tg) * N + cc0) = make_float2(v00, v01);
        *(float2*)(C + (size_t)(row0 + tg + 8) * N + cc0) = make_float2(v10, v11);
        myS[nt * 2] = v00 + v10;           myS[nt * 2 + 1] = v01 + v11;
        myQ[nt * 2] = v00 * v00 + v10 * v10; myQ[nt * 2 + 1] = v01 * v01 + v11 * v11;
    }

    if (st_s) {
        #pragma unroll
        for (int i = 0; i < 8; i++) {
            #pragma unroll
            for (int o = 4; o <= 16; o <<= 1) {
                myS[i] += __shfl_xor_sync(0xffffffffu, myS[i], o);
                myQ[i] += __shfl_xor_sync(0xffffffffu, myQ[i], o);
            }
        }
        if (tg == 0) {
            #pragma unroll
            for (int nt = 0; nt < 4; nt++) {
                Ssum[w][nt * 8 + 2 * tq] = myS[nt * 2];
                Ssum[w][nt * 8 + 2 * tq + 1] = myS[nt * 2 + 1];
                Ssq[w][nt * 8 + 2 * tq] = myQ[nt * 2];
                Ssq[w][nt * 8 + 2 * tq + 1] = myQ[nt * 2 + 1];
            }
        }
        __syncthreads();
        if (tid < 32) {
            float a = Ssum[0][tid] + Ssum[1][tid] + Ssum[2][tid] + Ssum[3][tid];
            float b = Ssq[0][tid] + Ssq[1][tid] + Ssq[2][tid] + Ssq[3][tid];
            atomicAdd(&st_s[col0 + tid], a);
            atomicAdd(&st_s2[col0 + tid], b);
        }
    }
}

// ---------------- mma.sync flash attention (tf32 S, bf16 hi/lo PV) ----------------
#define QSCALE 0.2944858445807166f

__global__ __launch_bounds__(128) void flash_mma(const float* __restrict__ qkv,
                                                 float* __restrict__ po,
                                                 float* __restrict__ pl) {
    __shared__ unsigned KtU[24 * 72];
    __shared__ unsigned short Vh[24 * 72];
    __shared__ unsigned short Vl[24 * 72];
    const int h   = blockIdx.y;
    const int q0  = blockIdx.x * 128;
    const int sp  = blockIdx.z;
    const int tid = threadIdx.x;
    const int w   = tid >> 5;
    const int lane = tid & 31;
    const int tg = lane >> 2, tq = lane & 3;

    unsigned QA[2][3][4];
    #pragma unroll
    for (int mi = 0; mi < 2; mi++) {
        const float* qp0 = qkv + (size_t)(q0 + 32 * w + 16 * mi + tg) * (3 * CC) + h * DH;
        const float* qp1 = qp0 + (size_t)8 * (3 * CC);
        #pragma unroll
        for (int kc = 0; kc < 3; kc++) {
            QA[mi][kc][0] = f2tf32(qp0[kc * 8 + tq] * QSCALE);
            QA[mi][kc][1] = f2tf32(qp1[kc * 8 + tq] * QSCALE);
            QA[mi][kc][2] = f2tf32(qp0[kc * 8 + tq + 4] * QSCALE);
            QA[mi][kc][3] = f2tf32(qp1[kc * 8 + tq + 4] * QSCALE);
        }
    }

    float OC[2][3][4];
    #pragma unroll
    for (int mi = 0; mi < 2; mi++)
        #pragma unroll
        for (int n = 0; n < 3; n++)
            #pragma unroll
            for (int r = 0; r < 4; r++) OC[mi][n][r] = 0.f;
    float lacc[2][2] = {{0.f, 0.f}, {0.f, 0.f}};

    for (int t = 0; t < (NN / SPLITS) / 64; t++) {
        const int kt = sp * (NN / SPLITS) + t * 64;
        __syncthreads();
        {
            int key = tid >> 1;
            int dh0 = (tid & 1) * 12;
            const float* kp = qkv + (size_t)(kt + key) * (3 * CC) + CC + h * DH + dh0;
            const float* vp = kp + CC;
            float4 kv0 = *(const float4*)(kp);
            float4 kv1 = *(const float4*)(kp + 4);
            float4 kv2 = *(const float4*)(kp + 8);
            float4 vv0 = *(const float4*)(vp);
            float4 vv1 = *(const float4*)(vp + 4);
            float4 vv2 = *(const float4*)(vp + 8);
            float kf[12] = {kv0.x, kv0.y, kv0.z, kv0.w, kv1.x, kv1.y, kv1.z, kv1.w,
                            kv2.x, kv2.y, kv2.z, kv2.w};
            float vf[12] = {vv0.x, vv0.y, vv0.z, vv0.w, vv1.x, vv1.y, vv1.z, vv1.w,
                            vv2.x, vv2.y, vv2.z, vv2.w};
            #pragma unroll
            for (int i = 0; i < 12; i++) {
                int d = dh0 + i;
                KtU[d * 72 + key] = f2tf32(kf[i]);
                __nv_bfloat16 bh = __float2bfloat16(vf[i]);
                float rem = vf[i] - __bfloat162float(bh);
                __nv_bfloat16 bl = __float2bfloat16(rem);
                Vh[d * 72 + key] = __bfloat16_as_ushort(bh);
                Vl[d * 72 + key] = __bfloat16_as_ushort(bl);
            }
        }
        __syncthreads();

        float SC[2][8][4];
        #pragma unroll
        for (int mi = 0; mi < 2; mi++)
            #pragma unroll
            for (int nt = 0; nt < 8; nt++)
                #pragma unroll
                for (int r = 0; r < 4; r++) SC[mi][nt][r] = 0.f;

        #pragma unroll
        for (int nt = 0; nt < 8; nt++) {
            unsigned bB[3][2];
            #pragma unroll
            for (int kc = 0; kc < 3; kc++) {
                bB[kc][0] = KtU[(kc * 8 + tq) * 72 + nt * 8 + tg];
                bB[kc][1] = KtU[(kc * 8 + tq + 4) * 72 + nt * 8 + tg];
            }
            #pragma unroll
            for (int kc = 0; kc < 3; kc++) {
                mma_tf32(SC[0][nt], QA[0][kc], bB[kc]);
                mma_tf32(SC[1][nt], QA[1][kc], bB[kc]);
            }
        }

        #pragma unroll
        for (int mi = 0; mi < 2; mi++)
            #pragma unroll
            for (int nt = 0; nt < 8; nt++)
                #pragma unroll
                for (int r = 0; r < 4; r++) {
                    float e;
                    asm("ex2.approx.ftz.f32 %0, %1;" : "=f"(e) : "f"(SC[mi][nt][r]));
                    SC[mi][nt][r] = e;
                    lacc[mi][r >> 1] += e;
                }

        unsigned PA[2][4][4];
        #pragma unroll
        for (int mi = 0; mi < 2; mi++)
            #pragma unroll
            for (int kc4 = 0; kc4 < 4; kc4++) {
                PA[mi][kc4][0] = pkbf(SC[mi][2 * kc4][0],     SC[mi][2 * kc4][1]);
                PA[mi][kc4][1] = pkbf(SC[mi][2 * kc4][2],     SC[mi][2 * kc4][3]);
                PA[mi][kc4][2] = pkbf(SC[mi][2 * kc4 + 1][0], SC[mi][2 * kc4 + 1][1]);
                PA[mi][kc4][3] = pkbf(SC[mi][2 * kc4 + 1][2], SC[mi][2 * kc4 + 1][3]);
            }

        #pragma unroll
        for (int kc4 = 0; kc4 < 4; kc4++) {
            #pragma unroll
            for (int n = 0; n < 3; n++) {
                int drow = n * 8 + tg;
                int col = kc4 * 16 + 2 * tq;
                unsigned bh[2], bl[2];
                bh[0] = *(const unsigned*)&Vh[drow * 72 + col];
                bh[1] = *(const unsigned*)&Vh[drow * 72 + col + 8];
                bl[0] = *(const unsigned*)&Vl[drow * 72 + col];
                bl[1] = *(const unsigned*)&Vl[drow * 72 + col + 8];
                mma_bf16(OC[0][n], PA[0][kc4], bh);
                mma_bf16(OC[1][n], PA[1][kc4], bh);
                mma_bf16(OC[0][n], PA[0][kc4], bl);
                mma_bf16(OC[1][n], PA[1][kc4], bl);
            }
        }
    }

    #pragma unroll
    for (int mi = 0; mi < 2; mi++)
        #pragma unroll
        for (int hi = 0; hi < 2; hi++) {
            float v = lacc[mi][hi];
            v += __shfl_xor_sync(0xffffffffu, v, 1);
            v += __shfl_xor_sync(0xffffffffu, v, 2);
            lacc[mi][hi] = v;
        }

    const int base = (sp * NHEADS + h) * NN;
    #pragma unroll
    for (int mi = 0; mi < 2; mi++) {
        int r0 = q0 + 32 * w + 16 * mi + tg;
        int r1 = r0 + 8;
        if (tq == 0) {
            pl[base + r0] = lacc[mi][0];
            pl[base + r1] = lacc[mi][1];
        }
        #pragma unroll
        for (int n = 0; n < 3; n++) {
            float2 v0 = make_float2(OC[mi][n][0], OC[mi][n][1]);
            float2 v1 = make_float2(OC[mi][n][2], OC[mi][n][3]);
            *(float2*)(po + ((size_t)(base + r0)) * DH + n * 8 + 2 * tq) = v0;
            *(float2*)(po + ((size_t)(base + r1)) * DH + n * 8 + 2 * tq) = v1;
        }
    }
}

__global__ void flash_combine(const float* __restrict__ po, const float* __restrict__ pl,
                              float* __restrict__ outp) {
    int t = blockIdx.x * blockDim.x + threadIdx.x;
    if (t >= NN * NHEADS) return;
    int q = t & (NN - 1);
    int h = t >> 12;
    float L = 0.f;
    #pragma unroll
    for (int s = 0; s < SPLITS; s++) L += pl[(s * NHEADS + h) * NN + q];
    float inv = 1.f / L;
    float* op = outp + (size_t)q * CC + h * DH;
    #pragma unroll
    for (int d = 0; d < DH; d += 4) {
        float4 acc = make_float4(0.f, 0.f, 0.f, 0.f);
        #pragma unroll
        for (int s = 0; s < SPLITS; s++) {
            const float4 v = *(const float4*)(po + ((size_t)(s * NHEADS + h) * NN + q) * DH + d);
            acc.x += v.x; acc.y += v.y; acc.z += v.z; acc.w += v.w;
        }
        acc.x *= inv; acc.y *= inv; acc.z *= inv; acc.w *= inv;
        *(float4*)(op + d) = acc;
    }
}

// ---------------- BN elementwise ----------------
__global__ void bn2_add(const float* __restrict__ p1, const float* __restrict__ p2,
                        const float* __restrict__ st,
                        const float* __restrict__ g1, const float* __restrict__ b1,
                        const float* __restrict__ g2, const float* __restrict__ b2,
                        float* __restrict__ out) {
    int i = blockIdx.x * blockDim.x + threadIdx.x;
    if (i >= NN * CC) return;
    int c = i % CC;
    const float invn = 1.f / NN;
    float m1 = st[c] * invn;
    float v1 = st[CC + c] * invn - m1 * m1;
    float m2 = st[2 * CC + c] * invn;
    float v2 = st[3 * CC + c] * invn - m2 * m2;
    float o = (p1[i] - m1) * rsqrtf(v1 + 1e-5f) * g1[c] + b1[c]
            + (p2[i] - m2) * rsqrtf(v2 + 1e-5f) * g2[c] + b2[c];
    out[i] = o;
}

__global__ void bn_apply(const float* __restrict__ p, const float* __restrict__ s,
                         const float* __restrict__ s2, const float* __restrict__ g,
                         const float* __restrict__ b, float* __restrict__ o) {
    int i = blockIdx.x * blockDim.x + threadIdx.x;
    if (i >= NN * CC) return;
    int c = i % CC;
    const float invn = 1.f / NN;
    float m = s[c] * invn;
    float v = s2[c] * invn - m * m;
    o[i] = (p[i] - m) * rsqrtf(v + 1e-5f) * g[c] + b[c];
}

// ---------------- final per-row LayerNorm ----------------
__global__ void out_ln(const float* __restrict__ y, const float* __restrict__ g,
                       const float* __restrict__ b, float* __restrict__ out) {
    int lane = threadIdx.x & 31;
    int warp = threadIdx.x >> 5;
    int row  = blockIdx.x * 4 + warp;
    const float* yr = y + (size_t)row * CC;
    float v0 = yr[lane], v1 = yr[lane + 32], v2 = yr[lane + 64];
    float s = v0 + v1 + v2;
    #pragma unroll
    for (int o = 16; o; o >>= 1) s += __shfl_xor_sync(0xffffffffu, s, o);
    float mean = s * (1.f / 96.f);
    float d0 = v0 - mean, d1 = v1 - mean, d2 = v2 - mean;
    float qv = d0 * d0 + d1 * d1 + d2 * d2;
    #pragma unroll
    for (int o = 16; o; o >>= 1) qv += __shfl_xor_sync(0xffffffffu, qv, o);
    float inv = rsqrtf(qv * (1.f / 96.f) + 1e-5f);
    float* orow = out + (size_t)row * CC;
    orow[lane]      = d0 * inv * g[lane]      + b[lane];
    orow[lane + 32] = d1 * inv * g[lane + 32] + b[lane + 32];
    orow[lane + 64] = d2 * inv * g[lane + 64] + b[lane + 64];
}

// ---------------- launch ----------------
extern "C" void kernel_launch(void* const* d_in, const int* in_sizes, int n_in,
                              void* d_out, int out_size) {
    const float*     x    = (const float*)d_in[0];
    const void*      ei   = d_in[1];
    const void*      ea   = d_in[2];
    const float*     w_in = (const float*)d_in[3];
    const float*     b_in = (const float*)d_in[4];
    const float*     emb  = (const float*)d_in[5];
    const float*     gw1  = (const float*)d_in[6];
    const float*     gb1  = (const float*)d_in[7];
    const float*     gw2  = (const float*)d_in[8];
    const float*     gb2  = (const float*)d_in[9];
    const float*     wqkv = (const float*)d_in[10];
    const float*     bqkv = (const float*)d_in[11];
    const float*     wo   = (const float*)d_in[12];
    const float*     bo   = (const float*)d_in[13];
    const float*     bng  = (const float*)d_in[14];
    const float*     bnb  = (const float*)d_in[15];
    const float*     fw1  = (const float*)d_in[16];
    const float*     fb1  = (const float*)d_in[17];
    const float*     fw2  = (const float*)d_in[18];
    const float*     fb2  = (const float*)d_in[19];
    const float*     w_o  = (const float*)d_in[20];
    const float*     b_o  = (const float*)d_in[21];
    const float*     lng  = (const float*)d_in[22];
    const float*     lnb  = (const float*)d_in[23];
    float* out = (float*)d_out;

    float *h_, *agg_, *t1_, *pre1_, *qkv_, *attno_, *pre2_, *outb_, *t2_, *pre3_, *y_, *stA_;
    float *po_, *pl_;
    cudaGetSymbolAddress((void**)&h_,    g_h);
    cudaGetSymbolAddress((void**)&agg_,  g_agg);
    cudaGetSymbolAddress((void**)&t1_,   g_t1);
    cudaGetSymbolAddress((void**)&pre1_, g_pre1);
    cudaGetSymbolAddress((void**)&qkv_,  g_qkv);
    cudaGetSymbolAddress((void**)&attno_,g_attno);
    cudaGetSymbolAddress((void**)&pre2_, g_pre2);
    cudaGetSymbolAddress((void**)&outb_, g_outb);
    cudaGetSymbolAddress((void**)&t2_,   g_t2);
    cudaGetSymbolAddress((void**)&pre3_, g_pre3);
    cudaGetSymbolAddress((void**)&y_,    g_y);
    cudaGetSymbolAddress((void**)&stA_,  g_stats);
    cudaGetSymbolAddress((void**)&po_,   g_po);
    cudaGetSymbolAddress((void**)&pl_,   g_pl);

    auto gemm = [&](const float* A, const float* A2, const float* W, const float* bias,
                    const float* res, float* Cp, int M, int Nc, int K, int relu,
                    float* ss = nullptr, float* ss2 = nullptr) {
        dim3 grid(Nc / 32, M / 64);
        tgemm<<<grid, 128>>>(A, A2, W, bias, res, Cp, M, Nc, K, relu, ss, ss2);
    };

    const int NCEL = NN * CC;

    // 1: prologue
    prep<<<16, 256>>>((const unsigned*)ei, (const unsigned*)ea);
    // 2: input projection
    gemm(x, nullptr, w_in, b_in, nullptr, h_, NN, CC, 64, 0);

    for (int i = 0; i < 2; i++) {
        float* st_ = stA_ + (size_t)i * 6 * CC;

        // --- attention branch (launch #4 overall = flash_mma, for ncu) ---
        gemm(h_, nullptr, wqkv + (size_t)i * CC * 3 * CC, bqkv + (size_t)i * 3 * CC,
             nullptr, qkv_, NN, 3 * CC, CC, 0);
        flash_mma<<<dim3(NN / 128, NHEADS, SPLITS), 128>>>(qkv_, po_, pl_);
        flash_combine<<<(NN * NHEADS + 255) / 256, 256>>>(po_, pl_, attno_);
        gemm(attno_, nullptr, wo + (size_t)i * CC * CC, bo + (size_t)i * CC,
             h_, pre2_, NN, CC, CC, 0, st_ + 2 * CC, st_ + 3 * CC);

        if (i == 0) {
            decode_idx<<<(EE + 255) / 256, 256>>>(ei, ea);
            csr_scan<<<1, 1024>>>();
            csr_fill<<<(EE + 255) / 256, 256>>>();
        }

        // --- GINE branch ---
        gine_agg<<<NN / 8, 256>>>(h_, emb, agg_);
        gemm(agg_, h_, gw1, gb1, nullptr, t1_, NN, CC, CC, 1);
        gemm(t1_, nullptr, gw2, gb2, h_, pre1_, NN, CC, CC, 0, st_ + 0, st_ + CC);

        // --- merge + FFN ---
        bn2_add<<<(NCEL + 255) / 256, 256>>>(pre1_, pre2_, st_,
                                             bng + (size_t)i * 3 * CC, bnb + (size_t)i * 3 * CC,
                                             bng + (size_t)i * 3 * CC + CC, bnb + (size_t)i * 3 * CC + CC,
                                             outb_);
        gemm(outb_, nullptr, fw1 + (size_t)i * CC * 2 * CC, fb1 + (size_t)i * 2 * CC,
             nullptr, t2_, NN, 2 * CC, CC, 1);
        gemm(t2_, nullptr, fw2 + (size_t)i * 2 * CC * CC, fb2 + (size_t)i * CC,
             outb_, pre3_, NN, CC, 2 * CC, 0, st_ + 4 * CC, st_ + 5 * CC);
        bn_apply<<<(NCEL + 255) / 256, 256>>>(pre3_, st_ + 4 * CC, st_ + 5 * CC,
                                              bng + (size_t)i * 3 * CC + 2 * CC,
                                              bnb + (size_t)i * 3 * CC + 2 * CC, h_);
    }

    gemm(h_, nullptr, w_o, b_o, nullptr, y_, NN, CC, CC, 0);
    out_ln<<<NN / 4, 128>>>(y_, lng, lnb, out);
}

// round 9
// speedup vs baseline: 4.2820x; 1.2061x over previous
#include <cuda_runtime.h>
#include <cuda_bf16.h>
#include <cstdint>

#define NN 4096
#define CC 96
#define EE 131072
#define NHEADS 4
#define DH 24
#define SPLITS 8

typedef unsigned long long u64;

// ---------------- scratch ----------------
__device__ float g_h[NN*CC];
__device__ float g_agg[NN*CC];
__device__ float g_t1[NN*CC];
__device__ float g_pre1[NN*CC];
__device__ float g_qkv[NN*3*CC];
__device__ float g_attno[NN*CC];
__device__ float g_pre2[NN*CC];
__device__ float g_outb[NN*CC];
__device__ float g_t2[NN*2*CC];
__device__ float g_pre3[NN*CC];
__device__ float g_y[NN*CC];
__device__ float g_stats[12*CC];
__device__ int   g_src[EE];
__device__ int   g_dst[EE];
__device__ int   g_eat[EE];
__device__ int   g_flags[2];
__device__ int   g_cnt[NN];
__device__ int   g_off[NN+1];
__device__ int   g_cur[NN];
__device__ int   g_csrc[EE];
__device__ int   g_ceat[EE];
__device__ float g_po[SPLITS*NHEADS*NN*DH];
__device__ float g_pl[SPLITS*NHEADS*NN];

// ---------------- mma.sync helpers ----------------
__device__ __forceinline__ unsigned f2tf32(float f) {
    unsigned r; asm("cvt.rna.tf32.f32 %0, %1;" : "=r"(r) : "f"(f)); return r;
}
__device__ __forceinline__ unsigned pkbf(float lo, float hi) {
    unsigned r; asm("cvt.rn.bf16x2.f32 %0, %1, %2;" : "=r"(r) : "f"(hi), "f"(lo)); return r;
}
__device__ __forceinline__ void mma_tf32(float* c, const unsigned* a, const unsigned* b) {
    asm volatile("mma.sync.aligned.m16n8k8.row.col.f32.tf32.tf32.f32 "
        "{%0,%1,%2,%3}, {%4,%5,%6,%7}, {%8,%9}, {%0,%1,%2,%3};"
        : "+f"(c[0]), "+f"(c[1]), "+f"(c[2]), "+f"(c[3])
        : "r"(a[0]), "r"(a[1]), "r"(a[2]), "r"(a[3]), "r"(b[0]), "r"(b[1]));
}
__device__ __forceinline__ void mma_bf16(float* c, const unsigned* a, const unsigned* b) {
    asm volatile("mma.sync.aligned.m16n8k16.row.col.f32.bf16.bf16.f32 "
        "{%0,%1,%2,%3}, {%4,%5,%6,%7}, {%8,%9}, {%0,%1,%2,%3};"
        : "+f"(c[0]), "+f"(c[1]), "+f"(c[2]), "+f"(c[3])
        : "r"(a[0]), "r"(a[1]), "r"(a[2]), "r"(a[3]), "r"(b[0]), "r"(b[1]));
}

// ---------------- prologue ----------------
__global__ void prep(const unsigned* __restrict__ ei, const unsigned* __restrict__ ea) {
    int t = blockIdx.x * blockDim.x + threadIdx.x;
    if (blockIdx.x == 0 && threadIdx.x < 32) {
        int lane = threadIdx.x;
        unsigned v1 = (lane < 16) ? ei[2 * lane + 1] : 0u;
        unsigned v2 = (lane < 16) ? ea[2 * lane + 1] : 0u;
        unsigned b1 = __ballot_sync(0xffffffffu, v1 != 0u);
        unsigned b2 = __ballot_sync(0xffffffffu, v2 != 0u);
        if (lane == 0) { g_flags[0] = (b1 == 0u); g_flags[1] = (b2 == 0u); }
    }
    if (t < NN) g_cnt[t] = 0;
    if (t < 12 * CC) g_stats[t] = 0.f;
}

__global__ void decode_idx(const void* __restrict__ ei, const void* __restrict__ ea) {
    int e = blockIdx.x * blockDim.x + threadIdx.x;
    if (e >= EE) return;
    int s, d, a;
    if (g_flags[0]) {
        const long long* p = (const long long*)ei;
        s = (int)p[e]; d = (int)p[EE + e];
    } else {
        const int* p = (const int*)ei;
        s = p[e]; d = p[EE + e];
    }
    if (g_flags[1]) {
        const long long* p = (const long long*)ea;
        a = (int)p[e];
    } else {
        const int* p = (const int*)ea;
        a = p[e];
    }
    g_src[e] = s; g_dst[e] = d; g_eat[e] = a;
    atomicAdd(&g_cnt[d], 1);
}

__global__ __launch_bounds__(1024) void csr_scan() {
    __shared__ int sh[1024];
    int t = threadIdx.x;
    int c0 = g_cnt[4*t], c1 = g_cnt[4*t+1], c2 = g_cnt[4*t+2], c3 = g_cnt[4*t+3];
    int s = c0 + c1 + c2 + c3;
    sh[t] = s;
    __syncthreads();
    for (int o = 1; o < 1024; o <<= 1) {
        int v = (t >= o) ? sh[t - o] : 0;
        __syncthreads();
        sh[t] += v;
        __syncthreads();
    }
    int base = sh[t] - s;
    g_off[4*t] = base;            g_cur[4*t] = base;
    g_off[4*t+1] = base+c0;       g_cur[4*t+1] = base+c0;
    g_off[4*t+2] = base+c0+c1;    g_cur[4*t+2] = base+c0+c1;
    g_off[4*t+3] = base+c0+c1+c2; g_cur[4*t+3] = base+c0+c1+c2;
    if (t == 1023) g_off[NN] = sh[1023];
}
__global__ void csr_fill() {
    int e = blockIdx.x * blockDim.x + threadIdx.x;
    if (e >= EE) return;
    int pos = atomicAdd(&g_cur[g_dst[e]], 1);
    g_csrc[pos] = g_src[e];
    g_ceat[pos] = g_eat[e];
}

// ---------------- GINE aggregate ----------------
__global__ __launch_bounds__(256) void gine_agg(const float* __restrict__ h,
                                                const float* __restrict__ emb,
                                                float* __restrict__ agg) {
    int warp = (blockIdx.x * 256 + threadIdx.x) >> 5;
    int lane = threadIdx.x & 31;
    if (warp >= NN) return;
    int beg = g_off[warp], end = g_off[warp + 1];
    float a0 = 0.f, a1 = 0.f, a2 = 0.f;
    for (int i = beg; i < end; i++) {
        int src = g_csrc[i], et = g_ceat[i];
        const float* hp = h + (size_t)src * CC;
        const float* ep = emb + (size_t)et * CC;
        a0 += fmaxf(hp[lane]      + ep[lane],      0.f);
        a1 += fmaxf(hp[lane + 32] + ep[lane + 32], 0.f);
        a2 += fmaxf(hp[lane + 64] + ep[lane + 64], 0.f);
    }
    float* ap = agg + (size_t)warp * CC;
    ap[lane] = a0; ap[lane + 32] = a1; ap[lane + 64] = a2;
}

// ---------------- 3xTF32 tensor-core GEMM with fused epilogue ----------------
__global__ __launch_bounds__(128) void tgemm(
    const float* __restrict__ A, const float* __restrict__ A2,
    const float* __restrict__ W, const float* __restrict__ bias,
    const float* __restrict__ res, float* __restrict__ C,
    int M, int N, int K, int relu,
    float* __restrict__ st_s, float* __restrict__ st_s2)
{
    __shared__ __align__(16) unsigned Bhi[32 * 40];
    __shared__ __align__(16) unsigned Blo[32 * 40];
    __shared__ float Ssum[4][32];
    __shared__ float Ssq[4][32];
    const int tid = threadIdx.x;
    const int w = tid >> 5, lane = tid & 31;
    const int tg = lane >> 2, tq = lane & 3;
    const int row0 = blockIdx.y * 64 + w * 16;
    const int col0 = blockIdx.x * 32;

    float c[4][4];
    #pragma unroll
    for (int nt = 0; nt < 4; nt++)
        #pragma unroll
        for (int r = 0; r < 4; r++) c[nt][r] = 0.f;

    for (int k0 = 0; k0 < K; k0 += 32) {
        __syncthreads();
        #pragma unroll
        for (int j = 0; j < 2; j++) {
            int idx = tid + j * 128;
            int r = idx >> 3, c4 = (idx & 7) * 4;
            float4 v = *(const float4*)(W + (size_t)(k0 + r) * N + col0 + c4);
            unsigned h0 = f2tf32(v.x), h1 = f2tf32(v.y), h2 = f2tf32(v.z), h3 = f2tf32(v.w);
            *(uint4*)&Bhi[r * 40 + c4] = make_uint4(h0, h1, h2, h3);
            *(uint4*)&Blo[r * 40 + c4] = make_uint4(
                f2tf32(v.x - __uint_as_float(h0)), f2tf32(v.y - __uint_as_float(h1)),
                f2tf32(v.z - __uint_as_float(h2)), f2tf32(v.w - __uint_as_float(h3)));
        }
        __syncthreads();
        #pragma unroll
        for (int kc = 0; kc < 4; kc++) {
            const float* ap0 = A + (size_t)(row0 + tg) * K + k0 + kc * 8;
            const float* ap1 = A + (size_t)(row0 + tg + 8) * K + k0 + kc * 8;
            float av[4];
            av[0] = ap0[tq]; av[1] = ap1[tq]; av[2] = ap0[tq + 4]; av[3] = ap1[tq + 4];
            if (A2) {
                const float* bp0 = A2 + (size_t)(row0 + tg) * K + k0 + kc * 8;
                const float* bp1 = A2 + (size_t)(row0 + tg + 8) * K + k0 + kc * 8;
                av[0] += bp0[tq]; av[1] += bp1[tq]; av[2] += bp0[tq + 4]; av[3] += bp1[tq + 4];
            }
            unsigned ahi[4], alo[4];
            #pragma unroll
            for (int r = 0; r < 4; r++) {
                ahi[r] = f2tf32(av[r]);
                alo[r] = f2tf32(av[r] - __uint_as_float(ahi[r]));
            }
            const int kr0 = (kc * 8 + tq) * 40;
            const int kr1 = (kc * 8 + tq + 4) * 40;
            #pragma unroll
            for (int nt = 0; nt < 4; nt++) {
                unsigned bh[2], bl[2];
                bh[0] = Bhi[kr0 + nt * 8 + tg]; bh[1] = Bhi[kr1 + nt * 8 + tg];
                bl[0] = Blo[kr0 + nt * 8 + tg]; bl[1] = Blo[kr1 + nt * 8 + tg];
                mma_tf32(c[nt], ahi, bh);
                mma_tf32(c[nt], ahi, bl);
                mma_tf32(c[nt], alo, bh);
            }
        }
    }

    float myS[8], myQ[8];
    #pragma unroll
    for (int nt = 0; nt < 4; nt++) {
        int cc0 = col0 + nt * 8 + 2 * tq;
        float b0 = bias[cc0], b1 = bias[cc0 + 1];
        float v00 = c[nt][0] + b0, v01 = c[nt][1] + b1;
        float v10 = c[nt][2] + b0, v11 = c[nt][3] + b1;
        if (res) {
            float2 r0v = *(const float2*)(res + (size_t)(row0 + tg) * N + cc0);
            float2 r1v = *(const float2*)(res + (size_t)(row0 + tg + 8) * N + cc0);
            v00 += r0v.x; v01 += r0v.y; v10 += r1v.x; v11 += r1v.y;
        }
        if (relu) {
            v00 = fmaxf(v00, 0.f); v01 = fmaxf(v01, 0.f);
            v10 = fmaxf(v10, 0.f); v11 = fmaxf(v11, 0.f);
        }
        *(float2*)(C + (size_t)(row0 + tg) * N + cc0) = make_float2(v00, v01);
        *(float2*)(C + (size_t)(row0 + tg + 8) * N + cc0) = make_float2(v10, v11);
        myS[nt * 2] = v00 + v10;           myS[nt * 2 + 1] = v01 + v11;
        myQ[nt * 2] = v00 * v00 + v10 * v10; myQ[nt * 2 + 1] = v01 * v01 + v11 * v11;
    }

    if (st_s) {
        #pragma unroll
        for (int i = 0; i < 8; i++) {
            #pragma unroll
            for (int o = 4; o <= 16; o <<= 1) {
                myS[i] += __shfl_xor_sync(0xffffffffu, myS[i], o);
                myQ[i] += __shfl_xor_sync(0xffffffffu, myQ[i], o);
            }
        }
        if (tg == 0) {
            #pragma unroll
            for (int nt = 0; nt < 4; nt++) {
                Ssum[w][nt * 8 + 2 * tq] = myS[nt * 2];
                Ssum[w][nt * 8 + 2 * tq + 1] = myS[nt * 2 + 1];
                Ssq[w][nt * 8 + 2 * tq] = myQ[nt * 2];
                Ssq[w][nt * 8 + 2 * tq + 1] = myQ[nt * 2 + 1];
            }
        }
        __syncthreads();
        if (tid < 32) {
            float a = Ssum[0][tid] + Ssum[1][tid] + Ssum[2][tid] + Ssum[3][tid];
            float b = Ssq[0][tid] + Ssq[1][tid] + Ssq[2][tid] + Ssq[3][tid];
            atomicAdd(&st_s[col0 + tid], a);
            atomicAdd(&st_s2[col0 + tid], b);
        }
    }
}

// ---------------- mma.sync flash attention (tf32 S, bf16 PV) ----------------
#define QSCALE 0.2944858445807166f

__global__ __launch_bounds__(128) void flash_mma(const float* __restrict__ qkv,
                                                 float* __restrict__ po,
                                                 float* __restrict__ pl) {
    __shared__ unsigned KtU[24 * 72];
    __shared__ unsigned short Vh[24 * 72];
    const int h   = blockIdx.y;
    const int q0  = blockIdx.x * 128;
    const int sp  = blockIdx.z;
    const int tid = threadIdx.x;
    const int w   = tid >> 5;
    const int lane = tid & 31;
    const int tg = lane >> 2, tq = lane & 3;

    unsigned QA[2][3][4];
    #pragma unroll
    for (int mi = 0; mi < 2; mi++) {
        const float* qp0 = qkv + (size_t)(q0 + 32 * w + 16 * mi + tg) * (3 * CC) + h * DH;
        const float* qp1 = qp0 + (size_t)8 * (3 * CC);
        #pragma unroll
        for (int kc = 0; kc < 3; kc++) {
            QA[mi][kc][0] = f2tf32(qp0[kc * 8 + tq] * QSCALE);
            QA[mi][kc][1] = f2tf32(qp1[kc * 8 + tq] * QSCALE);
            QA[mi][kc][2] = f2tf32(qp0[kc * 8 + tq + 4] * QSCALE);
            QA[mi][kc][3] = f2tf32(qp1[kc * 8 + tq + 4] * QSCALE);
        }
    }

    float OC[2][3][4];
    #pragma unroll
    for (int mi = 0; mi < 2; mi++)
        #pragma unroll
        for (int n = 0; n < 3; n++)
            #pragma unroll
            for (int r = 0; r < 4; r++) OC[mi][n][r] = 0.f;
    float lacc[2][2] = {{0.f, 0.f}, {0.f, 0.f}};

    for (int t = 0; t < (NN / SPLITS) / 64; t++) {
        const int kt = sp * (NN / SPLITS) + t * 64;
        __syncthreads();
        {
            int key = tid >> 1;
            int dh0 = (tid & 1) * 12;
            const float* kp = qkv + (size_t)(kt + key) * (3 * CC) + CC + h * DH + dh0;
            const float* vp = kp + CC;
            float4 kv0 = *(const float4*)(kp);
            float4 kv1 = *(const float4*)(kp + 4);
            float4 kv2 = *(const float4*)(kp + 8);
            float4 vv0 = *(const float4*)(vp);
            float4 vv1 = *(const float4*)(vp + 4);
            float4 vv2 = *(const float4*)(vp + 8);
            float kf[12] = {kv0.x, kv0.y, kv0.z, kv0.w, kv1.x, kv1.y, kv1.z, kv1.w,
                            kv2.x, kv2.y, kv2.z, kv2.w};
            float vf[12] = {vv0.x, vv0.y, vv0.z, vv0.w, vv1.x, vv1.y, vv1.z, vv1.w,
                            vv2.x, vv2.y, vv2.z, vv2.w};
            #pragma unroll
            for (int i = 0; i < 12; i++) {
                int d = dh0 + i;
                KtU[d * 72 + key] = f2tf32(kf[i]);
                Vh[d * 72 + key] = __bfloat16_as_ushort(__float2bfloat16(vf[i]));
            }
        }
        __syncthreads();

        float SC[2][8][4];
        #pragma unroll
        for (int mi = 0; mi < 2; mi++)
            #pragma unroll
            for (int nt = 0; nt < 8; nt++)
                #pragma unroll
                for (int r = 0; r < 4; r++) SC[mi][nt][r] = 0.f;

        #pragma unroll
        for (int nt = 0; nt < 8; nt++) {
            unsigned bB[3][2];
            #pragma unroll
            for (int kc = 0; kc < 3; kc++) {
                bB[kc][0] = KtU[(kc * 8 + tq) * 72 + nt * 8 + tg];
                bB[kc][1] = KtU[(kc * 8 + tq + 4) * 72 + nt * 8 + tg];
            }
            #pragma unroll
            for (int kc = 0; kc < 3; kc++) {
                mma_tf32(SC[0][nt], QA[0][kc], bB[kc]);
                mma_tf32(SC[1][nt], QA[1][kc], bB[kc]);
            }
        }

        #pragma unroll
        for (int mi = 0; mi < 2; mi++)
            #pragma unroll
            for (int nt = 0; nt < 8; nt++)
                #pragma unroll
                for (int r = 0; r < 4; r++) {
                    float e;
                    asm("ex2.approx.ftz.f32 %0, %1;" : "=f"(e) : "f"(SC[mi][nt][r]));
                    SC[mi][nt][r] = e;
                    lacc[mi][r >> 1] += e;
                }

        unsigned PA[2][4][4];
        #pragma unroll
        for (int mi = 0; mi < 2; mi++)
            #pragma unroll
            for (int kc4 = 0; kc4 < 4; kc4++) {
                PA[mi][kc4][0] = pkbf(SC[mi][2 * kc4][0],     SC[mi][2 * kc4][1]);
                PA[mi][kc4][1] = pkbf(SC[mi][2 * kc4][2],     SC[mi][2 * kc4][3]);
                PA[mi][kc4][2] = pkbf(SC[mi][2 * kc4 + 1][0], SC[mi][2 * kc4 + 1][1]);
                PA[mi][kc4][3] = pkbf(SC[mi][2 * kc4 + 1][2], SC[mi][2 * kc4 + 1][3]);
            }

        #pragma unroll
        for (int kc4 = 0; kc4 < 4; kc4++) {
            #pragma unroll
            for (int n = 0; n < 3; n++) {
                int drow = n * 8 + tg;
                int col = kc4 * 16 + 2 * tq;
                unsigned bh[2];
                bh[0] = *(const unsigned*)&Vh[drow * 72 + col];
                bh[1] = *(const unsigned*)&Vh[drow * 72 + col + 8];
                mma_bf16(OC[0][n], PA[0][kc4], bh);
                mma_bf16(OC[1][n], PA[1][kc4], bh);
            }
        }
    }

    #pragma unroll
    for (int mi = 0; mi < 2; mi++)
        #pragma unroll
        for (int hi = 0; hi < 2; hi++) {
            float v = lacc[mi][hi];
            v += __shfl_xor_sync(0xffffffffu, v, 1);
            v += __shfl_xor_sync(0xffffffffu, v, 2);
            lacc[mi][hi] = v;
        }

    const int base = (sp * NHEADS + h) * NN;
    #pragma unroll
    for (int mi = 0; mi < 2; mi++) {
        int r0 = q0 + 32 * w + 16 * mi + tg;
        int r1 = r0 + 8;
        if (tq == 0) {
            pl[base + r0] = lacc[mi][0];
            pl[base + r1] = lacc[mi][1];
        }
        #pragma unroll
        for (int n = 0; n < 3; n++) {
            float2 v0 = make_float2(OC[mi][n][0], OC[mi][n][1]);
            float2 v1 = make_float2(OC[mi][n][2], OC[mi][n][3]);
            *(float2*)(po + ((size_t)(base + r0)) * DH + n * 8 + 2 * tq) = v0;
            *(float2*)(po + ((size_t)(base + r1)) * DH + n * 8 + 2 * tq) = v1;
        }
    }
}

__global__ void flash_combine(const float* __restrict__ po, const float* __restrict__ pl,
                              float* __restrict__ outp) {
    int t = blockIdx.x * blockDim.x + threadIdx.x;
    if (t >= NN * NHEADS) return;
    int q = t & (NN - 1);
    int h = t >> 12;
    float L = 0.f;
    #pragma unroll
    for (int s = 0; s < SPLITS; s++) L += pl[(s * NHEADS + h) * NN + q];
    float inv = 1.f / L;
    float* op = outp + (size_t)q * CC + h * DH;
    #pragma unroll
    for (int d = 0; d < DH; d += 4) {
        float4 acc = make_float4(0.f, 0.f, 0.f, 0.f);
        #pragma unroll
        for (int s = 0; s < SPLITS; s++) {
            const float4 v = *(const float4*)(po + ((size_t)(s * NHEADS + h) * NN + q) * DH + d);
            acc.x += v.x; acc.y += v.y; acc.z += v.z; acc.w += v.w;
        }
        acc.x *= inv; acc.y *= inv; acc.z *= inv; acc.w *= inv;
        *(float4*)(op + d) = acc;
    }
}

// ---------------- BN elementwise ----------------
__global__ void bn2_add(const float* __restrict__ p1, const float* __restrict__ p2,
                        const float* __restrict__ st,
                        const float* __restrict__ g1, const float* __restrict__ b1,
                        const float* __restrict__ g2, const float* __restrict__ b2,
                        float* __restrict__ out) {
    int i = blockIdx.x * blockDim.x + threadIdx.x;
    if (i >= NN * CC) return;
    int c = i % CC;
    const float invn = 1.f / NN;
    float m1 = st[c] * invn;
    float v1 = st[CC + c] * invn - m1 * m1;
    float m2 = st[2 * CC + c] * invn;
    float v2 = st[3 * CC + c] * invn - m2 * m2;
    float o = (p1[i] - m1) * rsqrtf(v1 + 1e-5f) * g1[c] + b1[c]
            + (p2[i] - m2) * rsqrtf(v2 + 1e-5f) * g2[c] + b2[c];
    out[i] = o;
}

__global__ void bn_apply(const float* __restrict__ p, const float* __restrict__ s,
                         const float* __restrict__ s2, const float* __restrict__ g,
                         const float* __restrict__ b, float* __restrict__ o) {
    int i = blockIdx.x * blockDim.x + threadIdx.x;
    if (i >= NN * CC) return;
    int c = i % CC;
    const float invn = 1.f / NN;
    float m = s[c] * invn;
    float v = s2[c] * invn - m * m;
    o[i] = (p[i] - m) * rsqrtf(v + 1e-5f) * g[c] + b[c];
}

// ---------------- final per-row LayerNorm ----------------
__global__ void out_ln(const float* __restrict__ y, const float* __restrict__ g,
                       const float* __restrict__ b, float* __restrict__ out) {
    int lane = threadIdx.x & 31;
    int warp = threadIdx.x >> 5;
    int row  = blockIdx.x * 4 + warp;
    const float* yr = y + (size_t)row * CC;
    float v0 = yr[lane], v1 = yr[lane + 32], v2 = yr[lane + 64];
    float s = v0 + v1 + v2;
    #pragma unroll
    for (int o = 16; o; o >>= 1) s += __shfl_xor_sync(0xffffffffu, s, o);
    float mean = s * (1.f / 96.f);
    float d0 = v0 - mean, d1 = v1 - mean, d2 = v2 - mean;
    float qv = d0 * d0 + d1 * d1 + d2 * d2;
    #pragma unroll
    for (int o = 16; o; o >>= 1) qv += __shfl_xor_sync(0xffffffffu, qv, o);
    float inv = rsqrtf(qv * (1.f / 96.f) + 1e-5f);
    float* orow = out + (size_t)row * CC;
    orow[lane]      = d0 * inv * g[lane]      + b[lane];
    orow[lane + 32] = d1 * inv * g[lane + 32] + b[lane + 32];
    orow[lane + 64] = d2 * inv * g[lane + 64] + b[lane + 64];
}

// ---------------- launch ----------------
extern "C" void kernel_launch(void* const* d_in, const int* in_sizes, int n_in,
                              void* d_out, int out_size) {
    const float*     x    = (const float*)d_in[0];
    const void*      ei   = d_in[1];
    const void*      ea   = d_in[2];
    const float*     w_in = (const float*)d_in[3];
    const float*     b_in = (const float*)d_in[4];
    const float*     emb  = (const float*)d_in[5];
    const float*     gw1  = (const float*)d_in[6];
    const float*     gb1  = (const float*)d_in[7];
    const float*     gw2  = (const float*)d_in[8];
    const float*     gb2  = (const float*)d_in[9];
    const float*     wqkv = (const float*)d_in[10];
    const float*     bqkv = (const float*)d_in[11];
    const float*     wo   = (const float*)d_in[12];
    const float*     bo   = (const float*)d_in[13];
    const float*     bng  = (const float*)d_in[14];
    const float*     bnb  = (const float*)d_in[15];
    const float*     fw1  = (const float*)d_in[16];
    const float*     fb1  = (const float*)d_in[17];
    const float*     fw2  = (const float*)d_in[18];
    const float*     fb2  = (const float*)d_in[19];
    const float*     w_o  = (const float*)d_in[20];
    const float*     b_o  = (const float*)d_in[21];
    const float*     lng  = (const float*)d_in[22];
    const float*     lnb  = (const float*)d_in[23];
    float* out = (float*)d_out;

    float *h_, *agg_, *t1_, *pre1_, *qkv_, *attno_, *pre2_, *outb_, *t2_, *pre3_, *y_, *stA_;
    float *po_, *pl_;
    cudaGetSymbolAddress((void**)&h_,    g_h);
    cudaGetSymbolAddress((void**)&agg_,  g_agg);
    cudaGetSymbolAddress((void**)&t1_,   g_t1);
    cudaGetSymbolAddress((void**)&pre1_, g_pre1);
    cudaGetSymbolAddress((void**)&qkv_,  g_qkv);
    cudaGetSymbolAddress((void**)&attno_,g_attno);
    cudaGetSymbolAddress((void**)&pre2_, g_pre2);
    cudaGetSymbolAddress((void**)&outb_, g_outb);
    cudaGetSymbolAddress((void**)&t2_,   g_t2);
    cudaGetSymbolAddress((void**)&pre3_, g_pre3);
    cudaGetSymbolAddress((void**)&y_,    g_y);
    cudaGetSymbolAddress((void**)&stA_,  g_stats);
    cudaGetSymbolAddress((void**)&po_,   g_po);
    cudaGetSymbolAddress((void**)&pl_,   g_pl);

    // side stream + fork/join events (created fresh each call; host-side, no device mem)
    cudaStream_t s1;
    cudaStreamCreateWithFlags(&s1, cudaStreamNonBlocking);
    cudaEvent_t evF[2], evJ[2];
    for (int i = 0; i < 2; i++) {
        cudaEventCreateWithFlags(&evF[i], cudaEventDisableTiming);
        cudaEventCreateWithFlags(&evJ[i], cudaEventDisableTiming);
    }

    auto gemm = [&](const float* A, const float* A2, const float* W, const float* bias,
                    const float* res, float* Cp, int M, int Nc, int K, int relu,
                    float* ss, float* ss2, cudaStream_t st) {
        dim3 grid(Nc / 32, M / 64);
        tgemm<<<grid, 128, 0, st>>>(A, A2, W, bias, res, Cp, M, Nc, K, relu, ss, ss2);
    };

    const int NCEL = NN * CC;

    prep<<<16, 256>>>((const unsigned*)ei, (const unsigned*)ea);
    gemm(x, nullptr, w_in, b_in, nullptr, h_, NN, CC, 64, 0, nullptr, nullptr, 0);

    for (int i = 0; i < 2; i++) {
        float* st_ = stA_ + (size_t)i * 6 * CC;

        // fork: h_ (and for i==0, prep) are ready on the main stream
        cudaEventRecord(evF[i], 0);
        cudaStreamWaitEvent(s1, evF[i], 0);

        // --- side stream: CSR build (layer 0) + GINE branch ---
        if (i == 0) {
            decode_idx<<<(EE + 255) / 256, 256, 0, s1>>>(ei, ea);
            csr_scan<<<1, 1024, 0, s1>>>();
            csr_fill<<<(EE + 255) / 256, 256, 0, s1>>>();
        }
        gine_agg<<<NN / 8, 256, 0, s1>>>(h_, emb, agg_);
        gemm(agg_, h_, gw1, gb1, nullptr, t1_, NN, CC, CC, 1, nullptr, nullptr, s1);
        gemm(t1_, nullptr, gw2, gb2, h_, pre1_, NN, CC, CC, 0, st_ + 0, st_ + CC, s1);
        cudaEventRecord(evJ[i], s1);

        // --- main stream: attention branch ---
        gemm(h_, nullptr, wqkv + (size_t)i * CC * 3 * CC, bqkv + (size_t)i * 3 * CC,
             nullptr, qkv_, NN, 3 * CC, CC, 0, nullptr, nullptr, 0);
        flash_mma<<<dim3(NN / 128, NHEADS, SPLITS), 128>>>(qkv_, po_, pl_);
        flash_combine<<<(NN * NHEADS + 255) / 256, 256>>>(po_, pl_, attno_);
        gemm(attno_, nullptr, wo + (size_t)i * CC * CC, bo + (size_t)i * CC,
             h_, pre2_, NN, CC, CC, 0, st_ + 2 * CC, st_ + 3 * CC, 0);

        // join
        cudaStreamWaitEvent(0, evJ[i], 0);

        // --- merge + FFN (main stream) ---
        bn2_add<<<(NCEL + 255) / 256, 256>>>(pre1_, pre2_, st_,
                                             bng + (size_t)i * 3 * CC, bnb + (size_t)i * 3 * CC,
                                             bng + (size_t)i * 3 * CC + CC, bnb + (size_t)i * 3 * CC + CC,
                                             outb_);
        gemm(outb_, nullptr, fw1 + (size_t)i * CC * 2 * CC, fb1 + (size_t)i * 2 * CC,
             nullptr, t2_, NN, 2 * CC, CC, 1, nullptr, nullptr, 0);
        gemm(t2_, nullptr, fw2 + (size_t)i * 2 * CC * CC, fb2 + (size_t)i * CC,
             outb_, pre3_, NN, CC, 2 * CC, 0, st_ + 4 * CC, st_ + 5 * CC, 0);
        bn_apply<<<(NCEL + 255) / 256, 256>>>(pre3_, st_ + 4 * CC, st_ + 5 * CC,
                                              bng + (size_t)i * 3 * CC + 2 * CC,
                                              bnb + (size_t)i * 3 * CC + 2 * CC, h_);
    }

    gemm(h_, nullptr, w_o, b_o, nullptr, y_, NN, CC, CC, 0, nullptr, nullptr, 0);
    out_ln<<<NN / 4, 128>>>(y_, lng, lnb, out);
}

// round 10
// speedup vs baseline: 4.3499x; 1.0159x over previous
#include <cuda_runtime.h>
#include <cuda_bf16.h>
#include <cstdint>

#define NN 4096
#define CC 96
#define EE 131072
#define NHEADS 4
#define DH 24
#define SPLITS 8

typedef unsigned long long u64;

// ---------------- scratch ----------------
__device__ float g_h[NN*CC];
__device__ float g_agg[NN*CC];
__device__ float g_t1[NN*CC];
__device__ float g_pre1[NN*CC];
__device__ float g_qkv[NN*3*CC];
__device__ float g_attno[NN*CC];
__device__ float g_pre2[NN*CC];
__device__ float g_outb[NN*CC];
__device__ float g_t2[NN*2*CC];
__device__ float g_pre3[NN*CC];
__device__ float g_y[NN*CC];
__device__ float g_stats[12*CC];
__device__ int   g_src[EE];
__device__ int   g_dst[EE];
__device__ int   g_eat[EE];
__device__ int   g_flags[2];
__device__ int   g_cnt[NN];
__device__ int   g_off[NN+1];
__device__ int   g_cur[NN];
__device__ int   g_csrc[EE];
__device__ int   g_ceat[EE];
__device__ float g_po[SPLITS*NHEADS*NN*DH];
__device__ float g_pl[SPLITS*NHEADS*NN];
// packed attention operands: [h*24+d][key]
__device__ unsigned       g_kt[NHEADS*DH*NN];
__device__ unsigned short g_vh[NHEADS*DH*NN];

// ---------------- mma.sync helpers ----------------
__device__ __forceinline__ unsigned f2tf32(float f) {
    unsigned r; asm("cvt.rna.tf32.f32 %0, %1;" : "=r"(r) : "f"(f)); return r;
}
__device__ __forceinline__ unsigned pkbf(float lo, float hi) {
    unsigned r; asm("cvt.rn.bf16x2.f32 %0, %1, %2;" : "=r"(r) : "f"(hi), "f"(lo)); return r;
}
__device__ __forceinline__ void mma_tf32(float* c, const unsigned* a, const unsigned* b) {
    asm volatile("mma.sync.aligned.m16n8k8.row.col.f32.tf32.tf32.f32 "
        "{%0,%1,%2,%3}, {%4,%5,%6,%7}, {%8,%9}, {%0,%1,%2,%3};"
        : "+f"(c[0]), "+f"(c[1]), "+f"(c[2]), "+f"(c[3])
        : "r"(a[0]), "r"(a[1]), "r"(a[2]), "r"(a[3]), "r"(b[0]), "r"(b[1]));
}
__device__ __forceinline__ void mma_bf16(float* c, const unsigned* a, const unsigned* b) {
    asm volatile("mma.sync.aligned.m16n8k16.row.col.f32.bf16.bf16.f32 "
        "{%0,%1,%2,%3}, {%4,%5,%6,%7}, {%8,%9}, {%0,%1,%2,%3};"
        : "+f"(c[0]), "+f"(c[1]), "+f"(c[2]), "+f"(c[3])
        : "r"(a[0]), "r"(a[1]), "r"(a[2]), "r"(a[3]), "r"(b[0]), "r"(b[1]));
}

// ---------------- prologue ----------------
__global__ void prep(const unsigned* __restrict__ ei, const unsigned* __restrict__ ea) {
    int t = blockIdx.x * blockDim.x + threadIdx.x;
    if (blockIdx.x == 0 && threadIdx.x < 32) {
        int lane = threadIdx.x;
        unsigned v1 = (lane < 16) ? ei[2 * lane + 1] : 0u;
        unsigned v2 = (lane < 16) ? ea[2 * lane + 1] : 0u;
        unsigned b1 = __ballot_sync(0xffffffffu, v1 != 0u);
        unsigned b2 = __ballot_sync(0xffffffffu, v2 != 0u);
        if (lane == 0) { g_flags[0] = (b1 == 0u); g_flags[1] = (b2 == 0u); }
    }
    if (t < NN) g_cnt[t] = 0;
    if (t < 12 * CC) g_stats[t] = 0.f;
}

__global__ void decode_idx(const void* __restrict__ ei, const void* __restrict__ ea) {
    int e = blockIdx.x * blockDim.x + threadIdx.x;
    if (e >= EE) return;
    int s, d, a;
    if (g_flags[0]) {
        const long long* p = (const long long*)ei;
        s = (int)p[e]; d = (int)p[EE + e];
    } else {
        const int* p = (const int*)ei;
        s = p[e]; d = p[EE + e];
    }
    if (g_flags[1]) {
        const long long* p = (const long long*)ea;
        a = (int)p[e];
    } else {
        const int* p = (const int*)ea;
        a = p[e];
    }
    g_src[e] = s; g_dst[e] = d; g_eat[e] = a;
    atomicAdd(&g_cnt[d], 1);
}

__global__ __launch_bounds__(1024) void csr_scan() {
    __shared__ int sh[1024];
    int t = threadIdx.x;
    int c0 = g_cnt[4*t], c1 = g_cnt[4*t+1], c2 = g_cnt[4*t+2], c3 = g_cnt[4*t+3];
    int s = c0 + c1 + c2 + c3;
    sh[t] = s;
    __syncthreads();
    for (int o = 1; o < 1024; o <<= 1) {
        int v = (t >= o) ? sh[t - o] : 0;
        __syncthreads();
        sh[t] += v;
        __syncthreads();
    }
    int base = sh[t] - s;
    g_off[4*t] = base;            g_cur[4*t] = base;
    g_off[4*t+1] = base+c0;       g_cur[4*t+1] = base+c0;
    g_off[4*t+2] = base+c0+c1;    g_cur[4*t+2] = base+c0+c1;
    g_off[4*t+3] = base+c0+c1+c2; g_cur[4*t+3] = base+c0+c1+c2;
    if (t == 1023) g_off[NN] = sh[1023];
}
__global__ void csr_fill() {
    int e = blockIdx.x * blockDim.x + threadIdx.x;
    if (e >= EE) return;
    int pos = atomicAdd(&g_cur[g_dst[e]], 1);
    g_csrc[pos] = g_src[e];
    g_ceat[pos] = g_eat[e];
}

// ---------------- GINE aggregate ----------------
__global__ __launch_bounds__(256) void gine_agg(const float* __restrict__ h,
                                                const float* __restrict__ emb,
                                                float* __restrict__ agg) {
    int warp = (blockIdx.x * 256 + threadIdx.x) >> 5;
    int lane = threadIdx.x & 31;
    if (warp >= NN) return;
    int beg = g_off[warp], end = g_off[warp + 1];
    float a0 = 0.f, a1 = 0.f, a2 = 0.f;
    for (int i = beg; i < end; i++) {
        int src = g_csrc[i], et = g_ceat[i];
        const float* hp = h + (size_t)src * CC;
        const float* ep = emb + (size_t)et * CC;
        a0 += fmaxf(hp[lane]      + ep[lane],      0.f);
        a1 += fmaxf(hp[lane + 32] + ep[lane + 32], 0.f);
        a2 += fmaxf(hp[lane + 64] + ep[lane + 64], 0.f);
    }
    float* ap = agg + (size_t)warp * CC;
    ap[lane] = a0; ap[lane + 32] = a1; ap[lane + 64] = a2;
}

// ---------------- 3xTF32 tensor-core GEMM with fused epilogue ----------------
// Optional: BN-stats (st_s/st_s2), packed K/V planes (kt_out/vh_out, for the qkv gemm)
__global__ __launch_bounds__(128) void tgemm(
    const float* __restrict__ A, const float* __restrict__ A2,
    const float* __restrict__ W, const float* __restrict__ bias,
    const float* __restrict__ res, float* __restrict__ C,
    int M, int N, int K, int relu,
    float* __restrict__ st_s, float* __restrict__ st_s2,
    unsigned* __restrict__ kt_out, unsigned short* __restrict__ vh_out)
{
    __shared__ __align__(16) unsigned Bhi[32 * 40];
    __shared__ __align__(16) unsigned Blo[32 * 40];
    __shared__ float Ssum[4][32];
    __shared__ float Ssq[4][32];
    const int tid = threadIdx.x;
    const int w = tid >> 5, lane = tid & 31;
    const int tg = lane >> 2, tq = lane & 3;
    const int row0 = blockIdx.y * 64 + w * 16;
    const int col0 = blockIdx.x * 32;

    float c[4][4];
    #pragma unroll
    for (int nt = 0; nt < 4; nt++)
        #pragma unroll
        for (int r = 0; r < 4; r++) c[nt][r] = 0.f;

    for (int k0 = 0; k0 < K; k0 += 32) {
        __syncthreads();
        #pragma unroll
        for (int j = 0; j < 2; j++) {
            int idx = tid + j * 128;
            int r = idx >> 3, c4 = (idx & 7) * 4;
            float4 v = *(const float4*)(W + (size_t)(k0 + r) * N + col0 + c4);
            unsigned h0 = f2tf32(v.x), h1 = f2tf32(v.y), h2 = f2tf32(v.z), h3 = f2tf32(v.w);
            *(uint4*)&Bhi[r * 40 + c4] = make_uint4(h0, h1, h2, h3);
            *(uint4*)&Blo[r * 40 + c4] = make_uint4(
                f2tf32(v.x - __uint_as_float(h0)), f2tf32(v.y - __uint_as_float(h1)),
                f2tf32(v.z - __uint_as_float(h2)), f2tf32(v.w - __uint_as_float(h3)));
        }
        __syncthreads();
        #pragma unroll
        for (int kc = 0; kc < 4; kc++) {
            const float* ap0 = A + (size_t)(row0 + tg) * K + k0 + kc * 8;
            const float* ap1 = A + (size_t)(row0 + tg + 8) * K + k0 + kc * 8;
            float av[4];
            av[0] = ap0[tq]; av[1] = ap1[tq]; av[2] = ap0[tq + 4]; av[3] = ap1[tq + 4];
            if (A2) {
                const float* bp0 = A2 + (size_t)(row0 + tg) * K + k0 + kc * 8;
                const float* bp1 = A2 + (size_t)(row0 + tg + 8) * K + k0 + kc * 8;
                av[0] += bp0[tq]; av[1] += bp1[tq]; av[2] += bp0[tq + 4]; av[3] += bp1[tq + 4];
            }
            unsigned ahi[4], alo[4];
            #pragma unroll
            for (int r = 0; r < 4; r++) {
                ahi[r] = f2tf32(av[r]);
                alo[r] = f2tf32(av[r] - __uint_as_float(ahi[r]));
            }
            const int kr0 = (kc * 8 + tq) * 40;
            const int kr1 = (kc * 8 + tq + 4) * 40;
            #pragma unroll
            for (int nt = 0; nt < 4; nt++) {
                unsigned bh[2], bl[2];
                bh[0] = Bhi[kr0 + nt * 8 + tg]; bh[1] = Bhi[kr1 + nt * 8 + tg];
                bl[0] = Blo[kr0 + nt * 8 + tg]; bl[1] = Blo[kr1 + nt * 8 + tg];
                mma_tf32(c[nt], ahi, bh);
                mma_tf32(c[nt], ahi, bl);
                mma_tf32(c[nt], alo, bh);
            }
        }
    }

    float myS[8], myQ[8];
    #pragma unroll
    for (int nt = 0; nt < 4; nt++) {
        int cc0 = col0 + nt * 8 + 2 * tq;
        float b0 = bias[cc0], b1 = bias[cc0 + 1];
        float v00 = c[nt][0] + b0, v01 = c[nt][1] + b1;
        float v10 = c[nt][2] + b0, v11 = c[nt][3] + b1;
        if (res) {
            float2 r0v = *(const float2*)(res + (size_t)(row0 + tg) * N + cc0);
            float2 r1v = *(const float2*)(res + (size_t)(row0 + tg + 8) * N + cc0);
            v00 += r0v.x; v01 += r0v.y; v10 += r1v.x; v11 += r1v.y;
        }
        if (relu) {
            v00 = fmaxf(v00, 0.f); v01 = fmaxf(v01, 0.f);
            v10 = fmaxf(v10, 0.f); v11 = fmaxf(v11, 0.f);
        }
        *(float2*)(C + (size_t)(row0 + tg) * N + cc0) = make_float2(v00, v01);
        *(float2*)(C + (size_t)(row0 + tg + 8) * N + cc0) = make_float2(v10, v11);

        if (kt_out && cc0 >= CC) {
            // pack K (cols 96..191) as tf32, V (cols 192..287) as bf16, transposed [col-96][row]
            #pragma unroll
            for (int jj = 0; jj < 2; jj++) {
                int col = cc0 + jj;
                float va = jj ? v01 : v00;
                float vb = jj ? v11 : v10;
                if (col < 2 * CC) {
                    kt_out[(size_t)(col - CC) * NN + row0 + tg] = f2tf32(va);
                    kt_out[(size_t)(col - CC) * NN + row0 + tg + 8] = f2tf32(vb);
                } else {
                    vh_out[(size_t)(col - 2 * CC) * NN + row0 + tg] =
                        __bfloat16_as_ushort(__float2bfloat16(va));
                    vh_out[(size_t)(col - 2 * CC) * NN + row0 + tg + 8] =
                        __bfloat16_as_ushort(__float2bfloat16(vb));
                }
            }
        }

        myS[nt * 2] = v00 + v10;           myS[nt * 2 + 1] = v01 + v11;
        myQ[nt * 2] = v00 * v00 + v10 * v10; myQ[nt * 2 + 1] = v01 * v01 + v11 * v11;
    }

    if (st_s) {
        #pragma unroll
        for (int i = 0; i < 8; i++) {
            #pragma unroll
            for (int o = 4; o <= 16; o <<= 1) {
                myS[i] += __shfl_xor_sync(0xffffffffu, myS[i], o);
                myQ[i] += __shfl_xor_sync(0xffffffffu, myQ[i], o);
            }
        }
        if (tg == 0) {
            #pragma unroll
            for (int nt = 0; nt < 4; nt++) {
                Ssum[w][nt * 8 + 2 * tq] = myS[nt * 2];
                Ssum[w][nt * 8 + 2 * tq + 1] = myS[nt * 2 + 1];
                Ssq[w][nt * 8 + 2 * tq] = myQ[nt * 2];
                Ssq[w][nt * 8 + 2 * tq + 1] = myQ[nt * 2 + 1];
            }
        }
        __syncthreads();
        if (tid < 32) {
            float a = Ssum[0][tid] + Ssum[1][tid] + Ssum[2][tid] + Ssum[3][tid];
            float b = Ssq[0][tid] + Ssq[1][tid] + Ssq[2][tid] + Ssq[3][tid];
            atomicAdd(&st_s[col0 + tid], a);
            atomicAdd(&st_s2[col0 + tid], b);
        }
    }
}

// ---------------- mma.sync flash attention (pre-packed K/V) ----------------
#define QSCALE 0.2944858445807166f

__global__ __launch_bounds__(128) void flash_mma(const float* __restrict__ qkv,
                                                 const unsigned* __restrict__ kt,
                                                 const unsigned short* __restrict__ vh,
                                                 float* __restrict__ po,
                                                 float* __restrict__ pl) {
    __shared__ __align__(16) unsigned KtU[24 * 72];
    __shared__ __align__(16) unsigned short Vh[24 * 72];
    const int h   = blockIdx.y;
    const int q0  = blockIdx.x * 128;
    const int sp  = blockIdx.z;
    const int tid = threadIdx.x;
    const int w   = tid >> 5;
    const int lane = tid & 31;
    const int tg = lane >> 2, tq = lane & 3;

    unsigned QA[2][3][4];
    #pragma unroll
    for (int mi = 0; mi < 2; mi++) {
        const float* qp0 = qkv + (size_t)(q0 + 32 * w + 16 * mi + tg) * (3 * CC) + h * DH;
        const float* qp1 = qp0 + (size_t)8 * (3 * CC);
        #pragma unroll
        for (int kc = 0; kc < 3; kc++) {
            QA[mi][kc][0] = f2tf32(qp0[kc * 8 + tq] * QSCALE);
            QA[mi][kc][1] = f2tf32(qp1[kc * 8 + tq] * QSCALE);
            QA[mi][kc][2] = f2tf32(qp0[kc * 8 + tq + 4] * QSCALE);
            QA[mi][kc][3] = f2tf32(qp1[kc * 8 + tq + 4] * QSCALE);
        }
    }

    float OC[2][3][4];
    #pragma unroll
    for (int mi = 0; mi < 2; mi++)
        #pragma unroll
        for (int n = 0; n < 3; n++)
            #pragma unroll
            for (int r = 0; r < 4; r++) OC[mi][n][r] = 0.f;
    float lacc[2][2] = {{0.f, 0.f}, {0.f, 0.f}};

    const unsigned* ktb0 = kt + (size_t)h * DH * NN;
    const unsigned short* vhb0 = vh + (size_t)h * DH * NN;

    for (int t = 0; t < (NN / SPLITS) / 64; t++) {
        const int kt0 = sp * (NN / SPLITS) + t * 64;
        __syncthreads();
        {
            const unsigned* ktb = ktb0 + kt0;
            const unsigned short* vhb = vhb0 + kt0;
            // K: 24 rows x 16 uint4 = 384; V: 24 rows x 8 uint4 = 192; total 576
            for (int idx = tid; idx < 576; idx += 128) {
                if (idx < 384) {
                    int row = idx >> 4, q = idx & 15;
                    uint4 v = ((const uint4*)(ktb + (size_t)row * NN))[q];
                    *(uint4*)&KtU[row * 72 + q * 4] = v;
                } else {
                    int j = idx - 384;
                    int row = j >> 3, q = j & 7;
                    uint4 v = ((const uint4*)(vhb + (size_t)row * NN))[q];
                    *(uint4*)&Vh[row * 72 + q * 8] = v;
                }
            }
        }
        __syncthreads();

        float SC[2][8][4];
        #pragma unroll
        for (int mi = 0; mi < 2; mi++)
            #pragma unroll
            for (int nt = 0; nt < 8; nt++)
                #pragma unroll
                for (int r = 0; r < 4; r++) SC[mi][nt][r] = 0.f;

        #pragma unroll
        for (int nt = 0; nt < 8; nt++) {
            unsigned bB[3][2];
            #pragma unroll
            for (int kc = 0; kc < 3; kc++) {
                bB[kc][0] = KtU[(kc * 8 + tq) * 72 + nt * 8 + tg];
                bB[kc][1] = KtU[(kc * 8 + tq + 4) * 72 + nt * 8 + tg];
            }
            #pragma unroll
            for (int kc = 0; kc < 3; kc++) {
                mma_tf32(SC[0][nt], QA[0][kc], bB[kc]);
                mma_tf32(SC[1][nt], QA[1][kc], bB[kc]);
            }
        }

        #pragma unroll
        for (int mi = 0; mi < 2; mi++)
            #pragma unroll
            for (int nt = 0; nt < 8; nt++)
                #pragma unroll
                for (int r = 0; r < 4; r++) {
                    float e;
                    asm("ex2.approx.ftz.f32 %0, %1;" : "=f"(e) : "f"(SC[mi][nt][r]));
                    SC[mi][nt][r] = e;
                    lacc[mi][r >> 1] += e;
                }

        unsigned PA[2][4][4];
        #pragma unroll
        for (int mi = 0; mi < 2; mi++)
            #pragma unroll
            for (int kc4 = 0; kc4 < 4; kc4++) {
                PA[mi][kc4][0] = pkbf(SC[mi][2 * kc4][0],     SC[mi][2 * kc4][1]);
                PA[mi][kc4][1] = pkbf(SC[mi][2 * kc4][2],     SC[mi][2 * kc4][3]);
                PA[mi][kc4][2] = pkbf(SC[mi][2 * kc4 + 1][0], SC[mi][2 * kc4 + 1][1]);
                PA[mi][kc4][3] = pkbf(SC[mi][2 * kc4 + 1][2], SC[mi][2 * kc4 + 1][3]);
            }

        #pragma unroll
        for (int kc4 = 0; kc4 < 4; kc4++) {
            #pragma unroll
            for (int n = 0; n < 3; n++) {
                int drow = n * 8 + tg;
                int col = kc4 * 16 + 2 * tq;
                unsigned bh[2];
                bh[0] = *(const unsigned*)&Vh[drow * 72 + col];
                bh[1] = *(const unsigned*)&Vh[drow * 72 + col + 8];
                mma_bf16(OC[0][n], PA[0][kc4], bh);
                mma_bf16(OC[1][n], PA[1][kc4], bh);
            }
        }
    }

    #pragma unroll
    for (int mi = 0; mi < 2; mi++)
        #pragma unroll
        for (int hi = 0; hi < 2; hi++) {
            float v = lacc[mi][hi];
            v += __shfl_xor_sync(0xffffffffu, v, 1);
            v += __shfl_xor_sync(0xffffffffu, v, 2);
            lacc[mi][hi] = v;
        }

    const int base = (sp * NHEADS + h) * NN;
    #pragma unroll
    for (int mi = 0; mi < 2; mi++) {
        int r0 = q0 + 32 * w + 16 * mi + tg;
        int r1 = r0 + 8;
        if (tq == 0) {
            pl[base + r0] = lacc[mi][0];
            pl[base + r1] = lacc[mi][1];
        }
        #pragma unroll
        for (int n = 0; n < 3; n++) {
            float2 v0 = make_float2(OC[mi][n][0], OC[mi][n][1]);
            float2 v1 = make_float2(OC[mi][n][2], OC[mi][n][3]);
            *(float2*)(po + ((size_t)(base + r0)) * DH + n * 8 + 2 * tq) = v0;
            *(float2*)(po + ((size_t)(base + r1)) * DH + n * 8 + 2 * tq) = v1;
        }
    }
}

__global__ void flash_combine(const float* __restrict__ po, const float* __restrict__ pl,
                              float* __restrict__ outp) {
    int t = blockIdx.x * blockDim.x + threadIdx.x;
    if (t >= NN * NHEADS) return;
    int q = t & (NN - 1);
    int h = t >> 12;
    float L = 0.f;
    #pragma unroll
    for (int s = 0; s < SPLITS; s++) L += pl[(s * NHEADS + h) * NN + q];
    float inv = 1.f / L;
    float* op = outp + (size_t)q * CC + h * DH;
    #pragma unroll
    for (int d = 0; d < DH; d += 4) {
        float4 acc = make_float4(0.f, 0.f, 0.f, 0.f);
        #pragma unroll
        for (int s = 0; s < SPLITS; s++) {
            const float4 v = *(const float4*)(po + ((size_t)(s * NHEADS + h) * NN + q) * DH + d);
            acc.x += v.x; acc.y += v.y; acc.z += v.z; acc.w += v.w;
        }
        acc.x *= inv; acc.y *= inv; acc.z *= inv; acc.w *= inv;
        *(float4*)(op + d) = acc;
    }
}

// ---------------- BN elementwise ----------------
__global__ void bn2_add(const float* __restrict__ p1, const float* __restrict__ p2,
                        const float* __restrict__ st,
                        const float* __restrict__ g1, const float* __restrict__ b1,
                        const float* __restrict__ g2, const float* __restrict__ b2,
                        float* __restrict__ out) {
    int i = blockIdx.x * blockDim.x + threadIdx.x;
    if (i >= NN * CC) return;
    int c = i % CC;
    const float invn = 1.f / NN;
    float m1 = st[c] * invn;
    float v1 = st[CC + c] * invn - m1 * m1;
    float m2 = st[2 * CC + c] * invn;
    float v2 = st[3 * CC + c] * invn - m2 * m2;
    float o = (p1[i] - m1) * rsqrtf(v1 + 1e-5f) * g1[c] + b1[c]
            + (p2[i] - m2) * rsqrtf(v2 + 1e-5f) * g2[c] + b2[c];
    out[i] = o;
}

__global__ void bn_apply(const float* __restrict__ p, const float* __restrict__ s,
                         const float* __restrict__ s2, const float* __restrict__ g,
                         const float* __restrict__ b, float* __restrict__ o) {
    int i = blockIdx.x * blockDim.x + threadIdx.x;
    if (i >= NN * CC) return;
    int c = i % CC;
    const float invn = 1.f / NN;
    float m = s[c] * invn;
    float v = s2[c] * invn - m * m;
    o[i] = (p[i] - m) * rsqrtf(v + 1e-5f) * g[c] + b[c];
}

// ---------------- final per-row LayerNorm ----------------
__global__ void out_ln(const float* __restrict__ y, const float* __restrict__ g,
                       const float* __restrict__ b, float* __restrict__ out) {
    int lane = threadIdx.x & 31;
    int warp = threadIdx.x >> 5;
    int row  = blockIdx.x * 4 + warp;
    const float* yr = y + (size_t)row * CC;
    float v0 = yr[lane], v1 = yr[lane + 32], v2 = yr[lane + 64];
    float s = v0 + v1 + v2;
    #pragma unroll
    for (int o = 16; o; o >>= 1) s += __shfl_xor_sync(0xffffffffu, s, o);
    float mean = s * (1.f / 96.f);
    float d0 = v0 - mean, d1 = v1 - mean, d2 = v2 - mean;
    float qv = d0 * d0 + d1 * d1 + d2 * d2;
    #pragma unroll
    for (int o = 16; o; o >>= 1) qv += __shfl_xor_sync(0xffffffffu, qv, o);
    float inv = rsqrtf(qv * (1.f / 96.f) + 1e-5f);
    float* orow = out + (size_t)row * CC;
    orow[lane]      = d0 * inv * g[lane]      + b[lane];
    orow[lane + 32] = d1 * inv * g[lane + 32] + b[lane + 32];
    orow[lane + 64] = d2 * inv * g[lane + 64] + b[lane + 64];
}

// ---------------- launch ----------------
extern "C" void kernel_launch(void* const* d_in, const int* in_sizes, int n_in,
                              void* d_out, int out_size) {
    const float*     x    = (const float*)d_in[0];
    const void*      ei   = d_in[1];
    const void*      ea   = d_in[2];
    const float*     w_in = (const float*)d_in[3];
    const float*     b_in = (const float*)d_in[4];
    const float*     emb  = (const float*)d_in[5];
    const float*     gw1  = (const float*)d_in[6];
    const float*     gb1  = (const float*)d_in[7];
    const float*     gw2  = (const float*)d_in[8];
    const float*     gb2  = (const float*)d_in[9];
    const float*     wqkv = (const float*)d_in[10];
    const float*     bqkv = (const float*)d_in[11];
    const float*     wo   = (const float*)d_in[12];
    const float*     bo   = (const float*)d_in[13];
    const float*     bng  = (const float*)d_in[14];
    const float*     bnb  = (const float*)d_in[15];
    const float*     fw1  = (const float*)d_in[16];
    const float*     fb1  = (const float*)d_in[17];
    const float*     fw2  = (const float*)d_in[18];
    const float*     fb2  = (const float*)d_in[19];
    const float*     w_o  = (const float*)d_in[20];
    const float*     b_o  = (const float*)d_in[21];
    const float*     lng  = (const float*)d_in[22];
    const float*     lnb  = (const float*)d_in[23];
    float* out = (float*)d_out;

    float *h_, *agg_, *t1_, *pre1_, *qkv_, *attno_, *pre2_, *outb_, *t2_, *pre3_, *y_, *stA_;
    float *po_, *pl_;
    unsigned* kt_;
    unsigned short* vh_;
    cudaGetSymbolAddress((void**)&h_,    g_h);
    cudaGetSymbolAddress((void**)&agg_,  g_agg);
    cudaGetSymbolAddress((void**)&t1_,   g_t1);
    cudaGetSymbolAddress((void**)&pre1_, g_pre1);
    cudaGetSymbolAddress((void**)&qkv_,  g_qkv);
    cudaGetSymbolAddress((void**)&attno_,g_attno);
    cudaGetSymbolAddress((void**)&pre2_, g_pre2);
    cudaGetSymbolAddress((void**)&outb_, g_outb);
    cudaGetSymbolAddress((void**)&t2_,   g_t2);
    cudaGetSymbolAddress((void**)&pre3_, g_pre3);
    cudaGetSymbolAddress((void**)&y_,    g_y);
    cudaGetSymbolAddress((void**)&stA_,  g_stats);
    cudaGetSymbolAddress((void**)&po_,   g_po);
    cudaGetSymbolAddress((void**)&pl_,   g_pl);
    cudaGetSymbolAddress((void**)&kt_,   g_kt);
    cudaGetSymbolAddress((void**)&vh_,   g_vh);

    cudaStream_t s1;
    cudaStreamCreateWithFlags(&s1, cudaStreamNonBlocking);
    cudaEvent_t evF[2], evJ[2];
    for (int i = 0; i < 2; i++) {
        cudaEventCreateWithFlags(&evF[i], cudaEventDisableTiming);
        cudaEventCreateWithFlags(&evJ[i], cudaEventDisableTiming);
    }

    auto gemm = [&](const float* A, const float* A2, const float* W, const float* bias,
                    const float* res, float* Cp, int M, int Nc, int K, int relu,
                    float* ss, float* ss2, cudaStream_t st,
                    unsigned* kto = nullptr, unsigned short* vho = nullptr) {
        dim3 grid(Nc / 32, M / 64);
        tgemm<<<grid, 128, 0, st>>>(A, A2, W, bias, res, Cp, M, Nc, K, relu, ss, ss2, kto, vho);
    };

    const int NCEL = NN * CC;

    prep<<<16, 256>>>((const unsigned*)ei, (const unsigned*)ea);
    gemm(x, nullptr, w_in, b_in, nullptr, h_, NN, CC, 64, 0, nullptr, nullptr, 0);

    for (int i = 0; i < 2; i++) {
        float* st_ = stA_ + (size_t)i * 6 * CC;

        // fork point: h_ ready on main stream
        cudaEventRecord(evF[i], 0);

        // --- main stream: attention branch (enqueued first so flash is launch #4) ---
        gemm(h_, nullptr, wqkv + (size_t)i * CC * 3 * CC, bqkv + (size_t)i * 3 * CC,
             nullptr, qkv_, NN, 3 * CC, CC, 0, nullptr, nullptr, 0, kt_, vh_);
        flash_mma<<<dim3(NN / 128, NHEADS, SPLITS), 128>>>(qkv_, kt_, vh_, po_, pl_);
        flash_combine<<<(NN * NHEADS + 255) / 256, 256>>>(po_, pl_, attno_);
        gemm(attno_, nullptr, wo + (size_t)i * CC * CC, bo + (size_t)i * CC,
             h_, pre2_, NN, CC, CC, 0, st_ + 2 * CC, st_ + 3 * CC, 0);

        // --- side stream: CSR build (layer 0) + GINE branch ---
        cudaStreamWaitEvent(s1, evF[i], 0);
        if (i == 0) {
            decode_idx<<<(EE + 255) / 256, 256, 0, s1>>>(ei, ea);
            csr_scan<<<1, 1024, 0, s1>>>();
            csr_fill<<<(EE + 255) / 256, 256, 0, s1>>>();
        }
        gine_agg<<<NN / 8, 256, 0, s1>>>(h_, emb, agg_);
        gemm(agg_, h_, gw1, gb1, nullptr, t1_, NN, CC, CC, 1, nullptr, nullptr, s1);
        gemm(t1_, nullptr, gw2, gb2, h_, pre1_, NN, CC, CC, 0, st_ + 0, st_ + CC, s1);
        cudaEventRecord(evJ[i], s1);

        // join
        cudaStreamWaitEvent(0, evJ[i], 0);

        // --- merge + FFN (main stream) ---
        bn2_add<<<(NCEL + 255) / 256, 256>>>(pre1_, pre2_, st_,
                                             bng + (size_t)i * 3 * CC, bnb + (size_t)i * 3 * CC,
                                             bng + (size_t)i * 3 * CC + CC, bnb + (size_t)i * 3 * CC + CC,
                                             outb_);
        gemm(outb_, nullptr, fw1 + (size_t)i * CC * 2 * CC, fb1 + (size_t)i * 2 * CC,
             nullptr, t2_, NN, 2 * CC, CC, 1, nullptr, nullptr, 0);
        gemm(t2_, nullptr, fw2 + (size_t)i * 2 * CC * CC, fb2 + (size_t)i * CC,
             outb_, pre3_, NN, CC, 2 * CC, 0, st_ + 4 * CC, st_ + 5 * CC, 0);
        bn_apply<<<(NCEL + 255) / 256, 256>>>(pre3_, st_ + 4 * CC, st_ + 5 * CC,
                                              bng + (size_t)i * 3 * CC + 2 * CC,
                                              bnb + (size_t)i * 3 * CC + 2 * CC, h_);
    }

    gemm(h_, nullptr, w_o, b_o, nullptr, y_, NN, CC, CC, 0, nullptr, nullptr, 0);
    out_ln<<<NN / 4, 128>>>(y_, lng, lnb, out);
}

// round 12
// speedup vs baseline: 4.7625x; 1.0948x over previous
#include <cuda_runtime.h>
#include <cuda_bf16.h>
#include <cstdint>

#define NN 4096
#define CC 96
#define EE 131072
#define NHEADS 4
#define DH 24
#define SPLITS 8

typedef unsigned long long u64;

// ---------------- scratch ----------------
__device__ float g_h[NN*CC];
__device__ float g_agg[NN*CC];
__device__ float g_t1[NN*CC];
__device__ float g_pre1[NN*CC];
__device__ float g_qkv[NN*3*CC];
__device__ float g_attno[NN*CC];
__device__ float g_pre2[NN*CC];
__device__ float g_outb[NN*CC];
__device__ float g_t2[NN*2*CC];
__device__ float g_pre3[NN*CC];
__device__ float g_y[NN*CC];
__device__ float g_stats[12*CC];
__device__ int   g_src[EE];
__device__ int   g_dst[EE];
__device__ int   g_eat[EE];
__device__ int   g_flags[2];
__device__ int   g_cnt[NN];
__device__ int   g_off[NN+1];
__device__ int   g_cur[NN];
__device__ int   g_csrc[EE];
__device__ int   g_ceat[EE];
__device__ float g_po[SPLITS*NHEADS*NN*DH];
__device__ float g_pl[SPLITS*NHEADS*NN];
// packed attention operands: [h*24+d][key]
__device__ unsigned       g_kt[NHEADS*DH*NN];
__device__ unsigned short g_vh[NHEADS*DH*NN];

// ---------------- mma.sync helpers ----------------
__device__ __forceinline__ unsigned f2tf32(float f) {
    unsigned r; asm("cvt.rna.tf32.f32 %0, %1;" : "=r"(r) : "f"(f)); return r;
}
__device__ __forceinline__ unsigned pkbf(float lo, float hi) {
    unsigned r; asm("cvt.rn.bf16x2.f32 %0, %1, %2;" : "=r"(r) : "f"(hi), "f"(lo)); return r;
}
__device__ __forceinline__ void mma_tf32(float* c, const unsigned* a, const unsigned* b) {
    asm volatile("mma.sync.aligned.m16n8k8.row.col.f32.tf32.tf32.f32 "
        "{%0,%1,%2,%3}, {%4,%5,%6,%7}, {%8,%9}, {%0,%1,%2,%3};"
        : "+f"(c[0]), "+f"(c[1]), "+f"(c[2]), "+f"(c[3])
        : "r"(a[0]), "r"(a[1]), "r"(a[2]), "r"(a[3]), "r"(b[0]), "r"(b[1]));
}
__device__ __forceinline__ void mma_bf16(float* c, const unsigned* a, const unsigned* b) {
    asm volatile("mma.sync.aligned.m16n8k16.row.col.f32.bf16.bf16.f32 "
        "{%0,%1,%2,%3}, {%4,%5,%6,%7}, {%8,%9}, {%0,%1,%2,%3};"
        : "+f"(c[0]), "+f"(c[1]), "+f"(c[2]), "+f"(c[3])
        : "r"(a[0]), "r"(a[1]), "r"(a[2]), "r"(a[3]), "r"(b[0]), "r"(b[1]));
}
__device__ __forceinline__ void cp16(unsigned dst_smem, const void* src) {
    asm volatile("cp.async.cg.shared.global [%0], [%1], 16;" :: "r"(dst_smem), "l"(src));
}

// ---------------- prologue ----------------
__global__ void prep(const unsigned* __restrict__ ei, const unsigned* __restrict__ ea) {
    int t = blockIdx.x * blockDim.x + threadIdx.x;
    if (blockIdx.x == 0 && threadIdx.x < 32) {
        int lane = threadIdx.x;
        unsigned v1 = (lane < 16) ? ei[2 * lane + 1] : 0u;
        unsigned v2 = (lane < 16) ? ea[2 * lane + 1] : 0u;
        unsigned b1 = __ballot_sync(0xffffffffu, v1 != 0u);
        unsigned b2 = __ballot_sync(0xffffffffu, v2 != 0u);
        if (lane == 0) { g_flags[0] = (b1 == 0u); g_flags[1] = (b2 == 0u); }
    }
    if (t < NN) g_cnt[t] = 0;
    if (t < 12 * CC) g_stats[t] = 0.f;
}

__global__ void decode_idx(const void* __restrict__ ei, const void* __restrict__ ea) {
    int e = blockIdx.x * blockDim.x + threadIdx.x;
    if (e >= EE) return;
    int s, d, a;
    if (g_flags[0]) {
        const long long* p = (const long long*)ei;
        s = (int)p[e]; d = (int)p[EE + e];
    } else {
        const int* p = (const int*)ei;
        s = p[e]; d = p[EE + e];
    }
    if (g_flags[1]) {
        const long long* p = (const long long*)ea;
        a = (int)p[e];
    } else {
        const int* p = (const int*)ea;
        a = p[e];
    }
    g_src[e] = s; g_dst[e] = d; g_eat[e] = a;
    atomicAdd(&g_cnt[d], 1);
}

__global__ __launch_bounds__(1024) void csr_scan() {
    __shared__ int sh[1024];
    int t = threadIdx.x;
    int c0 = g_cnt[4*t], c1 = g_cnt[4*t+1], c2 = g_cnt[4*t+2], c3 = g_cnt[4*t+3];
    int s = c0 + c1 + c2 + c3;
    sh[t] = s;
    __syncthreads();
    for (int o = 1; o < 1024; o <<= 1) {
        int v = (t >= o) ? sh[t - o] : 0;
        __syncthreads();
        sh[t] += v;
        __syncthreads();
    }
    int base = sh[t] - s;
    g_off[4*t] = base;            g_cur[4*t] = base;
    g_off[4*t+1] = base+c0;       g_cur[4*t+1] = base+c0;
    g_off[4*t+2] = base+c0+c1;    g_cur[4*t+2] = base+c0+c1;
    g_off[4*t+3] = base+c0+c1+c2; g_cur[4*t+3] = base+c0+c1+c2;
    if (t == 1023) g_off[NN] = sh[1023];
}
__global__ void csr_fill() {
    int e = blockIdx.x * blockDim.x + threadIdx.x;
    if (e >= EE) return;
    int pos = atomicAdd(&g_cur[g_dst[e]], 1);
    g_csrc[pos] = g_src[e];
    g_ceat[pos] = g_eat[e];
}

// ---------------- GINE aggregate ----------------
__global__ __launch_bounds__(256) void gine_agg(const float* __restrict__ h,
                                                const float* __restrict__ emb,
                                                float* __restrict__ agg) {
    int warp = (blockIdx.x * 256 + threadIdx.x) >> 5;
    int lane = threadIdx.x & 31;
    if (warp >= NN) return;
    int beg = g_off[warp], end = g_off[warp + 1];
    float a0 = 0.f, a1 = 0.f, a2 = 0.f;
    for (int i = beg; i < end; i++) {
        int src = g_csrc[i], et = g_ceat[i];
        const float* hp = h + (size_t)src * CC;
        const float* ep = emb + (size_t)et * CC;
        a0 += fmaxf(hp[lane]      + ep[lane],      0.f);
        a1 += fmaxf(hp[lane + 32] + ep[lane + 32], 0.f);
        a2 += fmaxf(hp[lane + 64] + ep[lane + 64], 0.f);
    }
    float* ap = agg + (size_t)warp * CC;
    ap[lane] = a0; ap[lane + 32] = a1; ap[lane + 64] = a2;
}

// ---------------- 3xTF32 tensor-core GEMM with fused epilogue ----------------
__global__ __launch_bounds__(128) void tgemm(
    const float* __restrict__ A, const float* __restrict__ A2,
    const float* __restrict__ W, const float* __restrict__ bias,
    const float* __restrict__ res, float* __restrict__ C,
    int M, int N, int K, int relu,
    float* __restrict__ st_s, float* __restrict__ st_s2,
    unsigned* __restrict__ kt_out, unsigned short* __restrict__ vh_out)
{
    __shared__ __align__(16) unsigned Bhi[32 * 40];
    __shared__ __align__(16) unsigned Blo[32 * 40];
    __shared__ float Ssum[4][32];
    __shared__ float Ssq[4][32];
    const int tid = threadIdx.x;
    const int w = tid >> 5, lane = tid & 31;
    const int tg = lane >> 2, tq = lane & 3;
    const int row0 = blockIdx.y * 64 + w * 16;
    const int col0 = blockIdx.x * 32;

    float c[4][4];
    #pragma unroll
    for (int nt = 0; nt < 4; nt++)
        #pragma unroll
        for (int r = 0; r < 4; r++) c[nt][r] = 0.f;

    for (int k0 = 0; k0 < K; k0 += 32) {
        __syncthreads();
        #pragma unroll
        for (int j = 0; j < 2; j++) {
            int idx = tid + j * 128;
            int r = idx >> 3, c4 = (idx & 7) * 4;
            float4 v = *(const float4*)(W + (size_t)(k0 + r) * N + col0 + c4);
            unsigned h0 = f2tf32(v.x), h1 = f2tf32(v.y), h2 = f2tf32(v.z), h3 = f2tf32(v.w);
            *(uint4*)&Bhi[r * 40 + c4] = make_uint4(h0, h1, h2, h3);
            *(uint4*)&Blo[r * 40 + c4] = make_uint4(
                f2tf32(v.x - __uint_as_float(h0)), f2tf32(v.y - __uint_as_float(h1)),
                f2tf32(v.z - __uint_as_float(h2)), f2tf32(v.w - __uint_as_float(h3)));
        }
        __syncthreads();
        #pragma unroll
        for (int kc = 0; kc < 4; kc++) {
            const float* ap0 = A + (size_t)(row0 + tg) * K + k0 + kc * 8;
            const float* ap1 = A + (size_t)(row0 + tg + 8) * K + k0 + kc * 8;
            float av[4];
            av[0] = ap0[tq]; av[1] = ap1[tq]; av[2] = ap0[tq + 4]; av[3] = ap1[tq + 4];
            if (A2) {
                const float* bp0 = A2 + (size_t)(row0 + tg) * K + k0 + kc * 8;
                const float* bp1 = A2 + (size_t)(row0 + tg + 8) * K + k0 + kc * 8;
                av[0] += bp0[tq]; av[1] += bp1[tq]; av[2] += bp0[tq + 4]; av[3] += bp1[tq + 4];
            }
            unsigned ahi[4], alo[4];
            #pragma unroll
            for (int r = 0; r < 4; r++) {
                ahi[r] = f2tf32(av[r]);
                alo[r] = f2tf32(av[r] - __uint_as_float(ahi[r]));
            }
            const int kr0 = (kc * 8 + tq) * 40;
            const int kr1 = (kc * 8 + tq + 4) * 40;
            #pragma unroll
            for (int nt = 0; nt < 4; nt++) {
                unsigned bh[2], bl[2];
                bh[0] = Bhi[kr0 + nt * 8 + tg]; bh[1] = Bhi[kr1 + nt * 8 + tg];
                bl[0] = Blo[kr0 + nt * 8 + tg]; bl[1] = Blo[kr1 + nt * 8 + tg];
                mma_tf32(c[nt], ahi, bh);
                mma_tf32(c[nt], ahi, bl);
                mma_tf32(c[nt], alo, bh);
            }
        }
    }

    float myS[8], myQ[8];
    #pragma unroll
    for (int nt = 0; nt < 4; nt++) {
        int cc0 = col0 + nt * 8 + 2 * tq;
        float b0 = bias[cc0], b1 = bias[cc0 + 1];
        float v00 = c[nt][0] + b0, v01 = c[nt][1] + b1;
        float v10 = c[nt][2] + b0, v11 = c[nt][3] + b1;
        if (res) {
            float2 r0v = *(const float2*)(res + (size_t)(row0 + tg) * N + cc0);
            float2 r1v = *(const float2*)(res + (size_t)(row0 + tg + 8) * N + cc0);
            v00 += r0v.x; v01 += r0v.y; v10 += r1v.x; v11 += r1v.y;
        }
        if (relu) {
            v00 = fmaxf(v00, 0.f); v01 = fmaxf(v01, 0.f);
            v10 = fmaxf(v10, 0.f); v11 = fmaxf(v11, 0.f);
        }
        *(float2*)(C + (size_t)(row0 + tg) * N + cc0) = make_float2(v00, v01);
        *(float2*)(C + (size_t)(row0 + tg + 8) * N + cc0) = make_float2(v10, v11);

        if (kt_out && cc0 >= CC) {
            #pragma unroll
            for (int jj = 0; jj < 2; jj++) {
                int col = cc0 + jj;
                float va = jj ? v01 : v00;
                float vb = jj ? v11 : v10;
                if (col < 2 * CC) {
                    kt_out[(size_t)(col - CC) * NN + row0 + tg] = f2tf32(va);
                    kt_out[(size_t)(col - CC) * NN + row0 + tg + 8] = f2tf32(vb);
                } else {
                    vh_out[(size_t)(col - 2 * CC) * NN + row0 + tg] =
                        __bfloat16_as_ushort(__float2bfloat16(va));
                    vh_out[(size_t)(col - 2 * CC) * NN + row0 + tg + 8] =
                        __bfloat16_as_ushort(__float2bfloat16(vb));
                }
            }
        }

        myS[nt * 2] = v00 + v10;           myS[nt * 2 + 1] = v01 + v11;
        myQ[nt * 2] = v00 * v00 + v10 * v10; myQ[nt * 2 + 1] = v01 * v01 + v11 * v11;
    }

    if (st_s) {
        #pragma unroll
        for (int i = 0; i < 8; i++) {
            #pragma unroll
            for (int o = 4; o <= 16; o <<= 1) {
                myS[i] += __shfl_xor_sync(0xffffffffu, myS[i], o);
                myQ[i] += __shfl_xor_sync(0xffffffffu, myQ[i], o);
            }
        }
        if (tg == 0) {
            #pragma unroll
            for (int nt = 0; nt < 4; nt++) {
                Ssum[w][nt * 8 + 2 * tq] = myS[nt * 2];
                Ssum[w][nt * 8 + 2 * tq + 1] = myS[nt * 2 + 1];
                Ssq[w][nt * 8 + 2 * tq] = myQ[nt * 2];
                Ssq[w][nt * 8 + 2 * tq + 1] = myQ[nt * 2 + 1];
            }
        }
        __syncthreads();
        if (tid < 32) {
            float a = Ssum[0][tid] + Ssum[1][tid] + Ssum[2][tid] + Ssum[3][tid];
            float b = Ssq[0][tid] + Ssq[1][tid] + Ssq[2][tid] + Ssq[3][tid];
            atomicAdd(&st_s[col0 + tid], a);
            atomicAdd(&st_s2[col0 + tid], b);
        }
    }
}

// ---------------- mma.sync flash attention (cp.async double-buffered) ----------------
#define QSCALE 0.2944858445807166f
#define NTILES ((NN / SPLITS) / 64)

__global__ __launch_bounds__(128) void flash_mma(const float* __restrict__ qkv,
                                                 const unsigned* __restrict__ kt,
                                                 const unsigned short* __restrict__ vh,
                                                 float* __restrict__ po,
                                                 float* __restrict__ pl) {
    __shared__ __align__(16) unsigned KtU[2][24 * 72];
    __shared__ __align__(16) unsigned short Vh[2][24 * 72];
    const int h   = blockIdx.y;
    const int q0  = blockIdx.x * 128;
    const int sp  = blockIdx.z;
    const int tid = threadIdx.x;
    const int w   = tid >> 5;
    const int lane = tid & 31;
    const int tg = lane >> 2, tq = lane & 3;

    const unsigned* ktb0 = kt + (size_t)h * DH * NN + sp * (NN / SPLITS);
    const unsigned short* vhb0 = vh + (size_t)h * DH * NN + sp * (NN / SPLITS);

    // staging per tile: K = 24 rows x 16 x 16B = 384 ops; V = 24 rows x 8 x 16B = 192 ops
    auto stage = [&](int t, int buf) {
        const unsigned* ktb = ktb0 + t * 64;
        const unsigned short* vhb = vhb0 + t * 64;
        unsigned kbase = (unsigned)__cvta_generic_to_shared(&KtU[buf][0]);
        unsigned vbase = (unsigned)__cvta_generic_to_shared(&Vh[buf][0]);
        #pragma unroll
        for (int ii = 0; ii < 3; ii++) {              // K ops 0..383
            int idx = tid + ii * 128;
            int row = idx >> 4, q = idx & 15;
            cp16(kbase + (row * 72 + q * 4) * 4, ktb + (size_t)row * NN + q * 4);
        }
        {                                             // V ops 0..127
            int row = tid >> 3, q = tid & 7;
            cp16(vbase + (row * 72 + q * 8) * 2, vhb + (size_t)row * NN + q * 8);
        }
        if (tid < 64) {                               // V ops 128..191
            int idx = 128 + tid;
            int row = idx >> 3, q = idx & 7;
            cp16(vbase + (row * 72 + q * 8) * 2, vhb + (size_t)row * NN + q * 8);
        }
        asm volatile("cp.async.commit_group;" ::: "memory");
    };

    unsigned QA[2][3][4];
    #pragma unroll
    for (int mi = 0; mi < 2; mi++) {
        const float* qp0 = qkv + (size_t)(q0 + 32 * w + 16 * mi + tg) * (3 * CC) + h * DH;
        const float* qp1 = qp0 + (size_t)8 * (3 * CC);
        #pragma unroll
        for (int kc = 0; kc < 3; kc++) {
            QA[mi][kc][0] = f2tf32(qp0[kc * 8 + tq] * QSCALE);
            QA[mi][kc][1] = f2tf32(qp1[kc * 8 + tq] * QSCALE);
            QA[mi][kc][2] = f2tf32(qp0[kc * 8 + tq + 4] * QSCALE);
            QA[mi][kc][3] = f2tf32(qp1[kc * 8 + tq + 4] * QSCALE);
        }
    }

    float OC[2][3][4];
    #pragma unroll
    for (int mi = 0; mi < 2; mi++)
        #pragma unroll
        for (int n = 0; n < 3; n++)
            #pragma unroll
            for (int r = 0; r < 4; r++) OC[mi][n][r] = 0.f;
    float lacc[2][2] = {{0.f, 0.f}, {0.f, 0.f}};

    stage(0, 0);

    for (int t = 0; t < NTILES; t++) {
        const int buf = t & 1;
        if (t + 1 < NTILES) {
            stage(t + 1, buf ^ 1);
            asm volatile("cp.async.wait_group 1;" ::: "memory");
        } else {
            asm volatile("cp.async.wait_group 0;" ::: "memory");
        }
        __syncthreads();

        float SC[2][8][4];
        #pragma unroll
        for (int mi = 0; mi < 2; mi++)
            #pragma unroll
            for (int nt = 0; nt < 8; nt++)
                #pragma unroll
                for (int r = 0; r < 4; r++) SC[mi][nt][r] = 0.f;

        #pragma unroll
        for (int nt = 0; nt < 8; nt++) {
            unsigned bB[3][2];
            #pragma unroll
            for (int kc = 0; kc < 3; kc++) {
                bB[kc][0] = KtU[buf][(kc * 8 + tq) * 72 + nt * 8 + tg];
                bB[kc][1] = KtU[buf][(kc * 8 + tq + 4) * 72 + nt * 8 + tg];
            }
            #pragma unroll
            for (int kc = 0; kc < 3; kc++) {
                mma_tf32(SC[0][nt], QA[0][kc], bB[kc]);
                mma_tf32(SC[1][nt], QA[1][kc], bB[kc]);
            }
        }

        #pragma unroll
        for (int mi = 0; mi < 2; mi++)
            #pragma unroll
            for (int nt = 0; nt < 8; nt++)
                #pragma unroll
                for (int r = 0; r < 4; r++) {
                    float e;
                    asm("ex2.approx.ftz.f32 %0, %1;" : "=f"(e) : "f"(SC[mi][nt][r]));
                    SC[mi][nt][r] = e;
                    lacc[mi][r >> 1] += e;
                }

        unsigned PA[2][4][4];
        #pragma unroll
        for (int mi = 0; mi < 2; mi++)
            #pragma unroll
            for (int kc4 = 0; kc4 < 4; kc4++) {
                PA[mi][kc4][0] = pkbf(SC[mi][2 * kc4][0],     SC[mi][2 * kc4][1]);
                PA[mi][kc4][1] = pkbf(SC[mi][2 * kc4][2],     SC[mi][2 * kc4][3]);
                PA[mi][kc4][2] = pkbf(SC[mi][2 * kc4 + 1][0], SC[mi][2 * kc4 + 1][1]);
                PA[mi][kc4][3] = pkbf(SC[mi][2 * kc4 + 1][2], SC[mi][2 * kc4 + 1][3]);
            }

        #pragma unroll
        for (int kc4 = 0; kc4 < 4; kc4++) {
            #pragma unroll
            for (int n = 0; n < 3; n++) {
                int drow = n * 8 + tg;
                int col = kc4 * 16 + 2 * tq;
                unsigned bh[2];
                bh[0] = *(const unsigned*)&Vh[buf][drow * 72 + col];
                bh[1] = *(const unsigned*)&Vh[buf][drow * 72 + col + 8];
                mma_bf16(OC[0][n], PA[0][kc4], bh);
                mma_bf16(OC[1][n], PA[1][kc4], bh);
            }
        }
        __syncthreads();
    }

    #pragma unroll
    for (int mi = 0; mi < 2; mi++)
        #pragma unroll
        for (int hi = 0; hi < 2; hi++) {
            float v = lacc[mi][hi];
            v += __shfl_xor_sync(0xffffffffu, v, 1);
            v += __shfl_xor_sync(0xffffffffu, v, 2);
            lacc[mi][hi] = v;
        }

    const int base = (sp * NHEADS + h) * NN;
    #pragma unroll
    for (int mi = 0; mi < 2; mi++) {
        int r0 = q0 + 32 * w + 16 * mi + tg;
        int r1 = r0 + 8;
        if (tq == 0) {
            pl[base + r0] = lacc[mi][0];
            pl[base + r1] = lacc[mi][1];
        }
        #pragma unroll
        for (int n = 0; n < 3; n++) {
            float2 v0 = make_float2(OC[mi][n][0], OC[mi][n][1]);
            float2 v1 = make_float2(OC[mi][n][2], OC[mi][n][3]);
            *(float2*)(po + ((size_t)(base + r0)) * DH + n * 8 + 2 * tq) = v0;
            *(float2*)(po + ((size_t)(base + r1)) * DH + n * 8 + 2 * tq) = v1;
        }
    }
}

__global__ void flash_combine(const float* __restrict__ po, const float* __restrict__ pl,
                              float* __restrict__ outp) {
    int t = blockIdx.x * blockDim.x + threadIdx.x;
    if (t >= NN * NHEADS) return;
    int q = t & (NN - 1);
    int h = t >> 12;
    float L = 0.f;
    #pragma unroll
    for (int s = 0; s < SPLITS; s++) L += pl[(s * NHEADS + h) * NN + q];
    float inv = 1.f / L;
    float* op = outp + (size_t)q * CC + h * DH;
    #pragma unroll
    for (int d = 0; d < DH; d += 4) {
        float4 acc = make_float4(0.f, 0.f, 0.f, 0.f);
        #pragma unroll
        for (int s = 0; s < SPLITS; s++) {
            const float4 v = *(const float4*)(po + ((size_t)(s * NHEADS + h) * NN + q) * DH + d);
            acc.x += v.x; acc.y += v.y; acc.z += v.z; acc.w += v.w;
        }
        acc.x *= inv; acc.y *= inv; acc.z *= inv; acc.w *= inv;
        *(float4*)(op + d) = acc;
    }
}

// ---------------- BN elementwise ----------------
__global__ void bn2_add(const float* __restrict__ p1, const float* __restrict__ p2,
                        const float* __restrict__ st,
                        const float* __restrict__ g1, const float* __restrict__ b1,
                        const float* __restrict__ g2, const float* __restrict__ b2,
                        float* __restrict__ out) {
    int i = blockIdx.x * blockDim.x + threadIdx.x;
    if (i >= NN * CC) return;
    int c = i % CC;
    const float invn = 1.f / NN;
    float m1 = st[c] * invn;
    float v1 = st[CC + c] * invn - m1 * m1;
    float m2 = st[2 * CC + c] * invn;
    float v2 = st[3 * CC + c] * invn - m2 * m2;
    float o = (p1[i] - m1) * rsqrtf(v1 + 1e-5f) * g1[c] + b1[c]
            + (p2[i] - m2) * rsqrtf(v2 + 1e-5f) * g2[c] + b2[c];
    out[i] = o;
}

__global__ void bn_apply(const float* __restrict__ p, const float* __restrict__ s,
                         const float* __restrict__ s2, const float* __restrict__ g,
                         const float* __restrict__ b, float* __restrict__ o) {
    int i = blockIdx.x * blockDim.x + threadIdx.x;
    if (i >= NN * CC) return;
    int c = i % CC;
    const float invn = 1.f / NN;
    float m = s[c] * invn;
    float v = s2[c] * invn - m * m;
    o[i] = (p[i] - m) * rsqrtf(v + 1e-5f) * g[c] + b[c];
}

// ---------------- final per-row LayerNorm ----------------
__global__ void out_ln(const float* __restrict__ y, const float* __restrict__ g,
                       const float* __restrict__ b, float* __restrict__ out) {
    int lane = threadIdx.x & 31;
    int warp = threadIdx.x >> 5;
    int row  = blockIdx.x * 4 + warp;
    const float* yr = y + (size_t)row * CC;
    float v0 = yr[lane], v1 = yr[lane + 32], v2 = yr[lane + 64];
    float s = v0 + v1 + v2;
    #pragma unroll
    for (int o = 16; o; o >>= 1) s += __shfl_xor_sync(0xffffffffu, s, o);
    float mean = s * (1.f / 96.f);
    float d0 = v0 - mean, d1 = v1 - mean, d2 = v2 - mean;
    float qv = d0 * d0 + d1 * d1 + d2 * d2;
    #pragma unroll
    for (int o = 16; o; o >>= 1) qv += __shfl_xor_sync(0xffffffffu, qv, o);
    float inv = rsqrtf(qv * (1.f / 96.f) + 1e-5f);
    float* orow = out + (size_t)row * CC;
    orow[lane]      = d0 * inv * g[lane]      + b[lane];
    orow[lane + 32] = d1 * inv * g[lane + 32] + b[lane + 32];
    orow[lane + 64] = d2 * inv * g[lane + 64] + b[lane + 64];
}

// ---------------- launch ----------------
extern "C" void kernel_launch(void* const* d_in, const int* in_sizes, int n_in,
                              void* d_out, int out_size) {
    const float*     x    = (const float*)d_in[0];
    const void*      ei   = d_in[1];
    const void*      ea   = d_in[2];
    const float*     w_in = (const float*)d_in[3];
    const float*     b_in = (const float*)d_in[4];
    const float*     emb  = (const float*)d_in[5];
    const float*     gw1  = (const float*)d_in[6];
    const float*     gb1  = (const float*)d_in[7];
    const float*     gw2  = (const float*)d_in[8];
    const float*     gb2  = (const float*)d_in[9];
    const float*     wqkv = (const float*)d_in[10];
    const float*     bqkv = (const float*)d_in[11];
    const float*     wo   = (const float*)d_in[12];
    const float*     bo   = (const float*)d_in[13];
    const float*     bng  = (const float*)d_in[14];
    const float*     bnb  = (const float*)d_in[15];
    const float*     fw1  = (const float*)d_in[16];
    const float*     fb1  = (const float*)d_in[17];
    const float*     fw2  = (const float*)d_in[18];
    const float*     fb2  = (const float*)d_in[19];
    const float*     w_o  = (const float*)d_in[20];
    const float*     b_o  = (const float*)d_in[21];
    const float*     lng  = (const float*)d_in[22];
    const float*     lnb  = (const float*)d_in[23];
    float* out = (float*)d_out;

    float *h_, *agg_, *t1_, *pre1_, *qkv_, *attno_, *pre2_, *outb_, *t2_, *pre3_, *y_, *stA_;
    float *po_, *pl_;
    unsigned* kt_;
    unsigned short* vh_;
    cudaGetSymbolAddress((void**)&h_,    g_h);
    cudaGetSymbolAddress((void**)&agg_,  g_agg);
    cudaGetSymbolAddress((void**)&t1_,   g_t1);
    cudaGetSymbolAddress((void**)&pre1_, g_pre1);
    cudaGetSymbolAddress((void**)&qkv_,  g_qkv);
    cudaGetSymbolAddress((void**)&attno_,g_attno);
    cudaGetSymbolAddress((void**)&pre2_, g_pre2);
    cudaGetSymbolAddress((void**)&outb_, g_outb);
    cudaGetSymbolAddress((void**)&t2_,   g_t2);
    cudaGetSymbolAddress((void**)&pre3_, g_pre3);
    cudaGetSymbolAddress((void**)&y_,    g_y);
    cudaGetSymbolAddress((void**)&stA_,  g_stats);
    cudaGetSymbolAddress((void**)&po_,   g_po);
    cudaGetSymbolAddress((void**)&pl_,   g_pl);
    cudaGetSymbolAddress((void**)&kt_,   g_kt);
    cudaGetSymbolAddress((void**)&vh_,   g_vh);

    cudaStream_t s1;
    cudaStreamCreateWithFlags(&s1, cudaStreamNonBlocking);
    cudaEvent_t evF[2], evJ[2];
    for (int i = 0; i < 2; i++) {
        cudaEventCreateWithFlags(&evF[i], cudaEventDisableTiming);
        cudaEventCreateWithFlags(&evJ[i], cudaEventDisableTiming);
    }

    auto gemm = [&](const float* A, const float* A2, const float* W, const float* bias,
                    const float* res, float* Cp, int M, int Nc, int K, int relu,
                    float* ss, float* ss2, cudaStream_t st,
                    unsigned* kto = nullptr, unsigned short* vho = nullptr) {
        dim3 grid(Nc / 32, M / 64);
        tgemm<<<grid, 128, 0, st>>>(A, A2, W, bias, res, Cp, M, Nc, K, relu, ss, ss2, kto, vho);
    };

    const int NCEL = NN * CC;

    prep<<<16, 256>>>((const unsigned*)ei, (const unsigned*)ea);
    gemm(x, nullptr, w_in, b_in, nullptr, h_, NN, CC, 64, 0, nullptr, nullptr, 0);

    for (int i = 0; i < 2; i++) {
        float* st_ = stA_ + (size_t)i * 6 * CC;

        cudaEventRecord(evF[i], 0);

        // --- main stream: attention branch ---
        gemm(h_, nullptr, wqkv + (size_t)i * CC * 3 * CC, bqkv + (size_t)i * 3 * CC,
             nullptr, qkv_, NN, 3 * CC, CC, 0, nullptr, nullptr, 0, kt_, vh_);
        flash_mma<<<dim3(NN / 128, NHEADS, SPLITS), 128>>>(qkv_, kt_, vh_, po_, pl_);
        flash_combine<<<(NN * NHEADS + 255) / 256, 256>>>(po_, pl_, attno_);
        gemm(attno_, nullptr, wo + (size_t)i * CC * CC, bo + (size_t)i * CC,
             h_, pre2_, NN, CC, CC, 0, st_ + 2 * CC, st_ + 3 * CC, 0);

        // --- side stream: CSR build (layer 0) + GINE branch ---
        cudaStreamWaitEvent(s1, evF[i], 0);
        if (i == 0) {
            decode_idx<<<(EE + 255) / 256, 256, 0, s1>>>(ei, ea);
            csr_scan<<<1, 1024, 0, s1>>>();
            csr_fill<<<(EE + 255) / 256, 256, 0, s1>>>();
        }
        gine_agg<<<NN / 8, 256, 0, s1>>>(h_, emb, agg_);
        gemm(agg_, h_, gw1, gb1, nullptr, t1_, NN, CC, CC, 1, nullptr, nullptr, s1);
        gemm(t1_, nullptr, gw2, gb2, h_, pre1_, NN, CC, CC, 0, st_ + 0, st_ + CC, s1);
        cudaEventRecord(evJ[i], s1);

        cudaStreamWaitEvent(0, evJ[i], 0);

        // --- merge + FFN (main stream) ---
        bn2_add<<<(NCEL + 255) / 256, 256>>>(pre1_, pre2_, st_,
                                             bng + (size_t)i * 3 * CC, bnb + (size_t)i * 3 * CC,
                                             bng + (size_t)i * 3 * CC + CC, bnb + (size_t)i * 3 * CC + CC,
                                             outb_);
        gemm(outb_, nullptr, fw1 + (size_t)i * CC * 2 * CC, fb1 + (size_t)i * 2 * CC,
             nullptr, t2_, NN, 2 * CC, CC, 1, nullptr, nullptr, 0);
        gemm(t2_, nullptr, fw2 + (size_t)i * 2 * CC * CC, fb2 + (size_t)i * CC,
             outb_, pre3_, NN, CC, 2 * CC, 0, st_ + 4 * CC, st_ + 5 * CC, 0);
        bn_apply<<<(NCEL + 255) / 256, 256>>>(pre3_, st_ + 4 * CC, st_ + 5 * CC,
                                              bng + (size_t)i * 3 * CC + 2 * CC,
                                              bnb + (size_t)i * 3 * CC + 2 * CC, h_);
    }

    gemm(h_, nullptr, w_o, b_o, nullptr, y_, NN, CC, CC, 0, nullptr, nullptr, 0);
    out_ln<<<NN / 4, 128>>>(y_, lng, lnb, out);
}